// round 9
// baseline (speedup 1.0000x reference)
#include <cuda_runtime.h>
#include <cstdint>
#include <math.h>

// ---------------------------------------------------------------------------
// Problem constants
// ---------------------------------------------------------------------------
#define BATCH   8
#define DIMC    512
#define SPATIAL 1024             // H*W = 32*32
#define NTOK    (BATCH*SPATIAL)  // 8192 tokens
#define HEADS   8
#define HDIM    64
#define KVLEN   77
#define KVDIM   1024

// ---------------------------------------------------------------------------
// Scratch buffers (static device globals: allocation-free)
// ---------------------------------------------------------------------------
__device__ float g_x   [(size_t)NTOK * DIMC];          // running activation
__device__ float g_t   [(size_t)NTOK * DIMC];          // temp / normalized
__device__ float g_q   [(size_t)NTOK * DIMC];          // cross-attn q
__device__ float g_qkv [(size_t)NTOK * 1536];          // packed self-attn q|k|v
__device__ float g_kv2 [(size_t)(BATCH*KVLEN) * 1024]; // packed cross k|v
__device__ float g_gl  [(size_t)NTOK * 2048];          // geglu a-half / output
// transposed weights [N, K] row-major
__device__ float g_wtFcIn[(size_t)512 * 512];
__device__ float g_wtQkv [(size_t)1536 * 512];
__device__ float g_wtA1o [(size_t)512 * 512];
__device__ float g_wtA2q [(size_t)512 * 512];
__device__ float g_wtA2o [(size_t)512 * 512];
__device__ float g_wtKv2 [(size_t)1024 * 1024];
__device__ float g_wtFfp [(size_t)4096 * 512];
__device__ float g_wtFfo [(size_t)512 * 2048];
__device__ float g_wtFco [(size_t)512 * 512];

// ---------------------------------------------------------------------------
// Warp reduction helpers
// ---------------------------------------------------------------------------
__device__ __forceinline__ float warpSum(float v) {
    #pragma unroll
    for (int o = 16; o > 0; o >>= 1) v += __shfl_xor_sync(0xffffffffu, v, o);
    return v;
}

// ---------------------------------------------------------------------------
// mma / ldmatrix helpers (tf32, raw fp32 bits)
// ---------------------------------------------------------------------------
__device__ __forceinline__ void mma_tf32(float* d, const uint32_t* a, const uint32_t* b) {
    asm volatile(
        "mma.sync.aligned.m16n8k8.row.col.f32.tf32.tf32.f32 "
        "{%0,%1,%2,%3}, {%4,%5,%6,%7}, {%8,%9}, {%0,%1,%2,%3};"
        : "+f"(d[0]), "+f"(d[1]), "+f"(d[2]), "+f"(d[3])
        : "r"(a[0]), "r"(a[1]), "r"(a[2]), "r"(a[3]), "r"(b[0]), "r"(b[1]));
}
__device__ __forceinline__ void ldsm4(uint32_t& r0, uint32_t& r1,
                                      uint32_t& r2, uint32_t& r3, uint32_t addr) {
    asm volatile("ldmatrix.sync.aligned.m8n8.x4.shared.b16 {%0,%1,%2,%3}, [%4];"
                 : "=r"(r0), "=r"(r1), "=r"(r2), "=r"(r3) : "r"(addr));
}
__device__ __forceinline__ void cp_async16(uint32_t dst, const void* src, int bytes) {
    asm volatile("cp.async.cg.shared.global [%0], [%1], 16, %2;\n"
                 :: "r"(dst), "l"(src), "r"(bytes));
}
__device__ __forceinline__ void cp_commit() { asm volatile("cp.async.commit_group;\n"); }
__device__ __forceinline__ void cp_wait1()  { asm volatile("cp.async.wait_group 1;\n"); }
__device__ __forceinline__ void cp_wait0()  { asm volatile("cp.async.wait_group 0;\n"); }

// ---------------------------------------------------------------------------
// GroupNorm + transpose to token-major
// ---------------------------------------------------------------------------
__global__ void groupnorm_kernel(const float* __restrict__ qin,
                                 const float* __restrict__ gamma,
                                 const float* __restrict__ beta,
                                 float* __restrict__ out) {
    const int blk = blockIdx.x;
    const int b = blk >> 5;
    const int grp = blk & 31;
    const float* base = qin + ((size_t)b * DIMC + grp * 16) * SPATIAL;

    float s = 0.f, s2 = 0.f;
    for (int i = threadIdx.x; i < 16 * SPATIAL; i += 256) {
        float v = base[i];
        s += v; s2 += v * v;
    }
    __shared__ float red[2][8];
    s = warpSum(s); s2 = warpSum(s2);
    int wid = threadIdx.x >> 5, lid = threadIdx.x & 31;
    if (lid == 0) { red[0][wid] = s; red[1][wid] = s2; }
    __syncthreads();
    if (wid == 0) {
        float a = (lid < 8) ? red[0][lid] : 0.f;
        float c = (lid < 8) ? red[1][lid] : 0.f;
        a = warpSum(a); c = warpSum(c);
        if (lid == 0) { red[0][0] = a; red[1][0] = c; }
    }
    __syncthreads();
    const float mu  = red[0][0] * (1.f / 16384.f);
    const float var = red[1][0] * (1.f / 16384.f) - mu * mu;
    const float inv = rsqrtf(var + 1e-6f);

    for (int i = threadIdx.x; i < 16 * SPATIAL; i += 256) {
        int c = grp * 16 + (i >> 10);
        int sp = i & 1023;
        float v = (base[i] - mu) * inv * gamma[c] + beta[c];
        out[((size_t)(b * SPATIAL + sp)) * DIMC + c] = v;
    }
}

// ---------------------------------------------------------------------------
// LayerNorm over 512-dim rows. One warp per row.
// ---------------------------------------------------------------------------
__global__ void layernorm_kernel(const float* __restrict__ x,
                                 const float* __restrict__ gamma,
                                 const float* __restrict__ beta,
                                 float* __restrict__ out, int rows) {
    int row = blockIdx.x * 8 + (threadIdx.x >> 5);
    if (row >= rows) return;
    int lid = threadIdx.x & 31;
    const float4* xr = (const float4*)(x + (size_t)row * DIMC);

    float4 vals[4];
    float s = 0.f, s2 = 0.f;
    #pragma unroll
    for (int i = 0; i < 4; i++) {
        float4 v = xr[lid + 32 * i];
        vals[i] = v;
        s  += v.x + v.y + v.z + v.w;
        s2 += v.x*v.x + v.y*v.y + v.z*v.z + v.w*v.w;
    }
    s = warpSum(s); s2 = warpSum(s2);
    const float mu  = s * (1.f / 512.f);
    const float inv = rsqrtf(s2 * (1.f / 512.f) - mu * mu + 1e-5f);

    float4* orow = (float4*)(out + (size_t)row * DIMC);
    const float4* g4 = (const float4*)gamma;
    const float4* b4 = (const float4*)beta;
    #pragma unroll
    for (int i = 0; i < 4; i++) {
        int idx = lid + 32 * i;
        float4 v = vals[i], g = g4[idx], b = b4[idx], o;
        o.x = (v.x - mu) * inv * g.x + b.x;
        o.y = (v.y - mu) * inv * g.y + b.y;
        o.z = (v.z - mu) * inv * g.z + b.z;
        o.w = (v.w - mu) * inv * g.w + b.w;
        orow[idx] = o;
    }
}

// ---------------------------------------------------------------------------
// Tiled transpose: src [R, C] -> dst [C, R]  (R, C multiples of 32)
// ---------------------------------------------------------------------------
__global__ void transpose_kernel(const float* __restrict__ src,
                                 float* __restrict__ dst, int R, int C) {
    __shared__ float tile[32][33];
    int c0 = blockIdx.x * 32, r0 = blockIdx.y * 32;
    int x = threadIdx.x, y = threadIdx.y;
    #pragma unroll
    for (int i = 0; i < 32; i += 8)
        tile[y + i][x] = src[(size_t)(r0 + y + i) * C + c0 + x];
    __syncthreads();
    #pragma unroll
    for (int i = 0; i < 32; i += 8)
        dst[(size_t)(c0 + y + i) * R + r0 + x] = tile[x][y + i];
}

// ---------------------------------------------------------------------------
// Final transpose + residual
// ---------------------------------------------------------------------------
__global__ void output_kernel(const float* __restrict__ t,
                              const float* __restrict__ qin,
                              float* __restrict__ out) {
    int i = blockIdx.x * 256 + threadIdx.x;
    if (i >= BATCH * DIMC * SPATIAL) return;
    int sp = i & 1023;
    int bc = i >> 10;
    int c = bc & 511;
    int b = bc >> 9;
    out[i] = t[((size_t)(b * SPATIAL + sp)) * DIMC + c] + qin[i];
}

// ===========================================================================
// Fused flash self-attention (ldmatrix fragment loads).
// ===========================================================================
#define FSTR 68
#define PSTR 132
#define FS_SQ   0
#define FS_SK   (128*FSTR)
#define FS_SVT  (FS_SK + 128*FSTR)
#define FS_SP   (FS_SVT + 64*PSTR)
#define FS_TOTAL (FS_SP + 128*PSTR)

__global__ void __launch_bounds__(256) flash_self_kernel(
    const float* __restrict__ qkv, float* __restrict__ outp) {
    extern __shared__ float sm[];
    float* sQ  = sm + FS_SQ;
    float* sK  = sm + FS_SK;
    float* sVt = sm + FS_SVT;
    float* sP  = sm + FS_SP;

    const int b  = blockIdx.y >> 3;
    const int h  = blockIdx.y & 7;
    const int q0 = blockIdx.x * 128;
    const int tid = threadIdx.x;
    const int warp = tid >> 5;
    const int lane = tid & 31;
    const int g  = lane >> 2;
    const int tg = lane & 3;
    const int wm = warp * 16;

    const uint32_t smb = (uint32_t)__cvta_generic_to_shared(sm);
    const uint32_t lmrow = (lane & 15);
    const uint32_t lmhi  = (lane >> 4) << 2;

    for (int i = tid; i < 2048; i += 256) {
        int row = i >> 4;
        int c4  = (i & 15) * 4;
        const float4 v = *(const float4*)(qkv +
            (size_t)(b * 1024 + q0 + row) * 1536 + h * 64 + c4);
        float* d = sQ + row * FSTR + c4;
        d[0] = v.x * 0.125f; d[1] = v.y * 0.125f;
        d[2] = v.z * 0.125f; d[3] = v.w * 0.125f;
    }
    __syncthreads();

    uint32_t qf[8][4];
    {
        const uint32_t qbase = smb + (FS_SQ + (wm + lmrow) * FSTR + lmhi) * 4;
        #pragma unroll
        for (int kc = 0; kc < 8; kc++)
            ldsm4(qf[kc][0], qf[kc][1], qf[kc][2], qf[kc][3], qbase + kc * 32);
    }

    float m_[2] = {-1e30f, -1e30f};
    float l_[2] = {0.f, 0.f};
    float acco[8][4];
    #pragma unroll
    for (int i = 0; i < 8; i++)
        #pragma unroll
        for (int r = 0; r < 4; r++) acco[i][r] = 0.f;

    const uint32_t kbase = smb + (FS_SK + lmrow * FSTR + lmhi) * 4;
    const uint32_t pbase = smb + (FS_SP + (wm + lmrow) * PSTR + lmhi) * 4;
    const uint32_t vbase = smb + (FS_SVT + lmrow * PSTR + lmhi) * 4;

    for (int j = 0; j < 8; j++) {
        for (int i = tid; i < 2048; i += 256) {
            int row = i >> 4;
            int c4  = (i & 15) * 4;
            const float* base = qkv + (size_t)(b * 1024 + j * 128 + row) * 1536 + h * 64;
            const float4 kv4 = *(const float4*)(base + 512 + c4);
            float* dk = sK + row * FSTR + c4;
            dk[0] = kv4.x; dk[1] = kv4.y; dk[2] = kv4.z; dk[3] = kv4.w;
            const float4 vv = *(const float4*)(base + 1024 + c4);
            sVt[(c4 + 0) * PSTR + row] = vv.x;
            sVt[(c4 + 1) * PSTR + row] = vv.y;
            sVt[(c4 + 2) * PSTR + row] = vv.z;
            sVt[(c4 + 3) * PSTR + row] = vv.w;
        }
        __syncthreads();

        float accs[16][4];
        #pragma unroll
        for (int nt = 0; nt < 16; nt++)
            #pragma unroll
            for (int r = 0; r < 4; r++) accs[nt][r] = 0.f;

        #pragma unroll
        for (int kc = 0; kc < 8; kc++) {
            const uint32_t ka = kbase + kc * 32;
            #pragma unroll
            for (int p = 0; p < 8; p++) {
                uint32_t b0, b1, b2, b3;
                ldsm4(b0, b1, b2, b3, ka + (uint32_t)(p * 16 * FSTR) * 4);
                uint32_t bf0[2] = {b0, b2};
                uint32_t bf1[2] = {b1, b3};
                mma_tf32(accs[2 * p],     qf[kc], bf0);
                mma_tf32(accs[2 * p + 1], qf[kc], bf1);
            }
        }

        float mx0 = -1e30f, mx1 = -1e30f;
        #pragma unroll
        for (int nt = 0; nt < 16; nt++) {
            mx0 = fmaxf(mx0, fmaxf(accs[nt][0], accs[nt][1]));
            mx1 = fmaxf(mx1, fmaxf(accs[nt][2], accs[nt][3]));
        }
        mx0 = fmaxf(mx0, __shfl_xor_sync(0xffffffffu, mx0, 1));
        mx0 = fmaxf(mx0, __shfl_xor_sync(0xffffffffu, mx0, 2));
        mx1 = fmaxf(mx1, __shfl_xor_sync(0xffffffffu, mx1, 1));
        mx1 = fmaxf(mx1, __shfl_xor_sync(0xffffffffu, mx1, 2));
        const float mn0 = fmaxf(m_[0], mx0);
        const float mn1 = fmaxf(m_[1], mx1);
        const float c0 = __expf(m_[0] - mn0);
        const float c1 = __expf(m_[1] - mn1);
        l_[0] *= c0; l_[1] *= c1;
        #pragma unroll
        for (int nt = 0; nt < 8; nt++) {
            acco[nt][0] *= c0; acco[nt][1] *= c0;
            acco[nt][2] *= c1; acco[nt][3] *= c1;
        }
        float rs0 = 0.f, rs1 = 0.f;
        float* p0 = sP + (wm + g) * PSTR + 2 * tg;
        float* p1 = sP + (wm + g + 8) * PSTR + 2 * tg;
        #pragma unroll
        for (int nt = 0; nt < 16; nt++) {
            const float e0 = __expf(accs[nt][0] - mn0);
            const float e1 = __expf(accs[nt][1] - mn0);
            const float e2 = __expf(accs[nt][2] - mn1);
            const float e3 = __expf(accs[nt][3] - mn1);
            rs0 += e0 + e1; rs1 += e2 + e3;
            p0[nt * 8 + 0] = e0; p0[nt * 8 + 1] = e1;
            p1[nt * 8 + 0] = e2; p1[nt * 8 + 1] = e3;
        }
        rs0 += __shfl_xor_sync(0xffffffffu, rs0, 1);
        rs0 += __shfl_xor_sync(0xffffffffu, rs0, 2);
        rs1 += __shfl_xor_sync(0xffffffffu, rs1, 1);
        rs1 += __shfl_xor_sync(0xffffffffu, rs1, 2);
        l_[0] += rs0; l_[1] += rs1;
        m_[0] = mn0; m_[1] = mn1;
        __syncwarp();

        #pragma unroll
        for (int kc = 0; kc < 16; kc++) {
            uint32_t af[4];
            ldsm4(af[0], af[1], af[2], af[3], pbase + kc * 32);
            const uint32_t va = vbase + kc * 32;
            #pragma unroll
            for (int p = 0; p < 4; p++) {
                uint32_t b0, b1, b2, b3;
                ldsm4(b0, b1, b2, b3, va + (uint32_t)(p * 16 * PSTR) * 4);
                uint32_t bf0[2] = {b0, b2};
                uint32_t bf1[2] = {b1, b3};
                mma_tf32(acco[2 * p],     af, bf0);
                mma_tf32(acco[2 * p + 1], af, bf1);
            }
        }
        __syncthreads();   // before overwriting sK/sVt next iter
    }

    const float i0 = 1.f / l_[0];
    const float i1 = 1.f / l_[1];
    const int row0 = b * 1024 + q0 + wm + g;
    #pragma unroll
    for (int nt = 0; nt < 8; nt++) {
        const int col = h * 64 + nt * 8 + 2 * tg;
        outp[(size_t)row0 * 512 + col]           = acco[nt][0] * i0;
        outp[(size_t)row0 * 512 + col + 1]       = acco[nt][1] * i0;
        outp[(size_t)(row0 + 8) * 512 + col]     = acco[nt][2] * i1;
        outp[(size_t)(row0 + 8) * 512 + col + 1] = acco[nt][3] * i1;
    }
}

// ===========================================================================
// Fused flash cross-attention (kv len 77, padded to 80, single tile).
// ===========================================================================
#define CSTR 84
#define CF_SQ   0
#define CF_SK   (128*FSTR)
#define CF_SVT  (CF_SK + 80*FSTR)
#define CF_SP   (CF_SVT + 64*CSTR)
#define CF_TOTAL (CF_SP + 128*CSTR)

__global__ void __launch_bounds__(256) flash_cross_kernel(
    const float* __restrict__ qsrc, const float* __restrict__ kv2,
    float* __restrict__ outp) {
    extern __shared__ float sm[];
    float* sQ  = sm + CF_SQ;
    float* sK  = sm + CF_SK;
    float* sVt = sm + CF_SVT;
    float* sP  = sm + CF_SP;

    const int b  = blockIdx.y >> 3;
    const int h  = blockIdx.y & 7;
    const int q0 = blockIdx.x * 128;
    const int tid = threadIdx.x;
    const int warp = tid >> 5;
    const int lane = tid & 31;
    const int g  = lane >> 2;
    const int tg = lane & 3;
    const int wm = warp * 16;

    const uint32_t smb = (uint32_t)__cvta_generic_to_shared(sm);
    const uint32_t lmrow = (lane & 15);
    const uint32_t lmhi  = (lane >> 4) << 2;

    for (int i = tid; i < 2048; i += 256) {
        int row = i >> 4;
        int c4  = (i & 15) * 4;
        const float4 v = *(const float4*)(qsrc +
            (size_t)(b * 1024 + q0 + row) * 512 + h * 64 + c4);
        float* d = sQ + row * FSTR + c4;
        d[0] = v.x * 0.125f; d[1] = v.y * 0.125f;
        d[2] = v.z * 0.125f; d[3] = v.w * 0.125f;
    }
    for (int i = tid; i < 1280; i += 256) {
        int row = i >> 4;
        int c4  = (i & 15) * 4;
        float4 kk = make_float4(0.f, 0.f, 0.f, 0.f);
        float4 vv = make_float4(0.f, 0.f, 0.f, 0.f);
        if (row < KVLEN) {
            const float* base = kv2 + (size_t)(b * KVLEN + row) * 1024 + h * 64;
            kk = *(const float4*)(base + c4);
            vv = *(const float4*)(base + 512 + c4);
        }
        float* dk = sK + row * FSTR + c4;
        dk[0] = kk.x; dk[1] = kk.y; dk[2] = kk.z; dk[3] = kk.w;
        sVt[(c4 + 0) * CSTR + row] = vv.x;
        sVt[(c4 + 1) * CSTR + row] = vv.y;
        sVt[(c4 + 2) * CSTR + row] = vv.z;
        sVt[(c4 + 3) * CSTR + row] = vv.w;
    }
    __syncthreads();

    uint32_t qf[8][4];
    {
        const uint32_t qbase = smb + (CF_SQ + (wm + lmrow) * FSTR + lmhi) * 4;
        #pragma unroll
        for (int kc = 0; kc < 8; kc++)
            ldsm4(qf[kc][0], qf[kc][1], qf[kc][2], qf[kc][3], qbase + kc * 32);
    }

    float accs[10][4];
    #pragma unroll
    for (int nt = 0; nt < 10; nt++)
        #pragma unroll
        for (int r = 0; r < 4; r++) accs[nt][r] = 0.f;
    {
        const uint32_t kbase = smb + (CF_SK + lmrow * FSTR + lmhi) * 4;
        #pragma unroll
        for (int kc = 0; kc < 8; kc++) {
            const uint32_t ka = kbase + kc * 32;
            #pragma unroll
            for (int p = 0; p < 5; p++) {
                uint32_t b0, b1, b2, b3;
                ldsm4(b0, b1, b2, b3, ka + (uint32_t)(p * 16 * FSTR) * 4);
                uint32_t bf0[2] = {b0, b2};
                uint32_t bf1[2] = {b1, b3};
                mma_tf32(accs[2 * p],     qf[kc], bf0);
                mma_tf32(accs[2 * p + 1], qf[kc], bf1);
            }
        }
    }

    #pragma unroll
    for (int nt = 0; nt < 10; nt++) {
        const int col0 = nt * 8 + 2 * tg;
        if (col0 >= KVLEN)     { accs[nt][0] = -1e30f; accs[nt][2] = -1e30f; }
        if (col0 + 1 >= KVLEN) { accs[nt][1] = -1e30f; accs[nt][3] = -1e30f; }
    }
    float mx0 = -1e30f, mx1 = -1e30f;
    #pragma unroll
    for (int nt = 0; nt < 10; nt++) {
        mx0 = fmaxf(mx0, fmaxf(accs[nt][0], accs[nt][1]));
        mx1 = fmaxf(mx1, fmaxf(accs[nt][2], accs[nt][3]));
    }
    mx0 = fmaxf(mx0, __shfl_xor_sync(0xffffffffu, mx0, 1));
    mx0 = fmaxf(mx0, __shfl_xor_sync(0xffffffffu, mx0, 2));
    mx1 = fmaxf(mx1, __shfl_xor_sync(0xffffffffu, mx1, 1));
    mx1 = fmaxf(mx1, __shfl_xor_sync(0xffffffffu, mx1, 2));

    float rs0 = 0.f, rs1 = 0.f;
    float* p0 = sP + (wm + g) * CSTR + 2 * tg;
    float* p1 = sP + (wm + g + 8) * CSTR + 2 * tg;
    #pragma unroll
    for (int nt = 0; nt < 10; nt++) {
        const float e0 = __expf(accs[nt][0] - mx0);
        const float e1 = __expf(accs[nt][1] - mx0);
        const float e2 = __expf(accs[nt][2] - mx1);
        const float e3 = __expf(accs[nt][3] - mx1);
        rs0 += e0 + e1; rs1 += e2 + e3;
        p0[nt * 8 + 0] = e0; p0[nt * 8 + 1] = e1;
        p1[nt * 8 + 0] = e2; p1[nt * 8 + 1] = e3;
    }
    rs0 += __shfl_xor_sync(0xffffffffu, rs0, 1);
    rs0 += __shfl_xor_sync(0xffffffffu, rs0, 2);
    rs1 += __shfl_xor_sync(0xffffffffu, rs1, 1);
    rs1 += __shfl_xor_sync(0xffffffffu, rs1, 2);
    __syncwarp();

    float acco[8][4];
    #pragma unroll
    for (int nt = 0; nt < 8; nt++)
        #pragma unroll
        for (int r = 0; r < 4; r++) acco[nt][r] = 0.f;
    {
        const uint32_t pb = smb + (CF_SP + (wm + lmrow) * CSTR + lmhi) * 4;
        const uint32_t vb = smb + (CF_SVT + lmrow * CSTR + lmhi) * 4;
        #pragma unroll
        for (int kc = 0; kc < 10; kc++) {
            uint32_t af[4];
            ldsm4(af[0], af[1], af[2], af[3], pb + kc * 32);
            const uint32_t va = vb + kc * 32;
            #pragma unroll
            for (int p = 0; p < 4; p++) {
                uint32_t b0, b1, b2, b3;
                ldsm4(b0, b1, b2, b3, va + (uint32_t)(p * 16 * CSTR) * 4);
                uint32_t bf0[2] = {b0, b2};
                uint32_t bf1[2] = {b1, b3};
                mma_tf32(acco[2 * p],     af, bf0);
                mma_tf32(acco[2 * p + 1], af, bf1);
            }
        }
    }

    const float i0 = 1.f / rs0;
    const float i1 = 1.f / rs1;
    const int row0 = b * 1024 + q0 + wm + g;
    #pragma unroll
    for (int nt = 0; nt < 8; nt++) {
        const int col = h * 64 + nt * 8 + 2 * tg;
        outp[(size_t)row0 * 512 + col]           = acco[nt][0] * i0;
        outp[(size_t)row0 * 512 + col + 1]       = acco[nt][1] * i0;
        outp[(size_t)(row0 + 8) * 512 + col]     = acco[nt][2] * i1;
        outp[(size_t)(row0 + 8) * 512 + col + 1] = acco[nt][3] * i1;
    }
}

// ===========================================================================
// TF32 tensor-core GEMM: C = A @ Bt^T (+bias)(+Res / GEGLU)
//   A [M,K] row-major, Bt [N,K] row-major (pre-transposed weights).
//   N % 128 == 0, K % 64 == 0. M may be ragged (616).
//   BK=64, 3-stage cp.async pipeline, ONE barrier per k-tile,
//   ldmatrix for BOTH A and B fragments (both k-major, stride 68).
// ===========================================================================
#define BM 128
#define BN 128
#define BK 64
#define GSTR 68                          // 64 k + 4 pad floats
#define STG_HALF (128*GSTR)              // 8704 floats (A or B)
#define STG_FLOATS (2*STG_HALF)          // 17408 floats = 69632 B
#define GEMM_SMEM (3 * STG_FLOATS * 4)   // 208896 B

__global__ void __launch_bounds__(256) gemm_tf32_kernel(
    const float* __restrict__ A, int lda,
    const float* __restrict__ Bt, int ldb,
    float* __restrict__ C, int ldc,
    const float* __restrict__ Res, int ldres,
    const float* __restrict__ bias,
    int M, int K, int emode) {

    extern __shared__ float smem[];

    const int m0 = blockIdx.y * BM;
    const int n0 = blockIdx.x * BN;
    const int tid = threadIdx.x;
    const int warp = tid >> 5;
    const int lane = tid & 31;
    const int g  = lane >> 2;
    const int tg = lane & 3;
    const int wm = (warp >> 2) * 64;   // warp M offset
    const int wn = (warp & 3) * 32;    // warp N offset

    const uint32_t smem_u32 = (uint32_t)__cvta_generic_to_shared(smem);
    const int nk = K / BK;

    float acc[4][4][4];
    #pragma unroll
    for (int i = 0; i < 4; i++)
        #pragma unroll
        for (int j = 0; j < 4; j++)
            #pragma unroll
            for (int r = 0; r < 4; r++) acc[i][j][r] = 0.f;

    auto load_stage = [&](int stage, int k0) {
        const uint32_t abase = smem_u32 + (uint32_t)(stage * STG_FLOATS) * 4;
        // A: 128 rows x 64 floats = 2048 16B chunks, 8 per thread
        #pragma unroll
        for (int i = 0; i < 8; i++) {
            int idx = tid + i * 256;
            int row = idx >> 4;
            int kc  = (idx & 15) * 4;
            int bytes = (m0 + row < M) ? 16 : 0;
            cp_async16(abase + (uint32_t)(row * GSTR + kc) * 4,
                       A + (long long)(m0 + row) * lda + k0 + kc, bytes);
        }
        // Bt: 128 n-rows x 64 floats
        const uint32_t bbase = abase + (uint32_t)STG_HALF * 4;
        #pragma unroll
        for (int i = 0; i < 8; i++) {
            int idx = tid + i * 256;
            int row = idx >> 4;
            int kc  = (idx & 15) * 4;
            cp_async16(bbase + (uint32_t)(row * GSTR + kc) * 4,
                       Bt + (long long)(n0 + row) * ldb + k0 + kc, 16);
        }
        cp_commit();
    };

    // ldmatrix bases (stage 0): row = tile_base + lane%16, col = (lane>>4)*4
    const uint32_t lm_off = (uint32_t)((lane & 15) * GSTR + ((lane >> 4) << 2)) * 4;
    const uint32_t a_lm = smem_u32 + (uint32_t)(wm * GSTR) * 4 + lm_off;
    const uint32_t b_lm = smem_u32 + (uint32_t)(STG_HALF + wn * GSTR) * 4 + lm_off;

    auto compute_stage = [&](int stage) {
        const uint32_t soff = (uint32_t)(stage * STG_FLOATS) * 4;
        const uint32_t ab = a_lm + soff;
        const uint32_t bb = b_lm + soff;
        #pragma unroll
        for (int ks = 0; ks < 8; ks++) {
            const uint32_t kkb = (uint32_t)(ks * 8) * 4;
            uint32_t afr[4][4];
            #pragma unroll
            for (int mt = 0; mt < 4; mt++)
                ldsm4(afr[mt][0], afr[mt][1], afr[mt][2], afr[mt][3],
                      ab + (uint32_t)(mt * 16 * GSTR) * 4 + kkb);
            uint32_t bfr[4][2];
            #pragma unroll
            for (int p = 0; p < 2; p++) {
                uint32_t r0, r1, r2, r3;
                ldsm4(r0, r1, r2, r3, bb + (uint32_t)(p * 16 * GSTR) * 4 + kkb);
                bfr[2 * p][0]     = r0; bfr[2 * p][1]     = r2;
                bfr[2 * p + 1][0] = r1; bfr[2 * p + 1][1] = r3;
            }
            #pragma unroll
            for (int mt = 0; mt < 4; mt++)
                #pragma unroll
                for (int nt = 0; nt < 4; nt++)
                    mma_tf32(acc[mt][nt], afr[mt], bfr[nt]);
        }
    };

    load_stage(0, 0);
    if (nk > 1) load_stage(1, BK);
    for (int kt = 0; kt < nk; kt++) {
        if (kt + 1 < nk) cp_wait1(); else cp_wait0();
        __syncthreads();
        if (kt + 2 < nk) load_stage((kt + 2) % 3, (kt + 2) * BK);
        compute_stage(kt % 3);
    }

    // ---- epilogue ----
    #pragma unroll
    for (int mt = 0; mt < 4; mt++) {
        #pragma unroll
        for (int nt = 0; nt < 4; nt++) {
            const int row0 = m0 + wm + mt * 16 + g;
            const int col0 = n0 + wn + nt * 8 + tg * 2;
            #pragma unroll
            for (int r = 0; r < 4; r++) {
                const int row = row0 + (r >> 1) * 8;
                const int col = col0 + (r & 1);
                if (row < M) {
                    float v = acc[mt][nt][r];
                    if (bias) v += bias[col];
                    if (emode == 1) {
                        float ge = 0.5f * v * (1.f + erff(v * 0.70710678118654752f));
                        v = Res[(long long)row * ldres + col] * ge;
                    } else if (Res) {
                        v += Res[(long long)row * ldres + col];
                    }
                    C[(long long)row * ldc + col] = v;
                }
            }
        }
    }
}

// ---------------------------------------------------------------------------
// Host side
// ---------------------------------------------------------------------------
static void gemm(const float* A, int lda, const float* Bt, int ldb,
                 float* C, int ldc, const float* Res, int ldres,
                 const float* bias, int M, int N, int K, int emode = 0) {
    dim3 grid(N / BN, (M + BM - 1) / BM);
    gemm_tf32_kernel<<<grid, 256, GEMM_SMEM>>>(
        A, lda, Bt, ldb, C, ldc, Res, ldres, bias, M, K, emode);
}
static void tr(const float* src, float* dst, int R, int C) {
    dim3 grid(C / 32, R / 32), blk(32, 8);
    transpose_kernel<<<grid, blk>>>(src, dst, R, C);
}

extern "C" void kernel_launch(void* const* d_in, const int* in_sizes, int n_in,
                              void* d_out, int out_size) {
    const float* in_q     = (const float*)d_in[0];
    const float* in_kv    = (const float*)d_in[1];
    const float* gn_g     = (const float*)d_in[2];
    const float* gn_b     = (const float*)d_in[3];
    const float* ln2_g    = (const float*)d_in[4];
    const float* ln2_b    = (const float*)d_in[5];
    const float* ln3_g    = (const float*)d_in[6];
    const float* ln3_b    = (const float*)d_in[7];
    const float* ln4_g    = (const float*)d_in[8];
    const float* ln4_b    = (const float*)d_in[9];
    const float* fc_in_w  = (const float*)d_in[10];
    const float* fc_in_b  = (const float*)d_in[11];
    const float* fc_out_w = (const float*)d_in[12];
    const float* fc_out_b = (const float*)d_in[13];
    const float* a1_q     = (const float*)d_in[14];
    const float* a1_k     = (const float*)d_in[15];
    const float* a1_v     = (const float*)d_in[16];
    const float* a1_o     = (const float*)d_in[17];
    const float* a1_ob    = (const float*)d_in[18];
    const float* a2_q     = (const float*)d_in[19];
    const float* a2_k     = (const float*)d_in[20];
    const float* a2_v     = (const float*)d_in[21];
    const float* a2_o     = (const float*)d_in[22];
    const float* a2_ob    = (const float*)d_in[23];
    const float* ff_proj_w = (const float*)d_in[24];
    const float* ff_proj_b = (const float*)d_in[25];
    const float* ff_out_w  = (const float*)d_in[26];
    const float* ff_out_b  = (const float*)d_in[27];

    cudaFuncSetAttribute(gemm_tf32_kernel,
                         cudaFuncAttributeMaxDynamicSharedMemorySize, GEMM_SMEM);
    cudaFuncSetAttribute(flash_self_kernel,
                         cudaFuncAttributeMaxDynamicSharedMemorySize, FS_TOTAL * 4);
    cudaFuncSetAttribute(flash_cross_kernel,
                         cudaFuncAttributeMaxDynamicSharedMemorySize, CF_TOTAL * 4);

    float *x, *t, *q, *qkv, *kv2, *gl;
    float *wtFcIn, *wtQkv, *wtA1o, *wtA2q, *wtA2o, *wtKv2, *wtFfp, *wtFfo, *wtFco;
    cudaGetSymbolAddress((void**)&x,   g_x);
    cudaGetSymbolAddress((void**)&t,   g_t);
    cudaGetSymbolAddress((void**)&q,   g_q);
    cudaGetSymbolAddress((void**)&qkv, g_qkv);
    cudaGetSymbolAddress((void**)&kv2, g_kv2);
    cudaGetSymbolAddress((void**)&gl,  g_gl);
    cudaGetSymbolAddress((void**)&wtFcIn, g_wtFcIn);
    cudaGetSymbolAddress((void**)&wtQkv,  g_wtQkv);
    cudaGetSymbolAddress((void**)&wtA1o,  g_wtA1o);
    cudaGetSymbolAddress((void**)&wtA2q,  g_wtA2q);
    cudaGetSymbolAddress((void**)&wtA2o,  g_wtA2o);
    cudaGetSymbolAddress((void**)&wtKv2,  g_wtKv2);
    cudaGetSymbolAddress((void**)&wtFfp,  g_wtFfp);
    cudaGetSymbolAddress((void**)&wtFfo,  g_wtFfo);
    cudaGetSymbolAddress((void**)&wtFco,  g_wtFco);

    float* out = (float*)d_out;

    // ---- weight transposes ([K,N] -> [N,K]); qkv/kv packing via slices ----
    tr(fc_in_w, wtFcIn, 512, 512);
    tr(a1_q, wtQkv + 0,                  512, 512);
    tr(a1_k, wtQkv + (size_t)512 * 512,  512, 512);
    tr(a1_v, wtQkv + (size_t)1024 * 512, 512, 512);
    tr(a1_o, wtA1o, 512, 512);
    tr(a2_q, wtA2q, 512, 512);
    tr(a2_o, wtA2o, 512, 512);
    tr(a2_k, wtKv2 + 0,                   1024, 512);
    tr(a2_v, wtKv2 + (size_t)512 * 1024,  1024, 512);
    tr(ff_proj_w, wtFfp, 512, 4096);
    tr(ff_out_w,  wtFfo, 2048, 512);
    tr(fc_out_w,  wtFco, 512, 512);

    // 1. GroupNorm + transpose to tokens -> t
    groupnorm_kernel<<<BATCH * 32, 256>>>(in_q, gn_g, gn_b, t);

    // 2. x = t @ fc_in + b
    gemm(t, 512, wtFcIn, 512, x, 512, nullptr, 0, fc_in_b, NTOK, 512, 512);

    // ---- self attention ----
    layernorm_kernel<<<NTOK / 8, 256>>>(x, ln2_g, ln2_b, t, NTOK);
    gemm(t, 512, wtQkv, 512, qkv, 1536, nullptr, 0, nullptr, NTOK, 1536, 512);
    {
        dim3 grid(8, 64);
        flash_self_kernel<<<grid, 256, FS_TOTAL * 4>>>(qkv, t);
    }
    gemm(t, 512, wtA1o, 512, x, 512, x, 512, a1_ob, NTOK, 512, 512);

    // ---- cross attention ----
    layernorm_kernel<<<NTOK / 8, 256>>>(x, ln3_g, ln3_b, t, NTOK);
    gemm(t, 512, wtA2q, 512, q, 512, nullptr, 0, nullptr, NTOK, 512, 512);
    gemm(in_kv, 1024, wtKv2, 1024, kv2, 1024, nullptr, 0, nullptr,
         BATCH * KVLEN, 1024, 1024);
    {
        dim3 grid(8, 64);
        flash_cross_kernel<<<grid, 256, CF_TOTAL * 4>>>(q, kv2, t);
    }
    gemm(t, 512, wtA2o, 512, x, 512, x, 512, a2_ob, NTOK, 512, 512);

    // ---- feed-forward (GEGLU fused) ----
    layernorm_kernel<<<NTOK / 8, 256>>>(x, ln4_g, ln4_b, t, NTOK);
    gemm(t, 512, wtFfp, 512, gl, 2048, nullptr, 0, ff_proj_b, NTOK, 2048, 512);
    gemm(t, 512, wtFfp + (size_t)2048 * 512, 512, gl, 2048, gl, 2048,
         ff_proj_b + 2048, NTOK, 2048, 512, 1);
    gemm(gl, 2048, wtFfo, 2048, x, 512, x, 512, ff_out_b, NTOK, 512, 2048);

    // ---- output projection ----
    gemm(x, 512, wtFco, 512, t, 512, nullptr, 0, fc_out_b, NTOK, 512, 512);

    output_kernel<<<(BATCH * DIMC * SPATIAL) / 256, 256>>>(t, in_q, out);
}

// round 10
// speedup vs baseline: 1.6241x; 1.6241x over previous
#include <cuda_runtime.h>
#include <cuda_fp16.h>
#include <cstdint>
#include <math.h>

// ---------------------------------------------------------------------------
// Problem constants
// ---------------------------------------------------------------------------
#define BATCH   8
#define DIMC    512
#define SPATIAL 1024
#define NTOK    (BATCH*SPATIAL)  // 8192
#define HEADS   8
#define HDIM    64
#define KVLEN   77
#define KVDIM   1024

// ---------------------------------------------------------------------------
// Scratch buffers
// ---------------------------------------------------------------------------
__device__ float  g_x  [(size_t)NTOK * DIMC];           // fp32 residual stream
__device__ float  g_t  [(size_t)NTOK * DIMC];           // fp32 temp (fco out)
__device__ float  g_gb [(size_t)NTOK * 2048];           // gelu(gate) fp32
__device__ __half g_th  [(size_t)NTOK * DIMC];          // half activations (LN/GN/flash out)
__device__ __half g_qkvh[(size_t)NTOK * 1536];
__device__ __half g_qh  [(size_t)NTOK * DIMC];
__device__ __half g_kvh [(size_t)(BATCH*KVLEN) * 1024]; // in_kv converted
__device__ __half g_kv2h[(size_t)(BATCH*KVLEN) * 1024];
__device__ __half g_glh [(size_t)NTOK * 2048];
__device__ __half g_xh  [(size_t)NTOK * DIMC];
// half transposed weights [N, K]
__device__ __half g_whFcIn[(size_t)512 * 512];
__device__ __half g_whQkv [(size_t)1536 * 512];
__device__ __half g_whA1o [(size_t)512 * 512];
__device__ __half g_whA2q [(size_t)512 * 512];
__device__ __half g_whA2o [(size_t)512 * 512];
__device__ __half g_whKv2 [(size_t)1024 * 1024];
__device__ __half g_whFfp [(size_t)4096 * 512];
__device__ __half g_whFfo [(size_t)512 * 2048];
__device__ __half g_whFco [(size_t)512 * 512];

// ---------------------------------------------------------------------------
// Helpers
// ---------------------------------------------------------------------------
__device__ __forceinline__ float warpSum(float v) {
    #pragma unroll
    for (int o = 16; o > 0; o >>= 1) v += __shfl_xor_sync(0xffffffffu, v, o);
    return v;
}
__device__ __forceinline__ void mma_f16(float* d, const uint32_t* a, const uint32_t* b) {
    asm volatile(
        "mma.sync.aligned.m16n8k16.row.col.f32.f16.f16.f32 "
        "{%0,%1,%2,%3}, {%4,%5,%6,%7}, {%8,%9}, {%0,%1,%2,%3};"
        : "+f"(d[0]), "+f"(d[1]), "+f"(d[2]), "+f"(d[3])
        : "r"(a[0]), "r"(a[1]), "r"(a[2]), "r"(a[3]), "r"(b[0]), "r"(b[1]));
}
__device__ __forceinline__ void ldsm4(uint32_t& r0, uint32_t& r1,
                                      uint32_t& r2, uint32_t& r3, uint32_t addr) {
    asm volatile("ldmatrix.sync.aligned.m8n8.x4.shared.b16 {%0,%1,%2,%3}, [%4];"
                 : "=r"(r0), "=r"(r1), "=r"(r2), "=r"(r3) : "r"(addr));
}
__device__ __forceinline__ void cp_async16(uint32_t dst, const void* src, int bytes) {
    asm volatile("cp.async.cg.shared.global [%0], [%1], 16, %2;\n"
                 :: "r"(dst), "l"(src), "r"(bytes));
}
__device__ __forceinline__ void cp_commit() { asm volatile("cp.async.commit_group;\n"); }
__device__ __forceinline__ void cp_wait1()  { asm volatile("cp.async.wait_group 1;\n"); }
__device__ __forceinline__ void cp_wait0()  { asm volatile("cp.async.wait_group 0;\n"); }

// ---------------------------------------------------------------------------
// GroupNorm + transpose to token-major, half output
// ---------------------------------------------------------------------------
__global__ void groupnorm_kernel(const float* __restrict__ qin,
                                 const float* __restrict__ gamma,
                                 const float* __restrict__ beta,
                                 __half* __restrict__ out) {
    const int blk = blockIdx.x;
    const int b = blk >> 5;
    const int grp = blk & 31;
    const float* base = qin + ((size_t)b * DIMC + grp * 16) * SPATIAL;

    float s = 0.f, s2 = 0.f;
    for (int i = threadIdx.x; i < 16 * SPATIAL; i += 256) {
        float v = base[i];
        s += v; s2 += v * v;
    }
    __shared__ float red[2][8];
    s = warpSum(s); s2 = warpSum(s2);
    int wid = threadIdx.x >> 5, lid = threadIdx.x & 31;
    if (lid == 0) { red[0][wid] = s; red[1][wid] = s2; }
    __syncthreads();
    if (wid == 0) {
        float a = (lid < 8) ? red[0][lid] : 0.f;
        float c = (lid < 8) ? red[1][lid] : 0.f;
        a = warpSum(a); c = warpSum(c);
        if (lid == 0) { red[0][0] = a; red[1][0] = c; }
    }
    __syncthreads();
    const float mu  = red[0][0] * (1.f / 16384.f);
    const float var = red[1][0] * (1.f / 16384.f) - mu * mu;
    const float inv = rsqrtf(var + 1e-6f);

    for (int i = threadIdx.x; i < 16 * SPATIAL; i += 256) {
        int c = grp * 16 + (i >> 10);
        int sp = i & 1023;
        float v = (base[i] - mu) * inv * gamma[c] + beta[c];
        out[((size_t)(b * SPATIAL + sp)) * DIMC + c] = __float2half(v);
    }
}

// ---------------------------------------------------------------------------
// LayerNorm (fp32 in, half out). One warp per 512-dim row.
// ---------------------------------------------------------------------------
__global__ void layernorm_kernel(const float* __restrict__ x,
                                 const float* __restrict__ gamma,
                                 const float* __restrict__ beta,
                                 __half* __restrict__ out, int rows) {
    int row = blockIdx.x * 8 + (threadIdx.x >> 5);
    if (row >= rows) return;
    int lid = threadIdx.x & 31;
    const float4* xr = (const float4*)(x + (size_t)row * DIMC);

    float4 vals[4];
    float s = 0.f, s2 = 0.f;
    #pragma unroll
    for (int i = 0; i < 4; i++) {
        float4 v = xr[lid + 32 * i];
        vals[i] = v;
        s  += v.x + v.y + v.z + v.w;
        s2 += v.x*v.x + v.y*v.y + v.z*v.z + v.w*v.w;
    }
    s = warpSum(s); s2 = warpSum(s2);
    const float mu  = s * (1.f / 512.f);
    const float inv = rsqrtf(s2 * (1.f / 512.f) - mu * mu + 1e-5f);

    __half2* orow = (__half2*)(out + (size_t)row * DIMC);
    const float4* g4 = (const float4*)gamma;
    const float4* b4 = (const float4*)beta;
    #pragma unroll
    for (int i = 0; i < 4; i++) {
        int idx = lid + 32 * i;
        float4 v = vals[i], g = g4[idx], b = b4[idx];
        float ox = (v.x - mu) * inv * g.x + b.x;
        float oy = (v.y - mu) * inv * g.y + b.y;
        float oz = (v.z - mu) * inv * g.z + b.z;
        float ow = (v.w - mu) * inv * g.w + b.w;
        orow[idx * 2]     = __floats2half2_rn(ox, oy);
        orow[idx * 2 + 1] = __floats2half2_rn(oz, ow);
    }
}

// ---------------------------------------------------------------------------
// Transpose + f32->f16 convert: src [R, C] f32 -> dst [C, R] half
// ---------------------------------------------------------------------------
__global__ void trcvt_kernel(const float* __restrict__ src,
                             __half* __restrict__ dst, int R, int C) {
    __shared__ float tile[32][33];
    int c0 = blockIdx.x * 32, r0 = blockIdx.y * 32;
    int x = threadIdx.x, y = threadIdx.y;
    #pragma unroll
    for (int i = 0; i < 32; i += 8)
        tile[y + i][x] = src[(size_t)(r0 + y + i) * C + c0 + x];
    __syncthreads();
    #pragma unroll
    for (int i = 0; i < 32; i += 8)
        dst[(size_t)(c0 + y + i) * R + r0 + x] = __float2half(tile[x][y + i]);
}

// f32 -> f16 linear convert
__global__ void cvt_kernel(const float* __restrict__ src,
                           __half* __restrict__ dst, int n) {
    int i = blockIdx.x * 256 + threadIdx.x;
    if (i < n) dst[i] = __float2half(src[i]);
}

// ---------------------------------------------------------------------------
// Final transpose + residual
// ---------------------------------------------------------------------------
__global__ void output_kernel(const float* __restrict__ t,
                              const float* __restrict__ qin,
                              float* __restrict__ out) {
    int i = blockIdx.x * 256 + threadIdx.x;
    if (i >= BATCH * DIMC * SPATIAL) return;
    int sp = i & 1023;
    int bc = i >> 10;
    int c = bc & 511;
    int b = bc >> 9;
    out[i] = t[((size_t)(b * SPATIAL + sp)) * DIMC + c] + qin[i];
}

// ===========================================================================
// Fused flash self-attention, fp16 operands, fp32 accum.
//   qkvh [8192 x 1536] half. Out -> th [8192 x 512] half.
//   Softmax scale 1/8 folded into exp argument.
// ===========================================================================
#define SCL 0.125f
#define FH 72     // Q/K smem row stride (halves): 64 + 8
#define PH 136    // P / Vt stride (halves): 128 + 8
#define FS_SQ   0
#define FS_SK   (128*FH)
#define FS_SVT  (FS_SK + 128*FH)
#define FS_SP   (FS_SVT + 64*PH)
#define FS_TOTAL_H (FS_SP + 128*PH)     // halves

__global__ void __launch_bounds__(256) flash_self_kernel(
    const __half* __restrict__ qkv, __half* __restrict__ outp) {
    extern __shared__ __half smh[];
    __half* sQ  = smh + FS_SQ;
    __half* sK  = smh + FS_SK;
    __half* sVt = smh + FS_SVT;
    __half* sP  = smh + FS_SP;

    const int b  = blockIdx.y >> 3;
    const int h  = blockIdx.y & 7;
    const int q0 = blockIdx.x * 128;
    const int tid = threadIdx.x;
    const int warp = tid >> 5;
    const int lane = tid & 31;
    const int g  = lane >> 2;
    const int tg = lane & 3;
    const int wm = warp * 16;

    const uint32_t smb = (uint32_t)__cvta_generic_to_shared(smh);
    const uint32_t lr = lane & 15;
    const uint32_t lh = (lane >> 4) * 8;   // +8 halves for upper matrices

    // ---- load Q tile (plain copy; scale folded into exp) ----
    for (int i = tid; i < 1024; i += 256) {
        int row = i >> 3;
        int c8  = (i & 7) * 8;
        *(uint4*)(sQ + row * FH + c8) = *(const uint4*)(qkv +
            (size_t)(b * 1024 + q0 + row) * 1536 + h * 64 + c8);
    }
    __syncthreads();

    uint32_t qf[4][4];
    {
        const uint32_t qbase = smb + (uint32_t)(FS_SQ + (wm + lr) * FH + lh) * 2;
        #pragma unroll
        for (int kc = 0; kc < 4; kc++)
            ldsm4(qf[kc][0], qf[kc][1], qf[kc][2], qf[kc][3], qbase + kc * 32);
    }

    float m_[2] = {-1e30f, -1e30f};
    float l_[2] = {0.f, 0.f};
    float acco[8][4];
    #pragma unroll
    for (int i = 0; i < 8; i++)
        #pragma unroll
        for (int r = 0; r < 4; r++) acco[i][r] = 0.f;

    const uint32_t kbase = smb + (uint32_t)(FS_SK + lr * FH + lh) * 2;
    const uint32_t pbase = smb + (uint32_t)(FS_SP + (wm + lr) * PH + lh) * 2;
    const uint32_t vbase = smb + (uint32_t)(FS_SVT + lr * PH + lh) * 2;

    for (int j = 0; j < 8; j++) {
        // ---- load K + V(transposed) ----
        for (int i = tid; i < 1024; i += 256) {
            int row = i >> 3;
            int c8  = (i & 7) * 8;
            const __half* base = qkv + (size_t)(b * 1024 + j * 128 + row) * 1536 + h * 64;
            *(uint4*)(sK + row * FH + c8) = *(const uint4*)(base + 512 + c8);
            uint4 vv = *(const uint4*)(base + 1024 + c8);
            const __half* hv = (const __half*)&vv;
            #pragma unroll
            for (int q = 0; q < 8; q++) sVt[(c8 + q) * PH + row] = hv[q];
        }
        __syncthreads();

        // ---- S = Q @ K^T (16 x 128 per warp) ----
        float accs[16][4];
        #pragma unroll
        for (int nt = 0; nt < 16; nt++)
            #pragma unroll
            for (int r = 0; r < 4; r++) accs[nt][r] = 0.f;

        #pragma unroll
        for (int kc = 0; kc < 4; kc++) {
            const uint32_t ka = kbase + kc * 32;
            #pragma unroll
            for (int p = 0; p < 8; p++) {
                uint32_t b0, b1, b2, b3;
                ldsm4(b0, b1, b2, b3, ka + (uint32_t)(p * 16 * FH) * 2);
                uint32_t bf0[2] = {b0, b2};
                uint32_t bf1[2] = {b1, b3};
                mma_f16(accs[2 * p],     qf[kc], bf0);
                mma_f16(accs[2 * p + 1], qf[kc], bf1);
            }
        }

        // ---- online softmax (scale 1/8 in exp) ----
        float mx0 = -1e30f, mx1 = -1e30f;
        #pragma unroll
        for (int nt = 0; nt < 16; nt++) {
            mx0 = fmaxf(mx0, fmaxf(accs[nt][0], accs[nt][1]));
            mx1 = fmaxf(mx1, fmaxf(accs[nt][2], accs[nt][3]));
        }
        mx0 = fmaxf(mx0, __shfl_xor_sync(0xffffffffu, mx0, 1));
        mx0 = fmaxf(mx0, __shfl_xor_sync(0xffffffffu, mx0, 2));
        mx1 = fmaxf(mx1, __shfl_xor_sync(0xffffffffu, mx1, 1));
        mx1 = fmaxf(mx1, __shfl_xor_sync(0xffffffffu, mx1, 2));
        const float mn0 = fmaxf(m_[0], mx0);
        const float mn1 = fmaxf(m_[1], mx1);
        const float c0 = __expf((m_[0] - mn0) * SCL);
        const float c1 = __expf((m_[1] - mn1) * SCL);
        l_[0] *= c0; l_[1] *= c1;
        #pragma unroll
        for (int nt = 0; nt < 8; nt++) {
            acco[nt][0] *= c0; acco[nt][1] *= c0;
            acco[nt][2] *= c1; acco[nt][3] *= c1;
        }
        float rs0 = 0.f, rs1 = 0.f;
        __half* p0 = sP + (wm + g) * PH + 2 * tg;
        __half* p1 = sP + (wm + g + 8) * PH + 2 * tg;
        #pragma unroll
        for (int nt = 0; nt < 16; nt++) {
            const float e0 = __expf((accs[nt][0] - mn0) * SCL);
            const float e1 = __expf((accs[nt][1] - mn0) * SCL);
            const float e2 = __expf((accs[nt][2] - mn1) * SCL);
            const float e3 = __expf((accs[nt][3] - mn1) * SCL);
            rs0 += e0 + e1; rs1 += e2 + e3;
            *(__half2*)(p0 + nt * 8) = __floats2half2_rn(e0, e1);
            *(__half2*)(p1 + nt * 8) = __floats2half2_rn(e2, e3);
        }
        rs0 += __shfl_xor_sync(0xffffffffu, rs0, 1);
        rs0 += __shfl_xor_sync(0xffffffffu, rs0, 2);
        rs1 += __shfl_xor_sync(0xffffffffu, rs1, 1);
        rs1 += __shfl_xor_sync(0xffffffffu, rs1, 2);
        l_[0] += rs0; l_[1] += rs1;
        m_[0] = mn0; m_[1] = mn1;
        __syncwarp();

        // ---- O += P @ V  (K = 128 -> 8 k16 chunks) ----
        #pragma unroll
        for (int kc = 0; kc < 8; kc++) {
            uint32_t af[4];
            ldsm4(af[0], af[1], af[2], af[3], pbase + kc * 32);
            const uint32_t va = vbase + kc * 32;
            #pragma unroll
            for (int p = 0; p < 4; p++) {
                uint32_t b0, b1, b2, b3;
                ldsm4(b0, b1, b2, b3, va + (uint32_t)(p * 16 * PH) * 2);
                uint32_t bf0[2] = {b0, b2};
                uint32_t bf1[2] = {b1, b3};
                mma_f16(acco[2 * p],     af, bf0);
                mma_f16(acco[2 * p + 1], af, bf1);
            }
        }
        __syncthreads();
    }

    const float i0 = 1.f / l_[0];
    const float i1 = 1.f / l_[1];
    const int row0 = b * 1024 + q0 + wm + g;
    #pragma unroll
    for (int nt = 0; nt < 8; nt++) {
        const int col = h * 64 + nt * 8 + 2 * tg;
        *(__half2*)(outp + (size_t)row0 * 512 + col) =
            __floats2half2_rn(acco[nt][0] * i0, acco[nt][1] * i0);
        *(__half2*)(outp + (size_t)(row0 + 8) * 512 + col) =
            __floats2half2_rn(acco[nt][2] * i1, acco[nt][3] * i1);
    }
}

// ===========================================================================
// Fused flash cross-attention (kv 77 -> padded 80), fp16.
// ===========================================================================
#define CH 88     // cross Vt/P stride: 80 + 8
#define CF_SQ   0
#define CF_SK   (128*FH)
#define CF_SVT  (CF_SK + 80*FH)
#define CF_SP   (CF_SVT + 64*CH)
#define CF_TOTAL_H (CF_SP + 128*CH)

__global__ void __launch_bounds__(256) flash_cross_kernel(
    const __half* __restrict__ qsrc, const __half* __restrict__ kv2,
    __half* __restrict__ outp) {
    extern __shared__ __half smh[];
    __half* sQ  = smh + CF_SQ;
    __half* sK  = smh + CF_SK;
    __half* sVt = smh + CF_SVT;
    __half* sP  = smh + CF_SP;

    const int b  = blockIdx.y >> 3;
    const int h  = blockIdx.y & 7;
    const int q0 = blockIdx.x * 128;
    const int tid = threadIdx.x;
    const int warp = tid >> 5;
    const int lane = tid & 31;
    const int g  = lane >> 2;
    const int tg = lane & 3;
    const int wm = warp * 16;

    const uint32_t smb = (uint32_t)__cvta_generic_to_shared(smh);
    const uint32_t lr = lane & 15;
    const uint32_t lh = (lane >> 4) * 8;

    for (int i = tid; i < 1024; i += 256) {
        int row = i >> 3;
        int c8  = (i & 7) * 8;
        *(uint4*)(sQ + row * FH + c8) = *(const uint4*)(qsrc +
            (size_t)(b * 1024 + q0 + row) * 512 + h * 64 + c8);
    }
    for (int i = tid; i < 640; i += 256) {      // 80 rows x 8 chunks
        int row = i >> 3;
        int c8  = (i & 7) * 8;
        uint4 kk = make_uint4(0, 0, 0, 0), vv = make_uint4(0, 0, 0, 0);
        if (row < KVLEN) {
            const __half* base = kv2 + (size_t)(b * KVLEN + row) * 1024 + h * 64;
            kk = *(const uint4*)(base + c8);
            vv = *(const uint4*)(base + 512 + c8);
        }
        *(uint4*)(sK + row * FH + c8) = kk;
        const __half* hv = (const __half*)&vv;
        #pragma unroll
        for (int q = 0; q < 8; q++) sVt[(c8 + q) * CH + row] = hv[q];
    }
    __syncthreads();

    uint32_t qf[4][4];
    {
        const uint32_t qbase = smb + (uint32_t)(CF_SQ + (wm + lr) * FH + lh) * 2;
        #pragma unroll
        for (int kc = 0; kc < 4; kc++)
            ldsm4(qf[kc][0], qf[kc][1], qf[kc][2], qf[kc][3], qbase + kc * 32);
    }

    float accs[10][4];
    #pragma unroll
    for (int nt = 0; nt < 10; nt++)
        #pragma unroll
        for (int r = 0; r < 4; r++) accs[nt][r] = 0.f;
    {
        const uint32_t kbase = smb + (uint32_t)(CF_SK + lr * FH + lh) * 2;
        #pragma unroll
        for (int kc = 0; kc < 4; kc++) {
            const uint32_t ka = kbase + kc * 32;
            #pragma unroll
            for (int p = 0; p < 5; p++) {
                uint32_t b0, b1, b2, b3;
                ldsm4(b0, b1, b2, b3, ka + (uint32_t)(p * 16 * FH) * 2);
                uint32_t bf0[2] = {b0, b2};
                uint32_t bf1[2] = {b1, b3};
                mma_f16(accs[2 * p],     qf[kc], bf0);
                mma_f16(accs[2 * p + 1], qf[kc], bf1);
            }
        }
    }

    #pragma unroll
    for (int nt = 0; nt < 10; nt++) {
        const int col0 = nt * 8 + 2 * tg;
        if (col0 >= KVLEN)     { accs[nt][0] = -1e30f; accs[nt][2] = -1e30f; }
        if (col0 + 1 >= KVLEN) { accs[nt][1] = -1e30f; accs[nt][3] = -1e30f; }
    }
    float mx0 = -1e30f, mx1 = -1e30f;
    #pragma unroll
    for (int nt = 0; nt < 10; nt++) {
        mx0 = fmaxf(mx0, fmaxf(accs[nt][0], accs[nt][1]));
        mx1 = fmaxf(mx1, fmaxf(accs[nt][2], accs[nt][3]));
    }
    mx0 = fmaxf(mx0, __shfl_xor_sync(0xffffffffu, mx0, 1));
    mx0 = fmaxf(mx0, __shfl_xor_sync(0xffffffffu, mx0, 2));
    mx1 = fmaxf(mx1, __shfl_xor_sync(0xffffffffu, mx1, 1));
    mx1 = fmaxf(mx1, __shfl_xor_sync(0xffffffffu, mx1, 2));

    float rs0 = 0.f, rs1 = 0.f;
    __half* p0 = sP + (wm + g) * CH + 2 * tg;
    __half* p1 = sP + (wm + g + 8) * CH + 2 * tg;
    #pragma unroll
    for (int nt = 0; nt < 10; nt++) {
        const float e0 = __expf((accs[nt][0] - mx0) * SCL);
        const float e1 = __expf((accs[nt][1] - mx0) * SCL);
        const float e2 = __expf((accs[nt][2] - mx1) * SCL);
        const float e3 = __expf((accs[nt][3] - mx1) * SCL);
        rs0 += e0 + e1; rs1 += e2 + e3;
        *(__half2*)(p0 + nt * 8) = __floats2half2_rn(e0, e1);
        *(__half2*)(p1 + nt * 8) = __floats2half2_rn(e2, e3);
    }
    rs0 += __shfl_xor_sync(0xffffffffu, rs0, 1);
    rs0 += __shfl_xor_sync(0xffffffffu, rs0, 2);
    rs1 += __shfl_xor_sync(0xffffffffu, rs1, 1);
    rs1 += __shfl_xor_sync(0xffffffffu, rs1, 2);
    __syncwarp();

    float acco[8][4];
    #pragma unroll
    for (int nt = 0; nt < 8; nt++)
        #pragma unroll
        for (int r = 0; r < 4; r++) acco[nt][r] = 0.f;
    {
        const uint32_t pb = smb + (uint32_t)(CF_SP + (wm + lr) * CH + lh) * 2;
        const uint32_t vb = smb + (uint32_t)(CF_SVT + lr * CH + lh) * 2;
        #pragma unroll
        for (int kc = 0; kc < 5; kc++) {
            uint32_t af[4];
            ldsm4(af[0], af[1], af[2], af[3], pb + kc * 32);
            const uint32_t va = vb + kc * 32;
            #pragma unroll
            for (int p = 0; p < 4; p++) {
                uint32_t b0, b1, b2, b3;
                ldsm4(b0, b1, b2, b3, va + (uint32_t)(p * 16 * CH) * 2);
                uint32_t bf0[2] = {b0, b2};
                uint32_t bf1[2] = {b1, b3};
                mma_f16(acco[2 * p],     af, bf0);
                mma_f16(acco[2 * p + 1], af, bf1);
            }
        }
    }

    const float i0 = 1.f / rs0;
    const float i1 = 1.f / rs1;
    const int row0 = b * 1024 + q0 + wm + g;
    #pragma unroll
    for (int nt = 0; nt < 8; nt++) {
        const int col = h * 64 + nt * 8 + 2 * tg;
        *(__half2*)(outp + (size_t)row0 * 512 + col) =
            __floats2half2_rn(acco[nt][0] * i0, acco[nt][1] * i0);
        *(__half2*)(outp + (size_t)(row0 + 8) * 512 + col) =
            __floats2half2_rn(acco[nt][2] * i1, acco[nt][3] * i1);
    }
}

// ===========================================================================
// FP16 tensor-core GEMM: C = A @ Bt^T (+bias)(+Res / gelu / mulres)
//   A [M,K] half row-major, Bt [N,K] half row-major. N%128==0, K%32==0.
//   M ragged ok. BK=32 (2 x k16 mma). 3-stage cp.async, 61.4KB smem,
//   2 CTAs/SM. ldmatrix for both operands.
//   emode: 0 plain (+Res add), 1 gelu(v) [gate pass], 2 v*Res [a pass].
//   Writes Cf (f32) and/or Ch (half).
// ===========================================================================
#define BM 128
#define BN 128
#define BK 32
#define GSTR 40                                // halves per row
#define STG_BYTES (2 * 128 * GSTR * 2)         // A+B = 20480 B
#define GEMM_SMEM (3 * STG_BYTES)              // 61440 B

__global__ void __launch_bounds__(256, 2) gemm_f16_kernel(
    const __half* __restrict__ A, int lda,
    const __half* __restrict__ Bt, int ldb,
    float* __restrict__ Cf, __half* __restrict__ Ch, int ldc,
    const float* __restrict__ Res, int ldres,
    const float* __restrict__ bias,
    int M, int K, int emode) {

    extern __shared__ __half smh[];

    const int m0 = blockIdx.y * BM;
    const int n0 = blockIdx.x * BN;
    const int tid = threadIdx.x;
    const int warp = tid >> 5;
    const int lane = tid & 31;
    const int g  = lane >> 2;
    const int tg = lane & 3;
    const int wm = (warp >> 2) * 64;
    const int wn = (warp & 3) * 32;

    const uint32_t smem_u32 = (uint32_t)__cvta_generic_to_shared(smh);
    const int nk = K / BK;

    float acc[4][4][4];
    #pragma unroll
    for (int i = 0; i < 4; i++)
        #pragma unroll
        for (int j = 0; j < 4; j++)
            #pragma unroll
            for (int r = 0; r < 4; r++) acc[i][j][r] = 0.f;

    auto load_stage = [&](int stage, int k0) {
        const uint32_t abase = smem_u32 + (uint32_t)(stage * STG_BYTES);
        // A: 128 rows x 32 halves = 512 16B-chunks, 2/thread
        #pragma unroll
        for (int i = 0; i < 2; i++) {
            int idx = tid + i * 256;
            int row = idx >> 2;
            int kc  = (idx & 3) * 8;
            int bytes = (m0 + row < M) ? 16 : 0;
            cp_async16(abase + (uint32_t)(row * GSTR + kc) * 2,
                       A + (long long)(m0 + row) * lda + k0 + kc, bytes);
        }
        const uint32_t bbase = abase + (uint32_t)(128 * GSTR * 2);
        #pragma unroll
        for (int i = 0; i < 2; i++) {
            int idx = tid + i * 256;
            int row = idx >> 2;
            int kc  = (idx & 3) * 8;
            cp_async16(bbase + (uint32_t)(row * GSTR + kc) * 2,
                       Bt + (long long)(n0 + row) * ldb + k0 + kc, 16);
        }
        cp_commit();
    };

    const uint32_t lm_off = (uint32_t)((lane & 15) * GSTR + ((lane >> 4) * 8)) * 2;
    const uint32_t a_lm = smem_u32 + (uint32_t)(wm * GSTR) * 2 + lm_off;
    const uint32_t b_lm = smem_u32 + (uint32_t)(128 * GSTR + wn * GSTR) * 2 + lm_off;

    auto compute_stage = [&](int stage) {
        const uint32_t so = (uint32_t)(stage * STG_BYTES);
        #pragma unroll
        for (int ks = 0; ks < 2; ks++) {
            const uint32_t kkb = ks * 32;     // 16 halves
            uint32_t afr[4][4];
            #pragma unroll
            for (int mt = 0; mt < 4; mt++)
                ldsm4(afr[mt][0], afr[mt][1], afr[mt][2], afr[mt][3],
                      a_lm + so + (uint32_t)(mt * 16 * GSTR) * 2 + kkb);
            uint32_t bfr[4][2];
            #pragma unroll
            for (int p = 0; p < 2; p++) {
                uint32_t r0, r1, r2, r3;
                ldsm4(r0, r1, r2, r3, b_lm + so + (uint32_t)(p * 16 * GSTR) * 2 + kkb);
                bfr[2 * p][0]     = r0; bfr[2 * p][1]     = r2;
                bfr[2 * p + 1][0] = r1; bfr[2 * p + 1][1] = r3;
            }
            #pragma unroll
            for (int mt = 0; mt < 4; mt++)
                #pragma unroll
                for (int nt = 0; nt < 4; nt++)
                    mma_f16(acc[mt][nt], afr[mt], bfr[nt]);
        }
    };

    load_stage(0, 0);
    if (nk > 1) load_stage(1, BK);
    for (int kt = 0; kt < nk; kt++) {
        if (kt + 1 < nk) cp_wait1(); else cp_wait0();
        __syncthreads();
        if (kt + 2 < nk) load_stage((kt + 2) % 3, (kt + 2) * BK);
        compute_stage(kt % 3);
    }

    // ---- epilogue ----
    #pragma unroll
    for (int mt = 0; mt < 4; mt++) {
        #pragma unroll
        for (int nt = 0; nt < 4; nt++) {
            const int row0 = m0 + wm + mt * 16 + g;
            const int col0 = n0 + wn + nt * 8 + tg * 2;
            #pragma unroll
            for (int r = 0; r < 4; r++) {
                const int row = row0 + (r >> 1) * 8;
                const int col = col0 + (r & 1);
                if (row < M) {
                    float v = acc[mt][nt][r];
                    if (bias) v += bias[col];
                    if (emode == 1) {
                        v = 0.5f * v * (1.f + erff(v * 0.70710678118654752f));
                    } else if (emode == 2) {
                        v *= Res[(long long)row * ldres + col];
                    } else if (Res) {
                        v += Res[(long long)row * ldres + col];
                    }
                    if (Cf) Cf[(long long)row * ldc + col] = v;
                    if (Ch) Ch[(long long)row * ldc + col] = __float2half(v);
                }
            }
        }
    }
}

// ---------------------------------------------------------------------------
// Host side
// ---------------------------------------------------------------------------
static void gemm(const __half* A, int lda, const __half* Bt, int ldb,
                 float* Cf, __half* Ch, int ldc,
                 const float* Res, int ldres, const float* bias,
                 int M, int N, int K, int emode = 0) {
    dim3 grid(N / BN, (M + BM - 1) / BM);
    gemm_f16_kernel<<<grid, 256, GEMM_SMEM>>>(
        A, lda, Bt, ldb, Cf, Ch, ldc, Res, ldres, bias, M, K, emode);
}
static void trc(const float* src, __half* dst, int R, int C) {
    dim3 grid(C / 32, R / 32), blk(32, 8);
    trcvt_kernel<<<grid, blk>>>(src, dst, R, C);
}

extern "C" void kernel_launch(void* const* d_in, const int* in_sizes, int n_in,
                              void* d_out, int out_size) {
    const float* in_q     = (const float*)d_in[0];
    const float* in_kv    = (const float*)d_in[1];
    const float* gn_g     = (const float*)d_in[2];
    const float* gn_b     = (const float*)d_in[3];
    const float* ln2_g    = (const float*)d_in[4];
    const float* ln2_b    = (const float*)d_in[5];
    const float* ln3_g    = (const float*)d_in[6];
    const float* ln3_b    = (const float*)d_in[7];
    const float* ln4_g    = (const float*)d_in[8];
    const float* ln4_b    = (const float*)d_in[9];
    const float* fc_in_w  = (const float*)d_in[10];
    const float* fc_in_b  = (const float*)d_in[11];
    const float* fc_out_w = (const float*)d_in[12];
    const float* fc_out_b = (const float*)d_in[13];
    const float* a1_q     = (const float*)d_in[14];
    const float* a1_k     = (const float*)d_in[15];
    const float* a1_v     = (const float*)d_in[16];
    const float* a1_o     = (const float*)d_in[17];
    const float* a1_ob    = (const float*)d_in[18];
    const float* a2_q     = (const float*)d_in[19];
    const float* a2_k     = (const float*)d_in[20];
    const float* a2_v     = (const float*)d_in[21];
    const float* a2_o     = (const float*)d_in[22];
    const float* a2_ob    = (const float*)d_in[23];
    const float* ff_proj_w = (const float*)d_in[24];
    const float* ff_proj_b = (const float*)d_in[25];
    const float* ff_out_w  = (const float*)d_in[26];
    const float* ff_out_b  = (const float*)d_in[27];

    cudaFuncSetAttribute(gemm_f16_kernel,
                         cudaFuncAttributeMaxDynamicSharedMemorySize, GEMM_SMEM);
    cudaFuncSetAttribute(flash_self_kernel,
                         cudaFuncAttributeMaxDynamicSharedMemorySize, FS_TOTAL_H * 2);
    cudaFuncSetAttribute(flash_cross_kernel,
                         cudaFuncAttributeMaxDynamicSharedMemorySize, CF_TOTAL_H * 2);

    float *x, *t, *gb;
    __half *th, *qkvh, *qh, *kvh, *kv2h, *glh, *xh;
    __half *whFcIn, *whQkv, *whA1o, *whA2q, *whA2o, *whKv2, *whFfp, *whFfo, *whFco;
    cudaGetSymbolAddress((void**)&x,    g_x);
    cudaGetSymbolAddress((void**)&t,    g_t);
    cudaGetSymbolAddress((void**)&gb,   g_gb);
    cudaGetSymbolAddress((void**)&th,   g_th);
    cudaGetSymbolAddress((void**)&qkvh, g_qkvh);
    cudaGetSymbolAddress((void**)&qh,   g_qh);
    cudaGetSymbolAddress((void**)&kvh,  g_kvh);
    cudaGetSymbolAddress((void**)&kv2h, g_kv2h);
    cudaGetSymbolAddress((void**)&glh,  g_glh);
    cudaGetSymbolAddress((void**)&xh,   g_xh);
    cudaGetSymbolAddress((void**)&whFcIn, g_whFcIn);
    cudaGetSymbolAddress((void**)&whQkv,  g_whQkv);
    cudaGetSymbolAddress((void**)&whA1o,  g_whA1o);
    cudaGetSymbolAddress((void**)&whA2q,  g_whA2q);
    cudaGetSymbolAddress((void**)&whA2o,  g_whA2o);
    cudaGetSymbolAddress((void**)&whKv2,  g_whKv2);
    cudaGetSymbolAddress((void**)&whFfp,  g_whFfp);
    cudaGetSymbolAddress((void**)&whFfo,  g_whFfo);
    cudaGetSymbolAddress((void**)&whFco,  g_whFco);

    float* out = (float*)d_out;

    // ---- weight transpose+convert ([K,N] f32 -> [N,K] half) ----
    trc(fc_in_w, whFcIn, 512, 512);
    trc(a1_q, whQkv + 0,                  512, 512);
    trc(a1_k, whQkv + (size_t)512 * 512,  512, 512);
    trc(a1_v, whQkv + (size_t)1024 * 512, 512, 512);
    trc(a1_o, whA1o, 512, 512);
    trc(a2_q, whA2q, 512, 512);
    trc(a2_o, whA2o, 512, 512);
    trc(a2_k, whKv2 + 0,                   1024, 512);
    trc(a2_v, whKv2 + (size_t)512 * 1024,  1024, 512);
    trc(ff_proj_w, whFfp, 512, 4096);
    trc(ff_out_w,  whFfo, 2048, 512);
    trc(fc_out_w,  whFco, 512, 512);
    cvt_kernel<<<(BATCH * KVLEN * 1024 + 255) / 256, 256>>>(
        in_kv, kvh, BATCH * KVLEN * 1024);

    // 1. GroupNorm + transpose -> th (half)
    groupnorm_kernel<<<BATCH * 32, 256>>>(in_q, gn_g, gn_b, th);

    // 2. x = th @ fc_in + b   (fp32 C)
    gemm(th, 512, whFcIn, 512, x, nullptr, 512, nullptr, 0, fc_in_b,
         NTOK, 512, 512);

    // ---- self attention ----
    layernorm_kernel<<<NTOK / 8, 256>>>(x, ln2_g, ln2_b, th, NTOK);
    gemm(th, 512, whQkv, 512, nullptr, qkvh, 1536, nullptr, 0, nullptr,
         NTOK, 1536, 512);
    {
        dim3 grid(8, 64);
        flash_self_kernel<<<grid, 256, FS_TOTAL_H * 2>>>(qkvh, th);
    }
    gemm(th, 512, whA1o, 512, x, nullptr, 512, x, 512, a1_ob,
         NTOK, 512, 512);

    // ---- cross attention ----
    layernorm_kernel<<<NTOK / 8, 256>>>(x, ln3_g, ln3_b, th, NTOK);
    gemm(th, 512, whA2q, 512, nullptr, qh, 512, nullptr, 0, nullptr,
         NTOK, 512, 512);
    gemm(kvh, 1024, whKv2, 1024, nullptr, kv2h, 1024, nullptr, 0, nullptr,
         BATCH * KVLEN, 1024, 1024);
    {
        dim3 grid(8, 64);
        flash_cross_kernel<<<grid, 256, CF_TOTAL_H * 2>>>(qh, kv2h, th);
    }
    gemm(th, 512, whA2o, 512, x, nullptr, 512, x, 512, a2_ob,
         NTOK, 512, 512);

    // ---- feed-forward (GEGLU) ----
    layernorm_kernel<<<NTOK / 8, 256>>>(x, ln4_g, ln4_b, th, NTOK);
    // gate pass: gb = gelu(th @ Wp_gate + b_gate)  (fp32)
    gemm(th, 512, whFfp + (size_t)2048 * 512, 512, gb, nullptr, 2048,
         nullptr, 0, ff_proj_b + 2048, NTOK, 2048, 512, 1);
    // a pass: glh = (th @ Wp_a + b_a) * gb   (half)
    gemm(th, 512, whFfp, 512, nullptr, glh, 2048, gb, 2048, ff_proj_b,
         NTOK, 2048, 512, 2);
    // x = glh @ Wout + b + x  (fp32 + half mirror xh)
    gemm(glh, 2048, whFfo, 2048, x, xh, 512, x, 512, ff_out_b,
         NTOK, 512, 2048);

    // ---- output projection ----
    gemm(xh, 512, whFco, 512, t, nullptr, 512, nullptr, 0, fc_out_b,
         NTOK, 512, 512);

    output_kernel<<<(BATCH * DIMC * SPATIAL) / 256, 256>>>(t, in_q, out);
}

// round 11
// speedup vs baseline: 1.6673x; 1.0266x over previous
#include <cuda_runtime.h>
#include <cuda_fp16.h>
#include <cstdint>
#include <math.h>

// ---------------------------------------------------------------------------
// Problem constants
// ---------------------------------------------------------------------------
#define BATCH   8
#define DIMC    512
#define SPATIAL 1024
#define NTOK    (BATCH*SPATIAL)  // 8192
#define HEADS   8
#define HDIM    64
#define KVLEN   77
#define KVDIM   1024

// ---------------------------------------------------------------------------
// Scratch buffers
// ---------------------------------------------------------------------------
__device__ float  g_x  [(size_t)NTOK * DIMC];           // fp32 residual stream
__device__ float  g_t  [(size_t)NTOK * DIMC];           // fp32 temp (fco out)
__device__ __half g_gbh[(size_t)NTOK * 2048];           // gelu(gate) half
__device__ __half g_th  [(size_t)NTOK * DIMC];
__device__ __half g_qkvh[(size_t)NTOK * 1536];
__device__ __half g_qh  [(size_t)NTOK * DIMC];
__device__ __half g_kvh [(size_t)(BATCH*KVLEN) * 1024];
__device__ __half g_kv2h[(size_t)(BATCH*KVLEN) * 1024];
__device__ __half g_glh [(size_t)NTOK * 2048];
__device__ __half g_xh  [(size_t)NTOK * DIMC];
// half transposed weights [N, K]
__device__ __half g_whFcIn[(size_t)512 * 512];
__device__ __half g_whQkv [(size_t)1536 * 512];
__device__ __half g_whA1o [(size_t)512 * 512];
__device__ __half g_whA2q [(size_t)512 * 512];
__device__ __half g_whA2o [(size_t)512 * 512];
__device__ __half g_whKv2 [(size_t)1024 * 1024];
__device__ __half g_whFfp [(size_t)4096 * 512];
__device__ __half g_whFfo [(size_t)512 * 2048];
__device__ __half g_whFco [(size_t)512 * 512];

// ---------------------------------------------------------------------------
// Helpers
// ---------------------------------------------------------------------------
__device__ __forceinline__ float warpSum(float v) {
    #pragma unroll
    for (int o = 16; o > 0; o >>= 1) v += __shfl_xor_sync(0xffffffffu, v, o);
    return v;
}
__device__ __forceinline__ void mma_f16(float* d, const uint32_t* a, const uint32_t* b) {
    asm volatile(
        "mma.sync.aligned.m16n8k16.row.col.f32.f16.f16.f32 "
        "{%0,%1,%2,%3}, {%4,%5,%6,%7}, {%8,%9}, {%0,%1,%2,%3};"
        : "+f"(d[0]), "+f"(d[1]), "+f"(d[2]), "+f"(d[3])
        : "r"(a[0]), "r"(a[1]), "r"(a[2]), "r"(a[3]), "r"(b[0]), "r"(b[1]));
}
__device__ __forceinline__ void ldsm4(uint32_t& r0, uint32_t& r1,
                                      uint32_t& r2, uint32_t& r3, uint32_t addr) {
    asm volatile("ldmatrix.sync.aligned.m8n8.x4.shared.b16 {%0,%1,%2,%3}, [%4];"
                 : "=r"(r0), "=r"(r1), "=r"(r2), "=r"(r3) : "r"(addr));
}
__device__ __forceinline__ void cp_async16(uint32_t dst, const void* src, int bytes) {
    asm volatile("cp.async.cg.shared.global [%0], [%1], 16, %2;\n"
                 :: "r"(dst), "l"(src), "r"(bytes));
}
__device__ __forceinline__ void cp_commit() { asm volatile("cp.async.commit_group;\n"); }
__device__ __forceinline__ void cp_wait1()  { asm volatile("cp.async.wait_group 1;\n"); }
__device__ __forceinline__ void cp_wait0()  { asm volatile("cp.async.wait_group 0;\n"); }

// ---------------------------------------------------------------------------
// GroupNorm + transpose to token-major, half output
// ---------------------------------------------------------------------------
__global__ void groupnorm_kernel(const float* __restrict__ qin,
                                 const float* __restrict__ gamma,
                                 const float* __restrict__ beta,
                                 __half* __restrict__ out) {
    const int blk = blockIdx.x;
    const int b = blk >> 5;
    const int grp = blk & 31;
    const float* base = qin + ((size_t)b * DIMC + grp * 16) * SPATIAL;

    float s = 0.f, s2 = 0.f;
    for (int i = threadIdx.x; i < 16 * SPATIAL; i += 256) {
        float v = base[i];
        s += v; s2 += v * v;
    }
    __shared__ float red[2][8];
    s = warpSum(s); s2 = warpSum(s2);
    int wid = threadIdx.x >> 5, lid = threadIdx.x & 31;
    if (lid == 0) { red[0][wid] = s; red[1][wid] = s2; }
    __syncthreads();
    if (wid == 0) {
        float a = (lid < 8) ? red[0][lid] : 0.f;
        float c = (lid < 8) ? red[1][lid] : 0.f;
        a = warpSum(a); c = warpSum(c);
        if (lid == 0) { red[0][0] = a; red[1][0] = c; }
    }
    __syncthreads();
    const float mu  = red[0][0] * (1.f / 16384.f);
    const float var = red[1][0] * (1.f / 16384.f) - mu * mu;
    const float inv = rsqrtf(var + 1e-6f);

    for (int i = threadIdx.x; i < 16 * SPATIAL; i += 256) {
        int c = grp * 16 + (i >> 10);
        int sp = i & 1023;
        float v = (base[i] - mu) * inv * gamma[c] + beta[c];
        out[((size_t)(b * SPATIAL + sp)) * DIMC + c] = __float2half(v);
    }
}

// ---------------------------------------------------------------------------
// LayerNorm (fp32 in, half out). One warp per 512-dim row.
// ---------------------------------------------------------------------------
__global__ void layernorm_kernel(const float* __restrict__ x,
                                 const float* __restrict__ gamma,
                                 const float* __restrict__ beta,
                                 __half* __restrict__ out, int rows) {
    int row = blockIdx.x * 8 + (threadIdx.x >> 5);
    if (row >= rows) return;
    int lid = threadIdx.x & 31;
    const float4* xr = (const float4*)(x + (size_t)row * DIMC);

    float4 vals[4];
    float s = 0.f, s2 = 0.f;
    #pragma unroll
    for (int i = 0; i < 4; i++) {
        float4 v = xr[lid + 32 * i];
        vals[i] = v;
        s  += v.x + v.y + v.z + v.w;
        s2 += v.x*v.x + v.y*v.y + v.z*v.z + v.w*v.w;
    }
    s = warpSum(s); s2 = warpSum(s2);
    const float mu  = s * (1.f / 512.f);
    const float inv = rsqrtf(s2 * (1.f / 512.f) - mu * mu + 1e-5f);

    __half2* orow = (__half2*)(out + (size_t)row * DIMC);
    const float4* g4 = (const float4*)gamma;
    const float4* b4 = (const float4*)beta;
    #pragma unroll
    for (int i = 0; i < 4; i++) {
        int idx = lid + 32 * i;
        float4 v = vals[i], g = g4[idx], b = b4[idx];
        float ox = (v.x - mu) * inv * g.x + b.x;
        float oy = (v.y - mu) * inv * g.y + b.y;
        float oz = (v.z - mu) * inv * g.z + b.z;
        float ow = (v.w - mu) * inv * g.w + b.w;
        orow[idx * 2]     = __floats2half2_rn(ox, oy);
        orow[idx * 2 + 1] = __floats2half2_rn(oz, ow);
    }
}

// ---------------------------------------------------------------------------
// Batched transpose + f32->f16: all weights in ONE launch.
// Each job: src [R, C] f32 -> dst [C, R] half. 32x32 tiles.
// ---------------------------------------------------------------------------
#define NJOBS 12
struct TrJobs {
    const float* src[NJOBS];
    __half*      dst[NJOBS];
    int R[NJOBS], C[NJOBS];
    int tstart[NJOBS + 1];     // prefix sum of tile counts
};

__global__ void trcvt_all_kernel(TrJobs jobs) {
    __shared__ float tile[32][33];
    const int flat = blockIdx.x;
    int j = 0;
    #pragma unroll
    for (int i = 0; i < NJOBS; i++)
        if (flat >= jobs.tstart[i + 1]) j = i + 1;
    const int lt = flat - jobs.tstart[j];
    const int C = jobs.C[j], R = jobs.R[j];
    const int ctiles = C >> 5;
    const int c0 = (lt % ctiles) * 32;
    const int r0 = (lt / ctiles) * 32;
    const float* src = jobs.src[j];
    __half* dst = jobs.dst[j];

    int x = threadIdx.x, y = threadIdx.y;
    #pragma unroll
    for (int i = 0; i < 32; i += 8)
        tile[y + i][x] = src[(size_t)(r0 + y + i) * C + c0 + x];
    __syncthreads();
    #pragma unroll
    for (int i = 0; i < 32; i += 8)
        dst[(size_t)(c0 + y + i) * R + r0 + x] = __float2half(tile[x][y + i]);
}

// f32 -> f16 linear convert
__global__ void cvt_kernel(const float* __restrict__ src,
                           __half* __restrict__ dst, int n) {
    int i = blockIdx.x * 256 + threadIdx.x;
    if (i < n) dst[i] = __float2half(src[i]);
}

// ---------------------------------------------------------------------------
// Final transpose + residual
// ---------------------------------------------------------------------------
__global__ void output_kernel(const float* __restrict__ t,
                              const float* __restrict__ qin,
                              float* __restrict__ out) {
    int i = blockIdx.x * 256 + threadIdx.x;
    if (i >= BATCH * DIMC * SPATIAL) return;
    int sp = i & 1023;
    int bc = i >> 10;
    int c = bc & 511;
    int b = bc >> 9;
    out[i] = t[((size_t)(b * SPATIAL + sp)) * DIMC + c] + qin[i];
}

// ===========================================================================
// Fused flash self-attention, fp16 operands, fp32 accum.
// ===========================================================================
#define SCL 0.125f
#define FH 72
#define PH 136
#define FS_SQ   0
#define FS_SK   (128*FH)
#define FS_SVT  (FS_SK + 128*FH)
#define FS_SP   (FS_SVT + 64*PH)
#define FS_TOTAL_H (FS_SP + 128*PH)

__global__ void __launch_bounds__(256) flash_self_kernel(
    const __half* __restrict__ qkv, __half* __restrict__ outp) {
    extern __shared__ __half smh[];
    __half* sQ  = smh + FS_SQ;
    __half* sK  = smh + FS_SK;
    __half* sVt = smh + FS_SVT;
    __half* sP  = smh + FS_SP;

    const int b  = blockIdx.y >> 3;
    const int h  = blockIdx.y & 7;
    const int q0 = blockIdx.x * 128;
    const int tid = threadIdx.x;
    const int warp = tid >> 5;
    const int lane = tid & 31;
    const int g  = lane >> 2;
    const int tg = lane & 3;
    const int wm = warp * 16;

    const uint32_t smb = (uint32_t)__cvta_generic_to_shared(smh);
    const uint32_t lr = lane & 15;
    const uint32_t lh = (lane >> 4) * 8;

    for (int i = tid; i < 1024; i += 256) {
        int row = i >> 3;
        int c8  = (i & 7) * 8;
        *(uint4*)(sQ + row * FH + c8) = *(const uint4*)(qkv +
            (size_t)(b * 1024 + q0 + row) * 1536 + h * 64 + c8);
    }
    __syncthreads();

    uint32_t qf[4][4];
    {
        const uint32_t qbase = smb + (uint32_t)(FS_SQ + (wm + lr) * FH + lh) * 2;
        #pragma unroll
        for (int kc = 0; kc < 4; kc++)
            ldsm4(qf[kc][0], qf[kc][1], qf[kc][2], qf[kc][3], qbase + kc * 32);
    }

    float m_[2] = {-1e30f, -1e30f};
    float l_[2] = {0.f, 0.f};
    float acco[8][4];
    #pragma unroll
    for (int i = 0; i < 8; i++)
        #pragma unroll
        for (int r = 0; r < 4; r++) acco[i][r] = 0.f;

    const uint32_t kbase = smb + (uint32_t)(FS_SK + lr * FH + lh) * 2;
    const uint32_t pbase = smb + (uint32_t)(FS_SP + (wm + lr) * PH + lh) * 2;
    const uint32_t vbase = smb + (uint32_t)(FS_SVT + lr * PH + lh) * 2;

    for (int j = 0; j < 8; j++) {
        for (int i = tid; i < 1024; i += 256) {
            int row = i >> 3;
            int c8  = (i & 7) * 8;
            const __half* base = qkv + (size_t)(b * 1024 + j * 128 + row) * 1536 + h * 64;
            *(uint4*)(sK + row * FH + c8) = *(const uint4*)(base + 512 + c8);
            uint4 vv = *(const uint4*)(base + 1024 + c8);
            const __half* hv = (const __half*)&vv;
            #pragma unroll
            for (int q = 0; q < 8; q++) sVt[(c8 + q) * PH + row] = hv[q];
        }
        __syncthreads();

        float accs[16][4];
        #pragma unroll
        for (int nt = 0; nt < 16; nt++)
            #pragma unroll
            for (int r = 0; r < 4; r++) accs[nt][r] = 0.f;

        #pragma unroll
        for (int kc = 0; kc < 4; kc++) {
            const uint32_t ka = kbase + kc * 32;
            #pragma unroll
            for (int p = 0; p < 8; p++) {
                uint32_t b0, b1, b2, b3;
                ldsm4(b0, b1, b2, b3, ka + (uint32_t)(p * 16 * FH) * 2);
                uint32_t bf0[2] = {b0, b2};
                uint32_t bf1[2] = {b1, b3};
                mma_f16(accs[2 * p],     qf[kc], bf0);
                mma_f16(accs[2 * p + 1], qf[kc], bf1);
            }
        }

        float mx0 = -1e30f, mx1 = -1e30f;
        #pragma unroll
        for (int nt = 0; nt < 16; nt++) {
            mx0 = fmaxf(mx0, fmaxf(accs[nt][0], accs[nt][1]));
            mx1 = fmaxf(mx1, fmaxf(accs[nt][2], accs[nt][3]));
        }
        mx0 = fmaxf(mx0, __shfl_xor_sync(0xffffffffu, mx0, 1));
        mx0 = fmaxf(mx0, __shfl_xor_sync(0xffffffffu, mx0, 2));
        mx1 = fmaxf(mx1, __shfl_xor_sync(0xffffffffu, mx1, 1));
        mx1 = fmaxf(mx1, __shfl_xor_sync(0xffffffffu, mx1, 2));
        const float mn0 = fmaxf(m_[0], mx0);
        const float mn1 = fmaxf(m_[1], mx1);
        const float c0 = __expf((m_[0] - mn0) * SCL);
        const float c1 = __expf((m_[1] - mn1) * SCL);
        l_[0] *= c0; l_[1] *= c1;
        #pragma unroll
        for (int nt = 0; nt < 8; nt++) {
            acco[nt][0] *= c0; acco[nt][1] *= c0;
            acco[nt][2] *= c1; acco[nt][3] *= c1;
        }
        float rs0 = 0.f, rs1 = 0.f;
        __half* p0 = sP + (wm + g) * PH + 2 * tg;
        __half* p1 = sP + (wm + g + 8) * PH + 2 * tg;
        #pragma unroll
        for (int nt = 0; nt < 16; nt++) {
            const float e0 = __expf((accs[nt][0] - mn0) * SCL);
            const float e1 = __expf((accs[nt][1] - mn0) * SCL);
            const float e2 = __expf((accs[nt][2] - mn1) * SCL);
            const float e3 = __expf((accs[nt][3] - mn1) * SCL);
            rs0 += e0 + e1; rs1 += e2 + e3;
            *(__half2*)(p0 + nt * 8) = __floats2half2_rn(e0, e1);
            *(__half2*)(p1 + nt * 8) = __floats2half2_rn(e2, e3);
        }
        rs0 += __shfl_xor_sync(0xffffffffu, rs0, 1);
        rs0 += __shfl_xor_sync(0xffffffffu, rs0, 2);
        rs1 += __shfl_xor_sync(0xffffffffu, rs1, 1);
        rs1 += __shfl_xor_sync(0xffffffffu, rs1, 2);
        l_[0] += rs0; l_[1] += rs1;
        m_[0] = mn0; m_[1] = mn1;
        __syncwarp();

        #pragma unroll
        for (int kc = 0; kc < 8; kc++) {
            uint32_t af[4];
            ldsm4(af[0], af[1], af[2], af[3], pbase + kc * 32);
            const uint32_t va = vbase + kc * 32;
            #pragma unroll
            for (int p = 0; p < 4; p++) {
                uint32_t b0, b1, b2, b3;
                ldsm4(b0, b1, b2, b3, va + (uint32_t)(p * 16 * PH) * 2);
                uint32_t bf0[2] = {b0, b2};
                uint32_t bf1[2] = {b1, b3};
                mma_f16(acco[2 * p],     af, bf0);
                mma_f16(acco[2 * p + 1], af, bf1);
            }
        }
        __syncthreads();
    }

    const float i0 = 1.f / l_[0];
    const float i1 = 1.f / l_[1];
    const int row0 = b * 1024 + q0 + wm + g;
    #pragma unroll
    for (int nt = 0; nt < 8; nt++) {
        const int col = h * 64 + nt * 8 + 2 * tg;
        *(__half2*)(outp + (size_t)row0 * 512 + col) =
            __floats2half2_rn(acco[nt][0] * i0, acco[nt][1] * i0);
        *(__half2*)(outp + (size_t)(row0 + 8) * 512 + col) =
            __floats2half2_rn(acco[nt][2] * i1, acco[nt][3] * i1);
    }
}

// ===========================================================================
// Fused flash cross-attention (kv 77 -> padded 80), fp16.
// ===========================================================================
#define CH 88
#define CF_SQ   0
#define CF_SK   (128*FH)
#define CF_SVT  (CF_SK + 80*FH)
#define CF_SP   (CF_SVT + 64*CH)
#define CF_TOTAL_H (CF_SP + 128*CH)

__global__ void __launch_bounds__(256) flash_cross_kernel(
    const __half* __restrict__ qsrc, const __half* __restrict__ kv2,
    __half* __restrict__ outp) {
    extern __shared__ __half smh[];
    __half* sQ  = smh + CF_SQ;
    __half* sK  = smh + CF_SK;
    __half* sVt = smh + CF_SVT;
    __half* sP  = smh + CF_SP;

    const int b  = blockIdx.y >> 3;
    const int h  = blockIdx.y & 7;
    const int q0 = blockIdx.x * 128;
    const int tid = threadIdx.x;
    const int warp = tid >> 5;
    const int lane = tid & 31;
    const int g  = lane >> 2;
    const int tg = lane & 3;
    const int wm = warp * 16;

    const uint32_t smb = (uint32_t)__cvta_generic_to_shared(smh);
    const uint32_t lr = lane & 15;
    const uint32_t lh = (lane >> 4) * 8;

    for (int i = tid; i < 1024; i += 256) {
        int row = i >> 3;
        int c8  = (i & 7) * 8;
        *(uint4*)(sQ + row * FH + c8) = *(const uint4*)(qsrc +
            (size_t)(b * 1024 + q0 + row) * 512 + h * 64 + c8);
    }
    for (int i = tid; i < 640; i += 256) {
        int row = i >> 3;
        int c8  = (i & 7) * 8;
        uint4 kk = make_uint4(0, 0, 0, 0), vv = make_uint4(0, 0, 0, 0);
        if (row < KVLEN) {
            const __half* base = kv2 + (size_t)(b * KVLEN + row) * 1024 + h * 64;
            kk = *(const uint4*)(base + c8);
            vv = *(const uint4*)(base + 512 + c8);
        }
        *(uint4*)(sK + row * FH + c8) = kk;
        const __half* hv = (const __half*)&vv;
        #pragma unroll
        for (int q = 0; q < 8; q++) sVt[(c8 + q) * CH + row] = hv[q];
    }
    __syncthreads();

    uint32_t qf[4][4];
    {
        const uint32_t qbase = smb + (uint32_t)(CF_SQ + (wm + lr) * FH + lh) * 2;
        #pragma unroll
        for (int kc = 0; kc < 4; kc++)
            ldsm4(qf[kc][0], qf[kc][1], qf[kc][2], qf[kc][3], qbase + kc * 32);
    }

    float accs[10][4];
    #pragma unroll
    for (int nt = 0; nt < 10; nt++)
        #pragma unroll
        for (int r = 0; r < 4; r++) accs[nt][r] = 0.f;
    {
        const uint32_t kbase = smb + (uint32_t)(CF_SK + lr * FH + lh) * 2;
        #pragma unroll
        for (int kc = 0; kc < 4; kc++) {
            const uint32_t ka = kbase + kc * 32;
            #pragma unroll
            for (int p = 0; p < 5; p++) {
                uint32_t b0, b1, b2, b3;
                ldsm4(b0, b1, b2, b3, ka + (uint32_t)(p * 16 * FH) * 2);
                uint32_t bf0[2] = {b0, b2};
                uint32_t bf1[2] = {b1, b3};
                mma_f16(accs[2 * p],     qf[kc], bf0);
                mma_f16(accs[2 * p + 1], qf[kc], bf1);
            }
        }
    }

    #pragma unroll
    for (int nt = 0; nt < 10; nt++) {
        const int col0 = nt * 8 + 2 * tg;
        if (col0 >= KVLEN)     { accs[nt][0] = -1e30f; accs[nt][2] = -1e30f; }
        if (col0 + 1 >= KVLEN) { accs[nt][1] = -1e30f; accs[nt][3] = -1e30f; }
    }
    float mx0 = -1e30f, mx1 = -1e30f;
    #pragma unroll
    for (int nt = 0; nt < 10; nt++) {
        mx0 = fmaxf(mx0, fmaxf(accs[nt][0], accs[nt][1]));
        mx1 = fmaxf(mx1, fmaxf(accs[nt][2], accs[nt][3]));
    }
    mx0 = fmaxf(mx0, __shfl_xor_sync(0xffffffffu, mx0, 1));
    mx0 = fmaxf(mx0, __shfl_xor_sync(0xffffffffu, mx0, 2));
    mx1 = fmaxf(mx1, __shfl_xor_sync(0xffffffffu, mx1, 1));
    mx1 = fmaxf(mx1, __shfl_xor_sync(0xffffffffu, mx1, 2));

    float rs0 = 0.f, rs1 = 0.f;
    __half* p0 = sP + (wm + g) * CH + 2 * tg;
    __half* p1 = sP + (wm + g + 8) * CH + 2 * tg;
    #pragma unroll
    for (int nt = 0; nt < 10; nt++) {
        const float e0 = __expf((accs[nt][0] - mx0) * SCL);
        const float e1 = __expf((accs[nt][1] - mx0) * SCL);
        const float e2 = __expf((accs[nt][2] - mx1) * SCL);
        const float e3 = __expf((accs[nt][3] - mx1) * SCL);
        rs0 += e0 + e1; rs1 += e2 + e3;
        *(__half2*)(p0 + nt * 8) = __floats2half2_rn(e0, e1);
        *(__half2*)(p1 + nt * 8) = __floats2half2_rn(e2, e3);
    }
    rs0 += __shfl_xor_sync(0xffffffffu, rs0, 1);
    rs0 += __shfl_xor_sync(0xffffffffu, rs0, 2);
    rs1 += __shfl_xor_sync(0xffffffffu, rs1, 1);
    rs1 += __shfl_xor_sync(0xffffffffu, rs1, 2);
    __syncwarp();

    float acco[8][4];
    #pragma unroll
    for (int nt = 0; nt < 8; nt++)
        #pragma unroll
        for (int r = 0; r < 4; r++) acco[nt][r] = 0.f;
    {
        const uint32_t pb = smb + (uint32_t)(CF_SP + (wm + lr) * CH + lh) * 2;
        const uint32_t vb = smb + (uint32_t)(CF_SVT + lr * CH + lh) * 2;
        #pragma unroll
        for (int kc = 0; kc < 5; kc++) {
            uint32_t af[4];
            ldsm4(af[0], af[1], af[2], af[3], pb + kc * 32);
            const uint32_t va = vb + kc * 32;
            #pragma unroll
            for (int p = 0; p < 4; p++) {
                uint32_t b0, b1, b2, b3;
                ldsm4(b0, b1, b2, b3, va + (uint32_t)(p * 16 * CH) * 2);
                uint32_t bf0[2] = {b0, b2};
                uint32_t bf1[2] = {b1, b3};
                mma_f16(acco[2 * p],     af, bf0);
                mma_f16(acco[2 * p + 1], af, bf1);
            }
        }
    }

    const float i0 = 1.f / rs0;
    const float i1 = 1.f / rs1;
    const int row0 = b * 1024 + q0 + wm + g;
    #pragma unroll
    for (int nt = 0; nt < 8; nt++) {
        const int col = h * 64 + nt * 8 + 2 * tg;
        *(__half2*)(outp + (size_t)row0 * 512 + col) =
            __floats2half2_rn(acco[nt][0] * i0, acco[nt][1] * i0);
        *(__half2*)(outp + (size_t)(row0 + 8) * 512 + col) =
            __floats2half2_rn(acco[nt][2] * i1, acco[nt][3] * i1);
    }
}

// ===========================================================================
// FP16 tensor-core GEMM: C = A @ Bt^T (+bias)(+Res / gelu / mul-Resh)
//   emode 0: plain (+Res fp32 add); 1: gelu(v); 2: v * Resh (half gate)
// ===========================================================================
#define BM 128
#define BN 128
#define BK 32
#define GSTR 40
#define STG_BYTES (2 * 128 * GSTR * 2)
#define GEMM_SMEM (3 * STG_BYTES)

__global__ void __launch_bounds__(256, 2) gemm_f16_kernel(
    const __half* __restrict__ A, int lda,
    const __half* __restrict__ Bt, int ldb,
    float* __restrict__ Cf, __half* __restrict__ Ch, int ldc,
    const float* __restrict__ Res, const __half* __restrict__ Resh, int ldres,
    const float* __restrict__ bias,
    int M, int K, int emode) {

    extern __shared__ __half smh[];

    const int m0 = blockIdx.y * BM;
    const int n0 = blockIdx.x * BN;
    const int tid = threadIdx.x;
    const int warp = tid >> 5;
    const int lane = tid & 31;
    const int g  = lane >> 2;
    const int tg = lane & 3;
    const int wm = (warp >> 2) * 64;
    const int wn = (warp & 3) * 32;

    const uint32_t smem_u32 = (uint32_t)__cvta_generic_to_shared(smh);
    const int nk = K / BK;

    float acc[4][4][4];
    #pragma unroll
    for (int i = 0; i < 4; i++)
        #pragma unroll
        for (int j = 0; j < 4; j++)
            #pragma unroll
            for (int r = 0; r < 4; r++) acc[i][j][r] = 0.f;

    auto load_stage = [&](int stage, int k0) {
        const uint32_t abase = smem_u32 + (uint32_t)(stage * STG_BYTES);
        #pragma unroll
        for (int i = 0; i < 2; i++) {
            int idx = tid + i * 256;
            int row = idx >> 2;
            int kc  = (idx & 3) * 8;
            int bytes = (m0 + row < M) ? 16 : 0;
            cp_async16(abase + (uint32_t)(row * GSTR + kc) * 2,
                       A + (long long)(m0 + row) * lda + k0 + kc, bytes);
        }
        const uint32_t bbase = abase + (uint32_t)(128 * GSTR * 2);
        #pragma unroll
        for (int i = 0; i < 2; i++) {
            int idx = tid + i * 256;
            int row = idx >> 2;
            int kc  = (idx & 3) * 8;
            cp_async16(bbase + (uint32_t)(row * GSTR + kc) * 2,
                       Bt + (long long)(n0 + row) * ldb + k0 + kc, 16);
        }
        cp_commit();
    };

    const uint32_t lm_off = (uint32_t)((lane & 15) * GSTR + ((lane >> 4) * 8)) * 2;
    const uint32_t a_lm = smem_u32 + (uint32_t)(wm * GSTR) * 2 + lm_off;
    const uint32_t b_lm = smem_u32 + (uint32_t)(128 * GSTR + wn * GSTR) * 2 + lm_off;

    auto compute_stage = [&](int stage) {
        const uint32_t so = (uint32_t)(stage * STG_BYTES);
        #pragma unroll
        for (int ks = 0; ks < 2; ks++) {
            const uint32_t kkb = ks * 32;
            uint32_t afr[4][4];
            #pragma unroll
            for (int mt = 0; mt < 4; mt++)
                ldsm4(afr[mt][0], afr[mt][1], afr[mt][2], afr[mt][3],
                      a_lm + so + (uint32_t)(mt * 16 * GSTR) * 2 + kkb);
            uint32_t bfr[4][2];
            #pragma unroll
            for (int p = 0; p < 2; p++) {
                uint32_t r0, r1, r2, r3;
                ldsm4(r0, r1, r2, r3, b_lm + so + (uint32_t)(p * 16 * GSTR) * 2 + kkb);
                bfr[2 * p][0]     = r0; bfr[2 * p][1]     = r2;
                bfr[2 * p + 1][0] = r1; bfr[2 * p + 1][1] = r3;
            }
            #pragma unroll
            for (int mt = 0; mt < 4; mt++)
                #pragma unroll
                for (int nt = 0; nt < 4; nt++)
                    mma_f16(acc[mt][nt], afr[mt], bfr[nt]);
        }
    };

    load_stage(0, 0);
    if (nk > 1) load_stage(1, BK);
    for (int kt = 0; kt < nk; kt++) {
        if (kt + 1 < nk) cp_wait1(); else cp_wait0();
        __syncthreads();
        if (kt + 2 < nk) load_stage((kt + 2) % 3, (kt + 2) * BK);
        compute_stage(kt % 3);
    }

    // ---- epilogue ----
    #pragma unroll
    for (int mt = 0; mt < 4; mt++) {
        #pragma unroll
        for (int nt = 0; nt < 4; nt++) {
            const int row0 = m0 + wm + mt * 16 + g;
            const int col0 = n0 + wn + nt * 8 + tg * 2;
            #pragma unroll
            for (int r = 0; r < 4; r++) {
                const int row = row0 + (r >> 1) * 8;
                const int col = col0 + (r & 1);
                if (row < M) {
                    float v = acc[mt][nt][r];
                    if (bias) v += bias[col];
                    if (emode == 1) {
                        v = 0.5f * v * (1.f + erff(v * 0.70710678118654752f));
                    } else if (emode == 2) {
                        v *= __half2float(Resh[(long long)row * ldres + col]);
                    } else if (Res) {
                        v += Res[(long long)row * ldres + col];
                    }
                    if (Cf) Cf[(long long)row * ldc + col] = v;
                    if (Ch) Ch[(long long)row * ldc + col] = __float2half(v);
                }
            }
        }
    }
}

// ---------------------------------------------------------------------------
// Host side
// ---------------------------------------------------------------------------
static void gemm(const __half* A, int lda, const __half* Bt, int ldb,
                 float* Cf, __half* Ch, int ldc,
                 const float* Res, const __half* Resh, int ldres,
                 const float* bias, int M, int N, int K, int emode = 0) {
    dim3 grid(N / BN, (M + BM - 1) / BM);
    gemm_f16_kernel<<<grid, 256, GEMM_SMEM>>>(
        A, lda, Bt, ldb, Cf, Ch, ldc, Res, Resh, ldres, bias, M, K, emode);
}

extern "C" void kernel_launch(void* const* d_in, const int* in_sizes, int n_in,
                              void* d_out, int out_size) {
    const float* in_q     = (const float*)d_in[0];
    const float* in_kv    = (const float*)d_in[1];
    const float* gn_g     = (const float*)d_in[2];
    const float* gn_b     = (const float*)d_in[3];
    const float* ln2_g    = (const float*)d_in[4];
    const float* ln2_b    = (const float*)d_in[5];
    const float* ln3_g    = (const float*)d_in[6];
    const float* ln3_b    = (const float*)d_in[7];
    const float* ln4_g    = (const float*)d_in[8];
    const float* ln4_b    = (const float*)d_in[9];
    const float* fc_in_w  = (const float*)d_in[10];
    const float* fc_in_b  = (const float*)d_in[11];
    const float* fc_out_w = (const float*)d_in[12];
    const float* fc_out_b = (const float*)d_in[13];
    const float* a1_q     = (const float*)d_in[14];
    const float* a1_k     = (const float*)d_in[15];
    const float* a1_v     = (const float*)d_in[16];
    const float* a1_o     = (const float*)d_in[17];
    const float* a1_ob    = (const float*)d_in[18];
    const float* a2_q     = (const float*)d_in[19];
    const float* a2_k     = (const float*)d_in[20];
    const float* a2_v     = (const float*)d_in[21];
    const float* a2_o     = (const float*)d_in[22];
    const float* a2_ob    = (const float*)d_in[23];
    const float* ff_proj_w = (const float*)d_in[24];
    const float* ff_proj_b = (const float*)d_in[25];
    const float* ff_out_w  = (const float*)d_in[26];
    const float* ff_out_b  = (const float*)d_in[27];

    cudaFuncSetAttribute(gemm_f16_kernel,
                         cudaFuncAttributeMaxDynamicSharedMemorySize, GEMM_SMEM);
    cudaFuncSetAttribute(flash_self_kernel,
                         cudaFuncAttributeMaxDynamicSharedMemorySize, FS_TOTAL_H * 2);
    cudaFuncSetAttribute(flash_cross_kernel,
                         cudaFuncAttributeMaxDynamicSharedMemorySize, CF_TOTAL_H * 2);

    float *x, *t;
    __half *gbh, *th, *qkvh, *qh, *kvh, *kv2h, *glh, *xh;
    __half *whFcIn, *whQkv, *whA1o, *whA2q, *whA2o, *whKv2, *whFfp, *whFfo, *whFco;
    cudaGetSymbolAddress((void**)&x,    g_x);
    cudaGetSymbolAddress((void**)&t,    g_t);
    cudaGetSymbolAddress((void**)&gbh,  g_gbh);
    cudaGetSymbolAddress((void**)&th,   g_th);
    cudaGetSymbolAddress((void**)&qkvh, g_qkvh);
    cudaGetSymbolAddress((void**)&qh,   g_qh);
    cudaGetSymbolAddress((void**)&kvh,  g_kvh);
    cudaGetSymbolAddress((void**)&kv2h, g_kv2h);
    cudaGetSymbolAddress((void**)&glh,  g_glh);
    cudaGetSymbolAddress((void**)&xh,   g_xh);
    cudaGetSymbolAddress((void**)&whFcIn, g_whFcIn);
    cudaGetSymbolAddress((void**)&whQkv,  g_whQkv);
    cudaGetSymbolAddress((void**)&whA1o,  g_whA1o);
    cudaGetSymbolAddress((void**)&whA2q,  g_whA2q);
    cudaGetSymbolAddress((void**)&whA2o,  g_whA2o);
    cudaGetSymbolAddress((void**)&whKv2,  g_whKv2);
    cudaGetSymbolAddress((void**)&whFfp,  g_whFfp);
    cudaGetSymbolAddress((void**)&whFfo,  g_whFfo);
    cudaGetSymbolAddress((void**)&whFco,  g_whFco);

    float* out = (float*)d_out;

    // ---- batched weight transpose+convert (ONE launch) ----
    {
        TrJobs jb;
        const float* srcs[NJOBS] = {fc_in_w, a1_q, a1_k, a1_v, a1_o, a2_q,
                                    a2_o, a2_k, a2_v, ff_proj_w, ff_out_w, fc_out_w};
        __half* dsts[NJOBS] = {whFcIn, whQkv, whQkv + (size_t)512 * 512,
                               whQkv + (size_t)1024 * 512, whA1o, whA2q, whA2o,
                               whKv2, whKv2 + (size_t)512 * 1024,
                               whFfp, whFfo, whFco};
        int Rs[NJOBS] = {512, 512, 512, 512, 512, 512, 512, 1024, 1024, 512, 2048, 512};
        int Cs[NJOBS] = {512, 512, 512, 512, 512, 512, 512, 512, 512, 4096, 512, 512};
        int acc = 0;
        for (int i = 0; i < NJOBS; i++) {
            jb.src[i] = srcs[i]; jb.dst[i] = dsts[i];
            jb.R[i] = Rs[i]; jb.C[i] = Cs[i];
            jb.tstart[i] = acc;
            acc += (Rs[i] / 32) * (Cs[i] / 32);
        }
        jb.tstart[NJOBS] = acc;
        trcvt_all_kernel<<<acc, dim3(32, 8)>>>(jb);
    }
    cvt_kernel<<<(BATCH * KVLEN * 1024 + 255) / 256, 256>>>(
        in_kv, kvh, BATCH * KVLEN * 1024);

    // 1. GroupNorm + transpose -> th (half)
    groupnorm_kernel<<<BATCH * 32, 256>>>(in_q, gn_g, gn_b, th);

    // 2. x = th @ fc_in + b (fp32)
    gemm(th, 512, whFcIn, 512, x, nullptr, 512, nullptr, nullptr, 0, fc_in_b,
         NTOK, 512, 512);

    // ---- self attention ----
    layernorm_kernel<<<NTOK / 8, 256>>>(x, ln2_g, ln2_b, th, NTOK);
    gemm(th, 512, whQkv, 512, nullptr, qkvh, 1536, nullptr, nullptr, 0, nullptr,
         NTOK, 1536, 512);
    {
        dim3 grid(8, 64);
        flash_self_kernel<<<grid, 256, FS_TOTAL_H * 2>>>(qkvh, th);
    }
    gemm(th, 512, whA1o, 512, x, nullptr, 512, x, nullptr, 512, a1_ob,
         NTOK, 512, 512);

    // ---- cross attention ----
    layernorm_kernel<<<NTOK / 8, 256>>>(x, ln3_g, ln3_b, th, NTOK);
    gemm(th, 512, whA2q, 512, nullptr, qh, 512, nullptr, nullptr, 0, nullptr,
         NTOK, 512, 512);
    gemm(kvh, 1024, whKv2, 1024, nullptr, kv2h, 1024, nullptr, nullptr, 0, nullptr,
         BATCH * KVLEN, 1024, 1024);
    {
        dim3 grid(8, 64);
        flash_cross_kernel<<<grid, 256, CF_TOTAL_H * 2>>>(qh, kv2h, th);
    }
    gemm(th, 512, whA2o, 512, x, nullptr, 512, x, nullptr, 512, a2_ob,
         NTOK, 512, 512);

    // ---- feed-forward (GEGLU) ----
    layernorm_kernel<<<NTOK / 8, 256>>>(x, ln4_g, ln4_b, th, NTOK);
    // gate pass: gbh = gelu(th @ Wp_gate + b_gate)  (half)
    gemm(th, 512, whFfp + (size_t)2048 * 512, 512, nullptr, gbh, 2048,
         nullptr, nullptr, 0, ff_proj_b + 2048, NTOK, 2048, 512, 1);
    // a pass: glh = (th @ Wp_a + b_a) * gbh  (half)
    gemm(th, 512, whFfp, 512, nullptr, glh, 2048, nullptr, gbh, 2048,
         ff_proj_b, NTOK, 2048, 512, 2);
    // x = glh @ Wout + b + x  (fp32 + half mirror xh)
    gemm(glh, 2048, whFfo, 2048, x, xh, 512, x, nullptr, 512, ff_out_b,
         NTOK, 512, 2048);

    // ---- output projection ----
    gemm(xh, 512, whFco, 512, t, nullptr, 512, nullptr, nullptr, 0, fc_out_b,
         NTOK, 512, 512);

    output_kernel<<<(BATCH * DIMC * SPATIAL) / 256, 256>>>(t, in_q, out);
}

// round 12
// speedup vs baseline: 1.8850x; 1.1306x over previous
#include <cuda_runtime.h>
#include <cuda_fp16.h>
#include <cstdint>
#include <math.h>

// ---------------------------------------------------------------------------
// Problem constants
// ---------------------------------------------------------------------------
#define BATCH   8
#define DIMC    512
#define SPATIAL 1024
#define NTOK    (BATCH*SPATIAL)  // 8192
#define HEADS   8
#define HDIM    64
#define KVLEN   77
#define KVDIM   1024

// ---------------------------------------------------------------------------
// Scratch buffers
// ---------------------------------------------------------------------------
__device__ float  g_x  [(size_t)NTOK * DIMC];           // fp32 residual stream
__device__ float  g_t  [(size_t)NTOK * DIMC];           // fp32 temp (fco out)
__device__ float  g_bFfp[4096];                         // interleaved ffp bias
__device__ __half g_th  [(size_t)NTOK * DIMC];
__device__ __half g_qkvh[(size_t)NTOK * 1536];
__device__ __half g_qh  [(size_t)NTOK * DIMC];
__device__ __half g_kvh [(size_t)(BATCH*KVLEN) * 1024];
__device__ __half g_kv2h[(size_t)(BATCH*KVLEN) * 1024];
__device__ __half g_glh [(size_t)NTOK * 2048];
__device__ __half g_xh  [(size_t)NTOK * DIMC];
// half transposed weights [N, K]
__device__ __half g_whFcIn[(size_t)512 * 512];
__device__ __half g_whQkv [(size_t)1536 * 512];
__device__ __half g_whA1o [(size_t)512 * 512];
__device__ __half g_whA2q [(size_t)512 * 512];
__device__ __half g_whA2o [(size_t)512 * 512];
__device__ __half g_whKv2 [(size_t)1024 * 1024];
__device__ __half g_whFfp [(size_t)4096 * 512];         // a/gate interleaved rows
__device__ __half g_whFfo [(size_t)512 * 2048];
__device__ __half g_whFco [(size_t)512 * 512];

// ---------------------------------------------------------------------------
// Helpers
// ---------------------------------------------------------------------------
__device__ __forceinline__ float warpSum(float v) {
    #pragma unroll
    for (int o = 16; o > 0; o >>= 1) v += __shfl_xor_sync(0xffffffffu, v, o);
    return v;
}
__device__ __forceinline__ void mma_f16(float* d, const uint32_t* a, const uint32_t* b) {
    asm volatile(
        "mma.sync.aligned.m16n8k16.row.col.f32.f16.f16.f32 "
        "{%0,%1,%2,%3}, {%4,%5,%6,%7}, {%8,%9}, {%0,%1,%2,%3};"
        : "+f"(d[0]), "+f"(d[1]), "+f"(d[2]), "+f"(d[3])
        : "r"(a[0]), "r"(a[1]), "r"(a[2]), "r"(a[3]), "r"(b[0]), "r"(b[1]));
}
__device__ __forceinline__ void ldsm4(uint32_t& r0, uint32_t& r1,
                                      uint32_t& r2, uint32_t& r3, uint32_t addr) {
    asm volatile("ldmatrix.sync.aligned.m8n8.x4.shared.b16 {%0,%1,%2,%3}, [%4];"
                 : "=r"(r0), "=r"(r1), "=r"(r2), "=r"(r3) : "r"(addr));
}
__device__ __forceinline__ void cp_async16(uint32_t dst, const void* src, int bytes) {
    asm volatile("cp.async.cg.shared.global [%0], [%1], 16, %2;\n"
                 :: "r"(dst), "l"(src), "r"(bytes));
}
__device__ __forceinline__ void cp_commit() { asm volatile("cp.async.commit_group;\n"); }
__device__ __forceinline__ void cp_wait1()  { asm volatile("cp.async.wait_group 1;\n"); }
__device__ __forceinline__ void cp_wait0()  { asm volatile("cp.async.wait_group 0;\n"); }
__device__ __forceinline__ float gelu_f(float v) {
    return 0.5f * v * (1.f + erff(v * 0.70710678118654752f));
}

// ---------------------------------------------------------------------------
// GroupNorm + transpose to token-major, half output
// ---------------------------------------------------------------------------
__global__ void groupnorm_kernel(const float* __restrict__ qin,
                                 const float* __restrict__ gamma,
                                 const float* __restrict__ beta,
                                 __half* __restrict__ out) {
    const int blk = blockIdx.x;
    const int b = blk >> 5;
    const int grp = blk & 31;
    const float* base = qin + ((size_t)b * DIMC + grp * 16) * SPATIAL;

    float s = 0.f, s2 = 0.f;
    for (int i = threadIdx.x; i < 16 * SPATIAL; i += 256) {
        float v = base[i];
        s += v; s2 += v * v;
    }
    __shared__ float red[2][8];
    s = warpSum(s); s2 = warpSum(s2);
    int wid = threadIdx.x >> 5, lid = threadIdx.x & 31;
    if (lid == 0) { red[0][wid] = s; red[1][wid] = s2; }
    __syncthreads();
    if (wid == 0) {
        float a = (lid < 8) ? red[0][lid] : 0.f;
        float c = (lid < 8) ? red[1][lid] : 0.f;
        a = warpSum(a); c = warpSum(c);
        if (lid == 0) { red[0][0] = a; red[1][0] = c; }
    }
    __syncthreads();
    const float mu  = red[0][0] * (1.f / 16384.f);
    const float var = red[1][0] * (1.f / 16384.f) - mu * mu;
    const float inv = rsqrtf(var + 1e-6f);

    for (int i = threadIdx.x; i < 16 * SPATIAL; i += 256) {
        int c = grp * 16 + (i >> 10);
        int sp = i & 1023;
        float v = (base[i] - mu) * inv * gamma[c] + beta[c];
        out[((size_t)(b * SPATIAL + sp)) * DIMC + c] = __float2half(v);
    }
}

// ---------------------------------------------------------------------------
// LayerNorm (fp32 in, half out). One warp per 512-dim row.
// ---------------------------------------------------------------------------
__global__ void layernorm_kernel(const float* __restrict__ x,
                                 const float* __restrict__ gamma,
                                 const float* __restrict__ beta,
                                 __half* __restrict__ out, int rows) {
    int row = blockIdx.x * 8 + (threadIdx.x >> 5);
    if (row >= rows) return;
    int lid = threadIdx.x & 31;
    const float4* xr = (const float4*)(x + (size_t)row * DIMC);

    float4 vals[4];
    float s = 0.f, s2 = 0.f;
    #pragma unroll
    for (int i = 0; i < 4; i++) {
        float4 v = xr[lid + 32 * i];
        vals[i] = v;
        s  += v.x + v.y + v.z + v.w;
        s2 += v.x*v.x + v.y*v.y + v.z*v.z + v.w*v.w;
    }
    s = warpSum(s); s2 = warpSum(s2);
    const float mu  = s * (1.f / 512.f);
    const float inv = rsqrtf(s2 * (1.f / 512.f) - mu * mu + 1e-5f);

    __half2* orow = (__half2*)(out + (size_t)row * DIMC);
    const float4* g4 = (const float4*)gamma;
    const float4* b4 = (const float4*)beta;
    #pragma unroll
    for (int i = 0; i < 4; i++) {
        int idx = lid + 32 * i;
        float4 v = vals[i], g = g4[idx], b = b4[idx];
        float ox = (v.x - mu) * inv * g.x + b.x;
        float oy = (v.y - mu) * inv * g.y + b.y;
        float oz = (v.z - mu) * inv * g.z + b.z;
        float ow = (v.w - mu) * inv * g.w + b.w;
        orow[idx * 2]     = __floats2half2_rn(ox, oy);
        orow[idx * 2 + 1] = __floats2half2_rn(oz, ow);
    }
}

// ---------------------------------------------------------------------------
// Batched transpose + f32->f16 (12 weights, ONE launch). Optional row
// interleave for GEGLU: dst row d -> (d<C/2) ? 2d : 2(d-C/2)+1.
// ---------------------------------------------------------------------------
#define NJOBS 12
struct TrJobs {
    const float* src[NJOBS];
    __half*      dst[NJOBS];
    int R[NJOBS], C[NJOBS], ileave[NJOBS];
    int tstart[NJOBS + 1];
};

__global__ void trcvt_all_kernel(TrJobs jobs) {
    __shared__ float tile[32][33];
    const int flat = blockIdx.x;
    int j = 0;
    #pragma unroll
    for (int i = 0; i < NJOBS; i++)
        if (flat >= jobs.tstart[i + 1]) j = i + 1;
    const int lt = flat - jobs.tstart[j];
    const int C = jobs.C[j], R = jobs.R[j];
    const int ctiles = C >> 5;
    const int c0 = (lt % ctiles) * 32;
    const int r0 = (lt / ctiles) * 32;
    const float* src = jobs.src[j];
    __half* dst = jobs.dst[j];
    const int il = jobs.ileave[j];
    const int halfC = C >> 1;

    int x = threadIdx.x, y = threadIdx.y;
    #pragma unroll
    for (int i = 0; i < 32; i += 8)
        tile[y + i][x] = src[(size_t)(r0 + y + i) * C + c0 + x];
    __syncthreads();
    #pragma unroll
    for (int i = 0; i < 32; i += 8) {
        int d = c0 + y + i;
        if (il) d = (d < halfC) ? 2 * d : 2 * (d - halfC) + 1;
        dst[(size_t)d * R + r0 + x] = __float2half(tile[x][y + i]);
    }
}

// f32 -> f16 linear convert
__global__ void cvt_kernel(const float* __restrict__ src,
                           __half* __restrict__ dst, int n) {
    int i = blockIdx.x * 256 + threadIdx.x;
    if (i < n) dst[i] = __float2half(src[i]);
}

// interleave ffp bias: dst[2j] = b[j] (a), dst[2j+1] = b[2048+j] (gate)
__global__ void bias_ileave_kernel(const float* __restrict__ b,
                                   float* __restrict__ dst) {
    int j = blockIdx.x * 256 + threadIdx.x;
    if (j < 2048) {
        dst[2 * j]     = b[j];
        dst[2 * j + 1] = b[2048 + j];
    }
}

// ---------------------------------------------------------------------------
// Final transpose + residual
// ---------------------------------------------------------------------------
__global__ void output_kernel(const float* __restrict__ t,
                              const float* __restrict__ qin,
                              float* __restrict__ out) {
    int i = blockIdx.x * 256 + threadIdx.x;
    if (i >= BATCH * DIMC * SPATIAL) return;
    int sp = i & 1023;
    int bc = i >> 10;
    int c = bc & 511;
    int b = bc >> 9;
    out[i] = t[((size_t)(b * SPATIAL + sp)) * DIMC + c] + qin[i];
}

// ===========================================================================
// Fused flash self-attention, fp16 operands, fp32 accum.
// ===========================================================================
#define SCL 0.125f
#define FH 72
#define PH 136
#define FS_SQ   0
#define FS_SK   (128*FH)
#define FS_SVT  (FS_SK + 128*FH)
#define FS_SP   (FS_SVT + 64*PH)
#define FS_TOTAL_H (FS_SP + 128*PH)

__global__ void __launch_bounds__(256) flash_self_kernel(
    const __half* __restrict__ qkv, __half* __restrict__ outp) {
    extern __shared__ __half smh[];
    __half* sQ  = smh + FS_SQ;
    __half* sK  = smh + FS_SK;
    __half* sVt = smh + FS_SVT;
    __half* sP  = smh + FS_SP;

    const int b  = blockIdx.y >> 3;
    const int h  = blockIdx.y & 7;
    const int q0 = blockIdx.x * 128;
    const int tid = threadIdx.x;
    const int warp = tid >> 5;
    const int lane = tid & 31;
    const int g  = lane >> 2;
    const int tg = lane & 3;
    const int wm = warp * 16;

    const uint32_t smb = (uint32_t)__cvta_generic_to_shared(smh);
    const uint32_t lr = lane & 15;
    const uint32_t lh = (lane >> 4) * 8;

    for (int i = tid; i < 1024; i += 256) {
        int row = i >> 3;
        int c8  = (i & 7) * 8;
        *(uint4*)(sQ + row * FH + c8) = *(const uint4*)(qkv +
            (size_t)(b * 1024 + q0 + row) * 1536 + h * 64 + c8);
    }
    __syncthreads();

    uint32_t qf[4][4];
    {
        const uint32_t qbase = smb + (uint32_t)(FS_SQ + (wm + lr) * FH + lh) * 2;
        #pragma unroll
        for (int kc = 0; kc < 4; kc++)
            ldsm4(qf[kc][0], qf[kc][1], qf[kc][2], qf[kc][3], qbase + kc * 32);
    }

    float m_[2] = {-1e30f, -1e30f};
    float l_[2] = {0.f, 0.f};
    float acco[8][4];
    #pragma unroll
    for (int i = 0; i < 8; i++)
        #pragma unroll
        for (int r = 0; r < 4; r++) acco[i][r] = 0.f;

    const uint32_t kbase = smb + (uint32_t)(FS_SK + lr * FH + lh) * 2;
    const uint32_t pbase = smb + (uint32_t)(FS_SP + (wm + lr) * PH + lh) * 2;
    const uint32_t vbase = smb + (uint32_t)(FS_SVT + lr * PH + lh) * 2;

    for (int j = 0; j < 8; j++) {
        for (int i = tid; i < 1024; i += 256) {
            int row = i >> 3;
            int c8  = (i & 7) * 8;
            const __half* base = qkv + (size_t)(b * 1024 + j * 128 + row) * 1536 + h * 64;
            *(uint4*)(sK + row * FH + c8) = *(const uint4*)(base + 512 + c8);
            uint4 vv = *(const uint4*)(base + 1024 + c8);
            const __half* hv = (const __half*)&vv;
            #pragma unroll
            for (int q = 0; q < 8; q++) sVt[(c8 + q) * PH + row] = hv[q];
        }
        __syncthreads();

        float accs[16][4];
        #pragma unroll
        for (int nt = 0; nt < 16; nt++)
            #pragma unroll
            for (int r = 0; r < 4; r++) accs[nt][r] = 0.f;

        #pragma unroll
        for (int kc = 0; kc < 4; kc++) {
            const uint32_t ka = kbase + kc * 32;
            #pragma unroll
            for (int p = 0; p < 8; p++) {
                uint32_t b0, b1, b2, b3;
                ldsm4(b0, b1, b2, b3, ka + (uint32_t)(p * 16 * FH) * 2);
                uint32_t bf0[2] = {b0, b2};
                uint32_t bf1[2] = {b1, b3};
                mma_f16(accs[2 * p],     qf[kc], bf0);
                mma_f16(accs[2 * p + 1], qf[kc], bf1);
            }
        }

        float mx0 = -1e30f, mx1 = -1e30f;
        #pragma unroll
        for (int nt = 0; nt < 16; nt++) {
            mx0 = fmaxf(mx0, fmaxf(accs[nt][0], accs[nt][1]));
            mx1 = fmaxf(mx1, fmaxf(accs[nt][2], accs[nt][3]));
        }
        mx0 = fmaxf(mx0, __shfl_xor_sync(0xffffffffu, mx0, 1));
        mx0 = fmaxf(mx0, __shfl_xor_sync(0xffffffffu, mx0, 2));
        mx1 = fmaxf(mx1, __shfl_xor_sync(0xffffffffu, mx1, 1));
        mx1 = fmaxf(mx1, __shfl_xor_sync(0xffffffffu, mx1, 2));
        const float mn0 = fmaxf(m_[0], mx0);
        const float mn1 = fmaxf(m_[1], mx1);
        const float c0 = __expf((m_[0] - mn0) * SCL);
        const float c1 = __expf((m_[1] - mn1) * SCL);
        l_[0] *= c0; l_[1] *= c1;
        #pragma unroll
        for (int nt = 0; nt < 8; nt++) {
            acco[nt][0] *= c0; acco[nt][1] *= c0;
            acco[nt][2] *= c1; acco[nt][3] *= c1;
        }
        float rs0 = 0.f, rs1 = 0.f;
        __half* p0 = sP + (wm + g) * PH + 2 * tg;
        __half* p1 = sP + (wm + g + 8) * PH + 2 * tg;
        #pragma unroll
        for (int nt = 0; nt < 16; nt++) {
            const float e0 = __expf((accs[nt][0] - mn0) * SCL);
            const float e1 = __expf((accs[nt][1] - mn0) * SCL);
            const float e2 = __expf((accs[nt][2] - mn1) * SCL);
            const float e3 = __expf((accs[nt][3] - mn1) * SCL);
            rs0 += e0 + e1; rs1 += e2 + e3;
            *(__half2*)(p0 + nt * 8) = __floats2half2_rn(e0, e1);
            *(__half2*)(p1 + nt * 8) = __floats2half2_rn(e2, e3);
        }
        rs0 += __shfl_xor_sync(0xffffffffu, rs0, 1);
        rs0 += __shfl_xor_sync(0xffffffffu, rs0, 2);
        rs1 += __shfl_xor_sync(0xffffffffu, rs1, 1);
        rs1 += __shfl_xor_sync(0xffffffffu, rs1, 2);
        l_[0] += rs0; l_[1] += rs1;
        m_[0] = mn0; m_[1] = mn1;
        __syncwarp();

        #pragma unroll
        for (int kc = 0; kc < 8; kc++) {
            uint32_t af[4];
            ldsm4(af[0], af[1], af[2], af[3], pbase + kc * 32);
            const uint32_t va = vbase + kc * 32;
            #pragma unroll
            for (int p = 0; p < 4; p++) {
                uint32_t b0, b1, b2, b3;
                ldsm4(b0, b1, b2, b3, va + (uint32_t)(p * 16 * PH) * 2);
                uint32_t bf0[2] = {b0, b2};
                uint32_t bf1[2] = {b1, b3};
                mma_f16(acco[2 * p],     af, bf0);
                mma_f16(acco[2 * p + 1], af, bf1);
            }
        }
        __syncthreads();
    }

    const float i0 = 1.f / l_[0];
    const float i1 = 1.f / l_[1];
    const int row0 = b * 1024 + q0 + wm + g;
    #pragma unroll
    for (int nt = 0; nt < 8; nt++) {
        const int col = h * 64 + nt * 8 + 2 * tg;
        *(__half2*)(outp + (size_t)row0 * 512 + col) =
            __floats2half2_rn(acco[nt][0] * i0, acco[nt][1] * i0);
        *(__half2*)(outp + (size_t)(row0 + 8) * 512 + col) =
            __floats2half2_rn(acco[nt][2] * i1, acco[nt][3] * i1);
    }
}

// ===========================================================================
// Fused flash cross-attention (kv 77 -> padded 80), fp16.
// ===========================================================================
#define CH 88
#define CF_SQ   0
#define CF_SK   (128*FH)
#define CF_SVT  (CF_SK + 80*FH)
#define CF_SP   (CF_SVT + 64*CH)
#define CF_TOTAL_H (CF_SP + 128*CH)

__global__ void __launch_bounds__(256) flash_cross_kernel(
    const __half* __restrict__ qsrc, const __half* __restrict__ kv2,
    __half* __restrict__ outp) {
    extern __shared__ __half smh[];
    __half* sQ  = smh + CF_SQ;
    __half* sK  = smh + CF_SK;
    __half* sVt = smh + CF_SVT;
    __half* sP  = smh + CF_SP;

    const int b  = blockIdx.y >> 3;
    const int h  = blockIdx.y & 7;
    const int q0 = blockIdx.x * 128;
    const int tid = threadIdx.x;
    const int warp = tid >> 5;
    const int lane = tid & 31;
    const int g  = lane >> 2;
    const int tg = lane & 3;
    const int wm = warp * 16;

    const uint32_t smb = (uint32_t)__cvta_generic_to_shared(smh);
    const uint32_t lr = lane & 15;
    const uint32_t lh = (lane >> 4) * 8;

    for (int i = tid; i < 1024; i += 256) {
        int row = i >> 3;
        int c8  = (i & 7) * 8;
        *(uint4*)(sQ + row * FH + c8) = *(const uint4*)(qsrc +
            (size_t)(b * 1024 + q0 + row) * 512 + h * 64 + c8);
    }
    for (int i = tid; i < 640; i += 256) {
        int row = i >> 3;
        int c8  = (i & 7) * 8;
        uint4 kk = make_uint4(0, 0, 0, 0), vv = make_uint4(0, 0, 0, 0);
        if (row < KVLEN) {
            const __half* base = kv2 + (size_t)(b * KVLEN + row) * 1024 + h * 64;
            kk = *(const uint4*)(base + c8);
            vv = *(const uint4*)(base + 512 + c8);
        }
        *(uint4*)(sK + row * FH + c8) = kk;
        const __half* hv = (const __half*)&vv;
        #pragma unroll
        for (int q = 0; q < 8; q++) sVt[(c8 + q) * CH + row] = hv[q];
    }
    __syncthreads();

    uint32_t qf[4][4];
    {
        const uint32_t qbase = smb + (uint32_t)(CF_SQ + (wm + lr) * FH + lh) * 2;
        #pragma unroll
        for (int kc = 0; kc < 4; kc++)
            ldsm4(qf[kc][0], qf[kc][1], qf[kc][2], qf[kc][3], qbase + kc * 32);
    }

    float accs[10][4];
    #pragma unroll
    for (int nt = 0; nt < 10; nt++)
        #pragma unroll
        for (int r = 0; r < 4; r++) accs[nt][r] = 0.f;
    {
        const uint32_t kbase = smb + (uint32_t)(CF_SK + lr * FH + lh) * 2;
        #pragma unroll
        for (int kc = 0; kc < 4; kc++) {
            const uint32_t ka = kbase + kc * 32;
            #pragma unroll
            for (int p = 0; p < 5; p++) {
                uint32_t b0, b1, b2, b3;
                ldsm4(b0, b1, b2, b3, ka + (uint32_t)(p * 16 * FH) * 2);
                uint32_t bf0[2] = {b0, b2};
                uint32_t bf1[2] = {b1, b3};
                mma_f16(accs[2 * p],     qf[kc], bf0);
                mma_f16(accs[2 * p + 1], qf[kc], bf1);
            }
        }
    }

    #pragma unroll
    for (int nt = 0; nt < 10; nt++) {
        const int col0 = nt * 8 + 2 * tg;
        if (col0 >= KVLEN)     { accs[nt][0] = -1e30f; accs[nt][2] = -1e30f; }
        if (col0 + 1 >= KVLEN) { accs[nt][1] = -1e30f; accs[nt][3] = -1e30f; }
    }
    float mx0 = -1e30f, mx1 = -1e30f;
    #pragma unroll
    for (int nt = 0; nt < 10; nt++) {
        mx0 = fmaxf(mx0, fmaxf(accs[nt][0], accs[nt][1]));
        mx1 = fmaxf(mx1, fmaxf(accs[nt][2], accs[nt][3]));
    }
    mx0 = fmaxf(mx0, __shfl_xor_sync(0xffffffffu, mx0, 1));
    mx0 = fmaxf(mx0, __shfl_xor_sync(0xffffffffu, mx0, 2));
    mx1 = fmaxf(mx1, __shfl_xor_sync(0xffffffffu, mx1, 1));
    mx1 = fmaxf(mx1, __shfl_xor_sync(0xffffffffu, mx1, 2));

    float rs0 = 0.f, rs1 = 0.f;
    __half* p0 = sP + (wm + g) * CH + 2 * tg;
    __half* p1 = sP + (wm + g + 8) * CH + 2 * tg;
    #pragma unroll
    for (int nt = 0; nt < 10; nt++) {
        const float e0 = __expf((accs[nt][0] - mx0) * SCL);
        const float e1 = __expf((accs[nt][1] - mx0) * SCL);
        const float e2 = __expf((accs[nt][2] - mx1) * SCL);
        const float e3 = __expf((accs[nt][3] - mx1) * SCL);
        rs0 += e0 + e1; rs1 += e2 + e3;
        *(__half2*)(p0 + nt * 8) = __floats2half2_rn(e0, e1);
        *(__half2*)(p1 + nt * 8) = __floats2half2_rn(e2, e3);
    }
    rs0 += __shfl_xor_sync(0xffffffffu, rs0, 1);
    rs0 += __shfl_xor_sync(0xffffffffu, rs0, 2);
    rs1 += __shfl_xor_sync(0xffffffffu, rs1, 1);
    rs1 += __shfl_xor_sync(0xffffffffu, rs1, 2);
    __syncwarp();

    float acco[8][4];
    #pragma unroll
    for (int nt = 0; nt < 8; nt++)
        #pragma unroll
        for (int r = 0; r < 4; r++) acco[nt][r] = 0.f;
    {
        const uint32_t pb = smb + (uint32_t)(CF_SP + (wm + lr) * CH + lh) * 2;
        const uint32_t vb = smb + (uint32_t)(CF_SVT + lr * CH + lh) * 2;
        #pragma unroll
        for (int kc = 0; kc < 5; kc++) {
            uint32_t af[4];
            ldsm4(af[0], af[1], af[2], af[3], pb + kc * 32);
            const uint32_t va = vb + kc * 32;
            #pragma unroll
            for (int p = 0; p < 4; p++) {
                uint32_t b0, b1, b2, b3;
                ldsm4(b0, b1, b2, b3, va + (uint32_t)(p * 16 * CH) * 2);
                uint32_t bf0[2] = {b0, b2};
                uint32_t bf1[2] = {b1, b3};
                mma_f16(acco[2 * p],     af, bf0);
                mma_f16(acco[2 * p + 1], af, bf1);
            }
        }
    }

    const float i0 = 1.f / rs0;
    const float i1 = 1.f / rs1;
    const int row0 = b * 1024 + q0 + wm + g;
    #pragma unroll
    for (int nt = 0; nt < 8; nt++) {
        const int col = h * 64 + nt * 8 + 2 * tg;
        *(__half2*)(outp + (size_t)row0 * 512 + col) =
            __floats2half2_rn(acco[nt][0] * i0, acco[nt][1] * i0);
        *(__half2*)(outp + (size_t)(row0 + 8) * 512 + col) =
            __floats2half2_rn(acco[nt][2] * i1, acco[nt][3] * i1);
    }
}

// ===========================================================================
// FP16 tensor-core GEMM: C = A @ Bt^T (+bias)(+epilogue)
//   emode 0: plain (+Res fp32 add); 3: GEGLU-paired (cols interleaved
//   a/gate: out[row, col/2] = a * gelu(gate), Ch only, ldc = N/2).
//   Vectorized float2 / __half2 epilogue stores.
// ===========================================================================
#define BM 128
#define BN 128
#define BK 32
#define GSTR 40
#define STG_BYTES (2 * 128 * GSTR * 2)
#define GEMM_SMEM (3 * STG_BYTES)

__global__ void __launch_bounds__(256, 2) gemm_f16_kernel(
    const __half* __restrict__ A, int lda,
    const __half* __restrict__ Bt, int ldb,
    float* __restrict__ Cf, __half* __restrict__ Ch, int ldc,
    const float* __restrict__ Res, int ldres,
    const float* __restrict__ bias,
    int M, int K, int emode) {

    extern __shared__ __half smh[];

    const int m0 = blockIdx.y * BM;
    const int n0 = blockIdx.x * BN;
    const int tid = threadIdx.x;
    const int warp = tid >> 5;
    const int lane = tid & 31;
    const int g  = lane >> 2;
    const int tg = lane & 3;
    const int wm = (warp >> 2) * 64;
    const int wn = (warp & 3) * 32;

    const uint32_t smem_u32 = (uint32_t)__cvta_generic_to_shared(smh);
    const int nk = K / BK;

    float acc[4][4][4];
    #pragma unroll
    for (int i = 0; i < 4; i++)
        #pragma unroll
        for (int j = 0; j < 4; j++)
            #pragma unroll
            for (int r = 0; r < 4; r++) acc[i][j][r] = 0.f;

    auto load_stage = [&](int stage, int k0) {
        const uint32_t abase = smem_u32 + (uint32_t)(stage * STG_BYTES);
        #pragma unroll
        for (int i = 0; i < 2; i++) {
            int idx = tid + i * 256;
            int row = idx >> 2;
            int kc  = (idx & 3) * 8;
            int bytes = (m0 + row < M) ? 16 : 0;
            cp_async16(abase + (uint32_t)(row * GSTR + kc) * 2,
                       A + (long long)(m0 + row) * lda + k0 + kc, bytes);
        }
        const uint32_t bbase = abase + (uint32_t)(128 * GSTR * 2);
        #pragma unroll
        for (int i = 0; i < 2; i++) {
            int idx = tid + i * 256;
            int row = idx >> 2;
            int kc  = (idx & 3) * 8;
            cp_async16(bbase + (uint32_t)(row * GSTR + kc) * 2,
                       Bt + (long long)(n0 + row) * ldb + k0 + kc, 16);
        }
        cp_commit();
    };

    const uint32_t lm_off = (uint32_t)((lane & 15) * GSTR + ((lane >> 4) * 8)) * 2;
    const uint32_t a_lm = smem_u32 + (uint32_t)(wm * GSTR) * 2 + lm_off;
    const uint32_t b_lm = smem_u32 + (uint32_t)(128 * GSTR + wn * GSTR) * 2 + lm_off;

    auto compute_stage = [&](int stage) {
        const uint32_t so = (uint32_t)(stage * STG_BYTES);
        #pragma unroll
        for (int ks = 0; ks < 2; ks++) {
            const uint32_t kkb = ks * 32;
            uint32_t afr[4][4];
            #pragma unroll
            for (int mt = 0; mt < 4; mt++)
                ldsm4(afr[mt][0], afr[mt][1], afr[mt][2], afr[mt][3],
                      a_lm + so + (uint32_t)(mt * 16 * GSTR) * 2 + kkb);
            uint32_t bfr[4][2];
            #pragma unroll
            for (int p = 0; p < 2; p++) {
                uint32_t r0, r1, r2, r3;
                ldsm4(r0, r1, r2, r3, b_lm + so + (uint32_t)(p * 16 * GSTR) * 2 + kkb);
                bfr[2 * p][0]     = r0; bfr[2 * p][1]     = r2;
                bfr[2 * p + 1][0] = r1; bfr[2 * p + 1][1] = r3;
            }
            #pragma unroll
            for (int mt = 0; mt < 4; mt++)
                #pragma unroll
                for (int nt = 0; nt < 4; nt++)
                    mma_f16(acc[mt][nt], afr[mt], bfr[nt]);
        }
    };

    load_stage(0, 0);
    if (nk > 1) load_stage(1, BK);
    for (int kt = 0; kt < nk; kt++) {
        if (kt + 1 < nk) cp_wait1(); else cp_wait0();
        __syncthreads();
        if (kt + 2 < nk) load_stage((kt + 2) % 3, (kt + 2) * BK);
        compute_stage(kt % 3);
    }

    // ---- epilogue (vectorized) ----
    #pragma unroll
    for (int mt = 0; mt < 4; mt++) {
        #pragma unroll
        for (int nt = 0; nt < 4; nt++) {
            const int row0 = m0 + wm + mt * 16 + g;
            const int col0 = n0 + wn + nt * 8 + tg * 2;
            #pragma unroll
            for (int hh = 0; hh < 2; hh++) {
                const int row = row0 + hh * 8;
                if (row >= M) continue;
                float v0 = acc[mt][nt][2 * hh + 0];
                float v1 = acc[mt][nt][2 * hh + 1];
                if (bias) { v0 += bias[col0]; v1 += bias[col0 + 1]; }
                if (emode == 3) {
                    // cols interleaved a/gate
                    Ch[(long long)row * ldc + (col0 >> 1)] =
                        __float2half(v0 * gelu_f(v1));
                    continue;
                }
                if (Res) {
                    float2 r = *(const float2*)(Res + (long long)row * ldres + col0);
                    v0 += r.x; v1 += r.y;
                }
                if (Cf) *(float2*)(Cf + (long long)row * ldc + col0) =
                            make_float2(v0, v1);
                if (Ch) *(__half2*)(Ch + (long long)row * ldc + col0) =
                            __floats2half2_rn(v0, v1);
            }
        }
    }
}

// ---------------------------------------------------------------------------
// Host side
// ---------------------------------------------------------------------------
static void gemm(const __half* A, int lda, const __half* Bt, int ldb,
                 float* Cf, __half* Ch, int ldc,
                 const float* Res, int ldres,
                 const float* bias, int M, int N, int K, int emode = 0) {
    dim3 grid(N / BN, (M + BM - 1) / BM);
    gemm_f16_kernel<<<grid, 256, GEMM_SMEM>>>(
        A, lda, Bt, ldb, Cf, Ch, ldc, Res, ldres, bias, M, K, emode);
}

extern "C" void kernel_launch(void* const* d_in, const int* in_sizes, int n_in,
                              void* d_out, int out_size) {
    const float* in_q     = (const float*)d_in[0];
    const float* in_kv    = (const float*)d_in[1];
    const float* gn_g     = (const float*)d_in[2];
    const float* gn_b     = (const float*)d_in[3];
    const float* ln2_g    = (const float*)d_in[4];
    const float* ln2_b    = (const float*)d_in[5];
    const float* ln3_g    = (const float*)d_in[6];
    const float* ln3_b    = (const float*)d_in[7];
    const float* ln4_g    = (const float*)d_in[8];
    const float* ln4_b    = (const float*)d_in[9];
    const float* fc_in_w  = (const float*)d_in[10];
    const float* fc_in_b  = (const float*)d_in[11];
    const float* fc_out_w = (const float*)d_in[12];
    const float* fc_out_b = (const float*)d_in[13];
    const float* a1_q     = (const float*)d_in[14];
    const float* a1_k     = (const float*)d_in[15];
    const float* a1_v     = (const float*)d_in[16];
    const float* a1_o     = (const float*)d_in[17];
    const float* a1_ob    = (const float*)d_in[18];
    const float* a2_q     = (const float*)d_in[19];
    const float* a2_k     = (const float*)d_in[20];
    const float* a2_v     = (const float*)d_in[21];
    const float* a2_o     = (const float*)d_in[22];
    const float* a2_ob    = (const float*)d_in[23];
    const float* ff_proj_w = (const float*)d_in[24];
    const float* ff_proj_b = (const float*)d_in[25];
    const float* ff_out_w  = (const float*)d_in[26];
    const float* ff_out_b  = (const float*)d_in[27];

    cudaFuncSetAttribute(gemm_f16_kernel,
                         cudaFuncAttributeMaxDynamicSharedMemorySize, GEMM_SMEM);
    cudaFuncSetAttribute(flash_self_kernel,
                         cudaFuncAttributeMaxDynamicSharedMemorySize, FS_TOTAL_H * 2);
    cudaFuncSetAttribute(flash_cross_kernel,
                         cudaFuncAttributeMaxDynamicSharedMemorySize, CF_TOTAL_H * 2);

    float *x, *t, *bFfp;
    __half *th, *qkvh, *qh, *kvh, *kv2h, *glh, *xh;
    __half *whFcIn, *whQkv, *whA1o, *whA2q, *whA2o, *whKv2, *whFfp, *whFfo, *whFco;
    cudaGetSymbolAddress((void**)&x,    g_x);
    cudaGetSymbolAddress((void**)&t,    g_t);
    cudaGetSymbolAddress((void**)&bFfp, g_bFfp);
    cudaGetSymbolAddress((void**)&th,   g_th);
    cudaGetSymbolAddress((void**)&qkvh, g_qkvh);
    cudaGetSymbolAddress((void**)&qh,   g_qh);
    cudaGetSymbolAddress((void**)&kvh,  g_kvh);
    cudaGetSymbolAddress((void**)&kv2h, g_kv2h);
    cudaGetSymbolAddress((void**)&glh,  g_glh);
    cudaGetSymbolAddress((void**)&xh,   g_xh);
    cudaGetSymbolAddress((void**)&whFcIn, g_whFcIn);
    cudaGetSymbolAddress((void**)&whQkv,  g_whQkv);
    cudaGetSymbolAddress((void**)&whA1o,  g_whA1o);
    cudaGetSymbolAddress((void**)&whA2q,  g_whA2q);
    cudaGetSymbolAddress((void**)&whA2o,  g_whA2o);
    cudaGetSymbolAddress((void**)&whKv2,  g_whKv2);
    cudaGetSymbolAddress((void**)&whFfp,  g_whFfp);
    cudaGetSymbolAddress((void**)&whFfo,  g_whFfo);
    cudaGetSymbolAddress((void**)&whFco,  g_whFco);

    float* out = (float*)d_out;

    // ---- batched weight transpose+convert (ONE launch) ----
    {
        TrJobs jb;
        const float* srcs[NJOBS] = {fc_in_w, a1_q, a1_k, a1_v, a1_o, a2_q,
                                    a2_o, a2_k, a2_v, ff_proj_w, ff_out_w, fc_out_w};
        __half* dsts[NJOBS] = {whFcIn, whQkv, whQkv + (size_t)512 * 512,
                               whQkv + (size_t)1024 * 512, whA1o, whA2q, whA2o,
                               whKv2, whKv2 + (size_t)512 * 1024,
                               whFfp, whFfo, whFco};
        int Rs[NJOBS] = {512, 512, 512, 512, 512, 512, 512, 1024, 1024, 512, 2048, 512};
        int Cs[NJOBS] = {512, 512, 512, 512, 512, 512, 512, 512, 512, 4096, 512, 512};
        int Il[NJOBS] = {0, 0, 0, 0, 0, 0, 0, 0, 0, 1, 0, 0};
        int acc = 0;
        for (int i = 0; i < NJOBS; i++) {
            jb.src[i] = srcs[i]; jb.dst[i] = dsts[i];
            jb.R[i] = Rs[i]; jb.C[i] = Cs[i]; jb.ileave[i] = Il[i];
            jb.tstart[i] = acc;
            acc += (Rs[i] / 32) * (Cs[i] / 32);
        }
        jb.tstart[NJOBS] = acc;
        trcvt_all_kernel<<<acc, dim3(32, 8)>>>(jb);
    }
    cvt_kernel<<<(BATCH * KVLEN * 1024 + 255) / 256, 256>>>(
        in_kv, kvh, BATCH * KVLEN * 1024);
    bias_ileave_kernel<<<8, 256>>>(ff_proj_b, bFfp);

    // 1. GroupNorm + transpose -> th (half)
    groupnorm_kernel<<<BATCH * 32, 256>>>(in_q, gn_g, gn_b, th);

    // 2. x = th @ fc_in + b (fp32)
    gemm(th, 512, whFcIn, 512, x, nullptr, 512, nullptr, 0, fc_in_b,
         NTOK, 512, 512);

    // ---- self attention ----
    layernorm_kernel<<<NTOK / 8, 256>>>(x, ln2_g, ln2_b, th, NTOK);
    gemm(th, 512, whQkv, 512, nullptr, qkvh, 1536, nullptr, 0, nullptr,
         NTOK, 1536, 512);
    {
        dim3 grid(8, 64);
        flash_self_kernel<<<grid, 256, FS_TOTAL_H * 2>>>(qkvh, th);
    }
    gemm(th, 512, whA1o, 512, x, nullptr, 512, x, 512, a1_ob,
         NTOK, 512, 512);

    // ---- cross attention ----
    layernorm_kernel<<<NTOK / 8, 256>>>(x, ln3_g, ln3_b, th, NTOK);
    gemm(th, 512, whA2q, 512, nullptr, qh, 512, nullptr, 0, nullptr,
         NTOK, 512, 512);
    gemm(kvh, 1024, whKv2, 1024, nullptr, kv2h, 1024, nullptr, 0, nullptr,
         BATCH * KVLEN, 1024, 1024);
    {
        dim3 grid(8, 64);
        flash_cross_kernel<<<grid, 256, CF_TOTAL_H * 2>>>(qh, kv2h, th);
    }
    gemm(th, 512, whA2o, 512, x, nullptr, 512, x, 512, a2_ob,
         NTOK, 512, 512);

    // ---- feed-forward (GEGLU, single interleaved GEMM) ----
    layernorm_kernel<<<NTOK / 8, 256>>>(x, ln4_g, ln4_b, th, NTOK);
    gemm(th, 512, whFfp, 512, nullptr, glh, 2048, nullptr, 0, bFfp,
         NTOK, 4096, 512, 3);
    // x = glh @ Wout + b + x (fp32 + half mirror xh)
    gemm(glh, 2048, whFfo, 2048, x, xh, 512, x, 512, ff_out_b,
         NTOK, 512, 2048);

    // ---- output projection ----
    gemm(xh, 512, whFco, 512, t, nullptr, 512, nullptr, 0, fc_out_b,
         NTOK, 512, 512);

    output_kernel<<<(BATCH * DIMC * SPATIAL) / 256, 256>>>(t, in_q, out);
}

// round 13
// speedup vs baseline: 2.0028x; 1.0625x over previous
#include <cuda_runtime.h>
#include <cuda_fp16.h>
#include <cstdint>
#include <math.h>

// ---------------------------------------------------------------------------
// Problem constants
// ---------------------------------------------------------------------------
#define BATCH   8
#define DIMC    512
#define SPATIAL 1024
#define NTOK    (BATCH*SPATIAL)  // 8192
#define HEADS   8
#define HDIM    64
#define KVLEN   77
#define KVDIM   1024

// ---------------------------------------------------------------------------
// Scratch buffers
// ---------------------------------------------------------------------------
__device__ float  g_x  [(size_t)NTOK * DIMC];           // fp32 residual stream
__device__ float  g_t  [(size_t)NTOK * DIMC];           // fp32 temp (fco out)
__device__ float  g_bFfp[4096];                         // interleaved ffp bias
__device__ float  g_gnstats[BATCH * 32 * 2];            // groupnorm mu/inv
__device__ __half g_th  [(size_t)NTOK * DIMC];
__device__ __half g_qkvh[(size_t)NTOK * 1536];
__device__ __half g_qh  [(size_t)NTOK * DIMC];
__device__ __half g_kvh [(size_t)(BATCH*KVLEN) * 1024];
__device__ __half g_kv2h[(size_t)(BATCH*KVLEN) * 1024];
__device__ __half g_glh [(size_t)NTOK * 2048];
__device__ __half g_xh  [(size_t)NTOK * DIMC];
// half transposed weights [N, K]
__device__ __half g_whFcIn[(size_t)512 * 512];
__device__ __half g_whQkv [(size_t)1536 * 512];
__device__ __half g_whA1o [(size_t)512 * 512];
__device__ __half g_whA2q [(size_t)512 * 512];
__device__ __half g_whA2o [(size_t)512 * 512];
__device__ __half g_whKv2 [(size_t)1024 * 1024];
__device__ __half g_whFfp [(size_t)4096 * 512];         // a/gate interleaved rows
__device__ __half g_whFfo [(size_t)512 * 2048];
__device__ __half g_whFco [(size_t)512 * 512];

// ---------------------------------------------------------------------------
// Helpers
// ---------------------------------------------------------------------------
__device__ __forceinline__ float warpSum(float v) {
    #pragma unroll
    for (int o = 16; o > 0; o >>= 1) v += __shfl_xor_sync(0xffffffffu, v, o);
    return v;
}
__device__ __forceinline__ void mma_f16(float* d, const uint32_t* a, const uint32_t* b) {
    asm volatile(
        "mma.sync.aligned.m16n8k16.row.col.f32.f16.f16.f32 "
        "{%0,%1,%2,%3}, {%4,%5,%6,%7}, {%8,%9}, {%0,%1,%2,%3};"
        : "+f"(d[0]), "+f"(d[1]), "+f"(d[2]), "+f"(d[3])
        : "r"(a[0]), "r"(a[1]), "r"(a[2]), "r"(a[3]), "r"(b[0]), "r"(b[1]));
}
__device__ __forceinline__ void ldsm4(uint32_t& r0, uint32_t& r1,
                                      uint32_t& r2, uint32_t& r3, uint32_t addr) {
    asm volatile("ldmatrix.sync.aligned.m8n8.x4.shared.b16 {%0,%1,%2,%3}, [%4];"
                 : "=r"(r0), "=r"(r1), "=r"(r2), "=r"(r3) : "r"(addr));
}
__device__ __forceinline__ void cp_async16(uint32_t dst, const void* src, int bytes) {
    asm volatile("cp.async.cg.shared.global [%0], [%1], 16, %2;\n"
                 :: "r"(dst), "l"(src), "r"(bytes));
}
__device__ __forceinline__ void cp_commit() { asm volatile("cp.async.commit_group;\n"); }
__device__ __forceinline__ void cp_wait1()  { asm volatile("cp.async.wait_group 1;\n"); }
__device__ __forceinline__ void cp_wait0()  { asm volatile("cp.async.wait_group 0;\n"); }
__device__ __forceinline__ float gelu_f(float v) {
    return 0.5f * v * (1.f + erff(v * 0.70710678118654752f));
}

// ---------------------------------------------------------------------------
// GroupNorm stats: one block per (batch, group). Coalesced read only.
// ---------------------------------------------------------------------------
__global__ void gn_stats_kernel(const float* __restrict__ qin,
                                float* __restrict__ stats) {
    const int blk = blockIdx.x;             // b*32 + grp
    const float* base = qin + (size_t)blk * 16 * SPATIAL;

    float s = 0.f, s2 = 0.f;
    for (int i = threadIdx.x; i < 16 * SPATIAL; i += 256) {
        float v = base[i];
        s += v; s2 += v * v;
    }
    __shared__ float red[2][8];
    s = warpSum(s); s2 = warpSum(s2);
    int wid = threadIdx.x >> 5, lid = threadIdx.x & 31;
    if (lid == 0) { red[0][wid] = s; red[1][wid] = s2; }
    __syncthreads();
    if (threadIdx.x == 0) {
        float a = 0.f, c = 0.f;
        #pragma unroll
        for (int i = 0; i < 8; i++) { a += red[0][i]; c += red[1][i]; }
        const float mu  = a * (1.f / 16384.f);
        const float var = c * (1.f / 16384.f) - mu * mu;
        stats[blk * 2]     = mu;
        stats[blk * 2 + 1] = rsqrtf(var + 1e-6f);
    }
}

// ---------------------------------------------------------------------------
// GroupNorm normalize + transpose to token-major (32x32 tiles, coalesced).
// grid (S/32, C/32, B), block (32, 8)
// ---------------------------------------------------------------------------
__global__ void gn_write_kernel(const float* __restrict__ qin,
                                const float* __restrict__ stats,
                                const float* __restrict__ gamma,
                                const float* __restrict__ beta,
                                __half* __restrict__ out) {
    __shared__ float tile[32][33];
    const int b  = blockIdx.z;
    const int c0 = blockIdx.y * 32;
    const int s0 = blockIdx.x * 32;
    const int x = threadIdx.x, y = threadIdx.y;

    #pragma unroll
    for (int i = 0; i < 32; i += 8)
        tile[y + i][x] = qin[((size_t)(b * DIMC + c0 + y + i)) * SPATIAL + s0 + x];
    __syncthreads();

    const int c = c0 + x;
    const int sb = (b * 32 + (c >> 4)) * 2;
    const float mu  = stats[sb];
    const float inv = stats[sb + 1];
    const float gm = gamma[c], bt = beta[c];
    #pragma unroll
    for (int i = 0; i < 32; i += 8) {
        float v = (tile[x][y + i] - mu) * inv * gm + bt;
        out[((size_t)(b * SPATIAL + s0 + y + i)) * DIMC + c] = __float2half(v);
    }
}

// ---------------------------------------------------------------------------
// LayerNorm (fp32 in, half out). One warp per 512-dim row.
// ---------------------------------------------------------------------------
__global__ void layernorm_kernel(const float* __restrict__ x,
                                 const float* __restrict__ gamma,
                                 const float* __restrict__ beta,
                                 __half* __restrict__ out, int rows) {
    int row = blockIdx.x * 8 + (threadIdx.x >> 5);
    if (row >= rows) return;
    int lid = threadIdx.x & 31;
    const float4* xr = (const float4*)(x + (size_t)row * DIMC);

    float4 vals[4];
    float s = 0.f, s2 = 0.f;
    #pragma unroll
    for (int i = 0; i < 4; i++) {
        float4 v = xr[lid + 32 * i];
        vals[i] = v;
        s  += v.x + v.y + v.z + v.w;
        s2 += v.x*v.x + v.y*v.y + v.z*v.z + v.w*v.w;
    }
    s = warpSum(s); s2 = warpSum(s2);
    const float mu  = s * (1.f / 512.f);
    const float inv = rsqrtf(s2 * (1.f / 512.f) - mu * mu + 1e-5f);

    __half2* orow = (__half2*)(out + (size_t)row * DIMC);
    const float4* g4 = (const float4*)gamma;
    const float4* b4 = (const float4*)beta;
    #pragma unroll
    for (int i = 0; i < 4; i++) {
        int idx = lid + 32 * i;
        float4 v = vals[i], g = g4[idx], b = b4[idx];
        float ox = (v.x - mu) * inv * g.x + b.x;
        float oy = (v.y - mu) * inv * g.y + b.y;
        float oz = (v.z - mu) * inv * g.z + b.z;
        float ow = (v.w - mu) * inv * g.w + b.w;
        orow[idx * 2]     = __floats2half2_rn(ox, oy);
        orow[idx * 2 + 1] = __floats2half2_rn(oz, ow);
    }
}

// ---------------------------------------------------------------------------
// Batched transpose + f32->f16 (12 weights, ONE launch). Optional row
// interleave for GEGLU.
// ---------------------------------------------------------------------------
#define NJOBS 12
struct TrJobs {
    const float* src[NJOBS];
    __half*      dst[NJOBS];
    int R[NJOBS], C[NJOBS], ileave[NJOBS];
    int tstart[NJOBS + 1];
};

__global__ void trcvt_all_kernel(TrJobs jobs) {
    __shared__ float tile[32][33];
    const int flat = blockIdx.x;
    int j = 0;
    #pragma unroll
    for (int i = 0; i < NJOBS; i++)
        if (flat >= jobs.tstart[i + 1]) j = i + 1;
    const int lt = flat - jobs.tstart[j];
    const int C = jobs.C[j], R = jobs.R[j];
    const int ctiles = C >> 5;
    const int c0 = (lt % ctiles) * 32;
    const int r0 = (lt / ctiles) * 32;
    const float* src = jobs.src[j];
    __half* dst = jobs.dst[j];
    const int il = jobs.ileave[j];
    const int halfC = C >> 1;

    int x = threadIdx.x, y = threadIdx.y;
    #pragma unroll
    for (int i = 0; i < 32; i += 8)
        tile[y + i][x] = src[(size_t)(r0 + y + i) * C + c0 + x];
    __syncthreads();
    #pragma unroll
    for (int i = 0; i < 32; i += 8) {
        int d = c0 + y + i;
        if (il) d = (d < halfC) ? 2 * d : 2 * (d - halfC) + 1;
        dst[(size_t)d * R + r0 + x] = __float2half(tile[x][y + i]);
    }
}

// f32 -> f16 linear convert
__global__ void cvt_kernel(const float* __restrict__ src,
                           __half* __restrict__ dst, int n) {
    int i = blockIdx.x * 256 + threadIdx.x;
    if (i < n) dst[i] = __float2half(src[i]);
}

// interleave ffp bias
__global__ void bias_ileave_kernel(const float* __restrict__ b,
                                   float* __restrict__ dst) {
    int j = blockIdx.x * 256 + threadIdx.x;
    if (j < 2048) {
        dst[2 * j]     = b[j];
        dst[2 * j + 1] = b[2048 + j];
    }
}

// ---------------------------------------------------------------------------
// Final transpose + residual (32x32 tiles, coalesced both sides).
// grid (S/32, C/32, B), block (32, 8)
// ---------------------------------------------------------------------------
__global__ void output_kernel(const float* __restrict__ t,
                              const float* __restrict__ qin,
                              float* __restrict__ out) {
    __shared__ float tile[32][33];
    const int b  = blockIdx.z;
    const int c0 = blockIdx.y * 32;
    const int s0 = blockIdx.x * 32;
    const int x = threadIdx.x, y = threadIdx.y;

    #pragma unroll
    for (int i = 0; i < 32; i += 8)
        tile[y + i][x] = t[((size_t)(b * SPATIAL + s0 + y + i)) * DIMC + c0 + x];
    __syncthreads();

    #pragma unroll
    for (int i = 0; i < 32; i += 8) {
        const size_t o = ((size_t)(b * DIMC + c0 + y + i)) * SPATIAL + s0 + x;
        out[o] = tile[x][y + i] + qin[o];
    }
}

// ===========================================================================
// Fused flash self-attention, fp16 operands, fp32 accum.
// ===========================================================================
#define SCL 0.125f
#define FH 72
#define PH 136
#define FS_SQ   0
#define FS_SK   (128*FH)
#define FS_SVT  (FS_SK + 128*FH)
#define FS_SP   (FS_SVT + 64*PH)
#define FS_TOTAL_H (FS_SP + 128*PH)

__global__ void __launch_bounds__(256) flash_self_kernel(
    const __half* __restrict__ qkv, __half* __restrict__ outp) {
    extern __shared__ __half smh[];
    __half* sQ  = smh + FS_SQ;
    __half* sK  = smh + FS_SK;
    __half* sVt = smh + FS_SVT;
    __half* sP  = smh + FS_SP;

    const int b  = blockIdx.y >> 3;
    const int h  = blockIdx.y & 7;
    const int q0 = blockIdx.x * 128;
    const int tid = threadIdx.x;
    const int warp = tid >> 5;
    const int lane = tid & 31;
    const int g  = lane >> 2;
    const int tg = lane & 3;
    const int wm = warp * 16;

    const uint32_t smb = (uint32_t)__cvta_generic_to_shared(smh);
    const uint32_t lr = lane & 15;
    const uint32_t lh = (lane >> 4) * 8;

    for (int i = tid; i < 1024; i += 256) {
        int row = i >> 3;
        int c8  = (i & 7) * 8;
        *(uint4*)(sQ + row * FH + c8) = *(const uint4*)(qkv +
            (size_t)(b * 1024 + q0 + row) * 1536 + h * 64 + c8);
    }
    __syncthreads();

    uint32_t qf[4][4];
    {
        const uint32_t qbase = smb + (uint32_t)(FS_SQ + (wm + lr) * FH + lh) * 2;
        #pragma unroll
        for (int kc = 0; kc < 4; kc++)
            ldsm4(qf[kc][0], qf[kc][1], qf[kc][2], qf[kc][3], qbase + kc * 32);
    }

    float m_[2] = {-1e30f, -1e30f};
    float l_[2] = {0.f, 0.f};
    float acco[8][4];
    #pragma unroll
    for (int i = 0; i < 8; i++)
        #pragma unroll
        for (int r = 0; r < 4; r++) acco[i][r] = 0.f;

    const uint32_t kbase = smb + (uint32_t)(FS_SK + lr * FH + lh) * 2;
    const uint32_t pbase = smb + (uint32_t)(FS_SP + (wm + lr) * PH + lh) * 2;
    const uint32_t vbase = smb + (uint32_t)(FS_SVT + lr * PH + lh) * 2;

    for (int j = 0; j < 8; j++) {
        for (int i = tid; i < 1024; i += 256) {
            int row = i >> 3;
            int c8  = (i & 7) * 8;
            const __half* base = qkv + (size_t)(b * 1024 + j * 128 + row) * 1536 + h * 64;
            *(uint4*)(sK + row * FH + c8) = *(const uint4*)(base + 512 + c8);
            uint4 vv = *(const uint4*)(base + 1024 + c8);
            const __half* hv = (const __half*)&vv;
            #pragma unroll
            for (int q = 0; q < 8; q++) sVt[(c8 + q) * PH + row] = hv[q];
        }
        __syncthreads();

        float accs[16][4];
        #pragma unroll
        for (int nt = 0; nt < 16; nt++)
            #pragma unroll
            for (int r = 0; r < 4; r++) accs[nt][r] = 0.f;

        #pragma unroll
        for (int kc = 0; kc < 4; kc++) {
            const uint32_t ka = kbase + kc * 32;
            #pragma unroll
            for (int p = 0; p < 8; p++) {
                uint32_t b0, b1, b2, b3;
                ldsm4(b0, b1, b2, b3, ka + (uint32_t)(p * 16 * FH) * 2);
                uint32_t bf0[2] = {b0, b2};
                uint32_t bf1[2] = {b1, b3};
                mma_f16(accs[2 * p],     qf[kc], bf0);
                mma_f16(accs[2 * p + 1], qf[kc], bf1);
            }
        }

        float mx0 = -1e30f, mx1 = -1e30f;
        #pragma unroll
        for (int nt = 0; nt < 16; nt++) {
            mx0 = fmaxf(mx0, fmaxf(accs[nt][0], accs[nt][1]));
            mx1 = fmaxf(mx1, fmaxf(accs[nt][2], accs[nt][3]));
        }
        mx0 = fmaxf(mx0, __shfl_xor_sync(0xffffffffu, mx0, 1));
        mx0 = fmaxf(mx0, __shfl_xor_sync(0xffffffffu, mx0, 2));
        mx1 = fmaxf(mx1, __shfl_xor_sync(0xffffffffu, mx1, 1));
        mx1 = fmaxf(mx1, __shfl_xor_sync(0xffffffffu, mx1, 2));
        const float mn0 = fmaxf(m_[0], mx0);
        const float mn1 = fmaxf(m_[1], mx1);
        const float c0 = __expf((m_[0] - mn0) * SCL);
        const float c1 = __expf((m_[1] - mn1) * SCL);
        l_[0] *= c0; l_[1] *= c1;
        #pragma unroll
        for (int nt = 0; nt < 8; nt++) {
            acco[nt][0] *= c0; acco[nt][1] *= c0;
            acco[nt][2] *= c1; acco[nt][3] *= c1;
        }
        float rs0 = 0.f, rs1 = 0.f;
        __half* p0 = sP + (wm + g) * PH + 2 * tg;
        __half* p1 = sP + (wm + g + 8) * PH + 2 * tg;
        #pragma unroll
        for (int nt = 0; nt < 16; nt++) {
            const float e0 = __expf((accs[nt][0] - mn0) * SCL);
            const float e1 = __expf((accs[nt][1] - mn0) * SCL);
            const float e2 = __expf((accs[nt][2] - mn1) * SCL);
            const float e3 = __expf((accs[nt][3] - mn1) * SCL);
            rs0 += e0 + e1; rs1 += e2 + e3;
            *(__half2*)(p0 + nt * 8) = __floats2half2_rn(e0, e1);
            *(__half2*)(p1 + nt * 8) = __floats2half2_rn(e2, e3);
        }
        rs0 += __shfl_xor_sync(0xffffffffu, rs0, 1);
        rs0 += __shfl_xor_sync(0xffffffffu, rs0, 2);
        rs1 += __shfl_xor_sync(0xffffffffu, rs1, 1);
        rs1 += __shfl_xor_sync(0xffffffffu, rs1, 2);
        l_[0] += rs0; l_[1] += rs1;
        m_[0] = mn0; m_[1] = mn1;
        __syncwarp();

        #pragma unroll
        for (int kc = 0; kc < 8; kc++) {
            uint32_t af[4];
            ldsm4(af[0], af[1], af[2], af[3], pbase + kc * 32);
            const uint32_t va = vbase + kc * 32;
            #pragma unroll
            for (int p = 0; p < 4; p++) {
                uint32_t b0, b1, b2, b3;
                ldsm4(b0, b1, b2, b3, va + (uint32_t)(p * 16 * PH) * 2);
                uint32_t bf0[2] = {b0, b2};
                uint32_t bf1[2] = {b1, b3};
                mma_f16(acco[2 * p],     af, bf0);
                mma_f16(acco[2 * p + 1], af, bf1);
            }
        }
        __syncthreads();
    }

    const float i0 = 1.f / l_[0];
    const float i1 = 1.f / l_[1];
    const int row0 = b * 1024 + q0 + wm + g;
    #pragma unroll
    for (int nt = 0; nt < 8; nt++) {
        const int col = h * 64 + nt * 8 + 2 * tg;
        *(__half2*)(outp + (size_t)row0 * 512 + col) =
            __floats2half2_rn(acco[nt][0] * i0, acco[nt][1] * i0);
        *(__half2*)(outp + (size_t)(row0 + 8) * 512 + col) =
            __floats2half2_rn(acco[nt][2] * i1, acco[nt][3] * i1);
    }
}

// ===========================================================================
// Fused flash cross-attention (kv 77 -> padded 80), fp16.
// ===========================================================================
#define CH 88
#define CF_SQ   0
#define CF_SK   (128*FH)
#define CF_SVT  (CF_SK + 80*FH)
#define CF_SP   (CF_SVT + 64*CH)
#define CF_TOTAL_H (CF_SP + 128*CH)

__global__ void __launch_bounds__(256) flash_cross_kernel(
    const __half* __restrict__ qsrc, const __half* __restrict__ kv2,
    __half* __restrict__ outp) {
    extern __shared__ __half smh[];
    __half* sQ  = smh + CF_SQ;
    __half* sK  = smh + CF_SK;
    __half* sVt = smh + CF_SVT;
    __half* sP  = smh + CF_SP;

    const int b  = blockIdx.y >> 3;
    const int h  = blockIdx.y & 7;
    const int q0 = blockIdx.x * 128;
    const int tid = threadIdx.x;
    const int warp = tid >> 5;
    const int lane = tid & 31;
    const int g  = lane >> 2;
    const int tg = lane & 3;
    const int wm = warp * 16;

    const uint32_t smb = (uint32_t)__cvta_generic_to_shared(smh);
    const uint32_t lr = lane & 15;
    const uint32_t lh = (lane >> 4) * 8;

    for (int i = tid; i < 1024; i += 256) {
        int row = i >> 3;
        int c8  = (i & 7) * 8;
        *(uint4*)(sQ + row * FH + c8) = *(const uint4*)(qsrc +
            (size_t)(b * 1024 + q0 + row) * 512 + h * 64 + c8);
    }
    for (int i = tid; i < 640; i += 256) {
        int row = i >> 3;
        int c8  = (i & 7) * 8;
        uint4 kk = make_uint4(0, 0, 0, 0), vv = make_uint4(0, 0, 0, 0);
        if (row < KVLEN) {
            const __half* base = kv2 + (size_t)(b * KVLEN + row) * 1024 + h * 64;
            kk = *(const uint4*)(base + c8);
            vv = *(const uint4*)(base + 512 + c8);
        }
        *(uint4*)(sK + row * FH + c8) = kk;
        const __half* hv = (const __half*)&vv;
        #pragma unroll
        for (int q = 0; q < 8; q++) sVt[(c8 + q) * CH + row] = hv[q];
    }
    __syncthreads();

    uint32_t qf[4][4];
    {
        const uint32_t qbase = smb + (uint32_t)(CF_SQ + (wm + lr) * FH + lh) * 2;
        #pragma unroll
        for (int kc = 0; kc < 4; kc++)
            ldsm4(qf[kc][0], qf[kc][1], qf[kc][2], qf[kc][3], qbase + kc * 32);
    }

    float accs[10][4];
    #pragma unroll
    for (int nt = 0; nt < 10; nt++)
        #pragma unroll
        for (int r = 0; r < 4; r++) accs[nt][r] = 0.f;
    {
        const uint32_t kbase = smb + (uint32_t)(CF_SK + lr * FH + lh) * 2;
        #pragma unroll
        for (int kc = 0; kc < 4; kc++) {
            const uint32_t ka = kbase + kc * 32;
            #pragma unroll
            for (int p = 0; p < 5; p++) {
                uint32_t b0, b1, b2, b3;
                ldsm4(b0, b1, b2, b3, ka + (uint32_t)(p * 16 * FH) * 2);
                uint32_t bf0[2] = {b0, b2};
                uint32_t bf1[2] = {b1, b3};
                mma_f16(accs[2 * p],     qf[kc], bf0);
                mma_f16(accs[2 * p + 1], qf[kc], bf1);
            }
        }
    }

    #pragma unroll
    for (int nt = 0; nt < 10; nt++) {
        const int col0 = nt * 8 + 2 * tg;
        if (col0 >= KVLEN)     { accs[nt][0] = -1e30f; accs[nt][2] = -1e30f; }
        if (col0 + 1 >= KVLEN) { accs[nt][1] = -1e30f; accs[nt][3] = -1e30f; }
    }
    float mx0 = -1e30f, mx1 = -1e30f;
    #pragma unroll
    for (int nt = 0; nt < 10; nt++) {
        mx0 = fmaxf(mx0, fmaxf(accs[nt][0], accs[nt][1]));
        mx1 = fmaxf(mx1, fmaxf(accs[nt][2], accs[nt][3]));
    }
    mx0 = fmaxf(mx0, __shfl_xor_sync(0xffffffffu, mx0, 1));
    mx0 = fmaxf(mx0, __shfl_xor_sync(0xffffffffu, mx0, 2));
    mx1 = fmaxf(mx1, __shfl_xor_sync(0xffffffffu, mx1, 1));
    mx1 = fmaxf(mx1, __shfl_xor_sync(0xffffffffu, mx1, 2));

    float rs0 = 0.f, rs1 = 0.f;
    __half* p0 = sP + (wm + g) * CH + 2 * tg;
    __half* p1 = sP + (wm + g + 8) * CH + 2 * tg;
    #pragma unroll
    for (int nt = 0; nt < 10; nt++) {
        const float e0 = __expf((accs[nt][0] - mx0) * SCL);
        const float e1 = __expf((accs[nt][1] - mx0) * SCL);
        const float e2 = __expf((accs[nt][2] - mx1) * SCL);
        const float e3 = __expf((accs[nt][3] - mx1) * SCL);
        rs0 += e0 + e1; rs1 += e2 + e3;
        *(__half2*)(p0 + nt * 8) = __floats2half2_rn(e0, e1);
        *(__half2*)(p1 + nt * 8) = __floats2half2_rn(e2, e3);
    }
    rs0 += __shfl_xor_sync(0xffffffffu, rs0, 1);
    rs0 += __shfl_xor_sync(0xffffffffu, rs0, 2);
    rs1 += __shfl_xor_sync(0xffffffffu, rs1, 1);
    rs1 += __shfl_xor_sync(0xffffffffu, rs1, 2);
    __syncwarp();

    float acco[8][4];
    #pragma unroll
    for (int nt = 0; nt < 8; nt++)
        #pragma unroll
        for (int r = 0; r < 4; r++) acco[nt][r] = 0.f;
    {
        const uint32_t pb = smb + (uint32_t)(CF_SP + (wm + lr) * CH + lh) * 2;
        const uint32_t vb = smb + (uint32_t)(CF_SVT + lr * CH + lh) * 2;
        #pragma unroll
        for (int kc = 0; kc < 5; kc++) {
            uint32_t af[4];
            ldsm4(af[0], af[1], af[2], af[3], pb + kc * 32);
            const uint32_t va = vb + kc * 32;
            #pragma unroll
            for (int p = 0; p < 4; p++) {
                uint32_t b0, b1, b2, b3;
                ldsm4(b0, b1, b2, b3, va + (uint32_t)(p * 16 * CH) * 2);
                uint32_t bf0[2] = {b0, b2};
                uint32_t bf1[2] = {b1, b3};
                mma_f16(acco[2 * p],     af, bf0);
                mma_f16(acco[2 * p + 1], af, bf1);
            }
        }
    }

    const float i0 = 1.f / rs0;
    const float i1 = 1.f / rs1;
    const int row0 = b * 1024 + q0 + wm + g;
    #pragma unroll
    for (int nt = 0; nt < 8; nt++) {
        const int col = h * 64 + nt * 8 + 2 * tg;
        *(__half2*)(outp + (size_t)row0 * 512 + col) =
            __floats2half2_rn(acco[nt][0] * i0, acco[nt][1] * i0);
        *(__half2*)(outp + (size_t)(row0 + 8) * 512 + col) =
            __floats2half2_rn(acco[nt][2] * i1, acco[nt][3] * i1);
    }
}

// ===========================================================================
// FP16 tensor-core GEMM: C = A @ Bt^T (+bias)(+epilogue)
//   emode 0: plain (+Res fp32 add); 3: GEGLU-paired interleaved a/gate.
// ===========================================================================
#define BM 128
#define BN 128
#define BK 32
#define GSTR 40
#define STG_BYTES (2 * 128 * GSTR * 2)
#define GEMM_SMEM (3 * STG_BYTES)

__global__ void __launch_bounds__(256, 2) gemm_f16_kernel(
    const __half* __restrict__ A, int lda,
    const __half* __restrict__ Bt, int ldb,
    float* __restrict__ Cf, __half* __restrict__ Ch, int ldc,
    const float* __restrict__ Res, int ldres,
    const float* __restrict__ bias,
    int M, int K, int emode) {

    extern __shared__ __half smh[];

    const int m0 = blockIdx.y * BM;
    const int n0 = blockIdx.x * BN;
    const int tid = threadIdx.x;
    const int warp = tid >> 5;
    const int lane = tid & 31;
    const int g  = lane >> 2;
    const int tg = lane & 3;
    const int wm = (warp >> 2) * 64;
    const int wn = (warp & 3) * 32;

    const uint32_t smem_u32 = (uint32_t)__cvta_generic_to_shared(smh);
    const int nk = K / BK;

    float acc[4][4][4];
    #pragma unroll
    for (int i = 0; i < 4; i++)
        #pragma unroll
        for (int j = 0; j < 4; j++)
            #pragma unroll
            for (int r = 0; r < 4; r++) acc[i][j][r] = 0.f;

    auto load_stage = [&](int stage, int k0) {
        const uint32_t abase = smem_u32 + (uint32_t)(stage * STG_BYTES);
        #pragma unroll
        for (int i = 0; i < 2; i++) {
            int idx = tid + i * 256;
            int row = idx >> 2;
            int kc  = (idx & 3) * 8;
            int bytes = (m0 + row < M) ? 16 : 0;
            cp_async16(abase + (uint32_t)(row * GSTR + kc) * 2,
                       A + (long long)(m0 + row) * lda + k0 + kc, bytes);
        }
        const uint32_t bbase = abase + (uint32_t)(128 * GSTR * 2);
        #pragma unroll
        for (int i = 0; i < 2; i++) {
            int idx = tid + i * 256;
            int row = idx >> 2;
            int kc  = (idx & 3) * 8;
            cp_async16(bbase + (uint32_t)(row * GSTR + kc) * 2,
                       Bt + (long long)(n0 + row) * ldb + k0 + kc, 16);
        }
        cp_commit();
    };

    const uint32_t lm_off = (uint32_t)((lane & 15) * GSTR + ((lane >> 4) * 8)) * 2;
    const uint32_t a_lm = smem_u32 + (uint32_t)(wm * GSTR) * 2 + lm_off;
    const uint32_t b_lm = smem_u32 + (uint32_t)(128 * GSTR + wn * GSTR) * 2 + lm_off;

    auto compute_stage = [&](int stage) {
        const uint32_t so = (uint32_t)(stage * STG_BYTES);
        #pragma unroll
        for (int ks = 0; ks < 2; ks++) {
            const uint32_t kkb = ks * 32;
            uint32_t afr[4][4];
            #pragma unroll
            for (int mt = 0; mt < 4; mt++)
                ldsm4(afr[mt][0], afr[mt][1], afr[mt][2], afr[mt][3],
                      a_lm + so + (uint32_t)(mt * 16 * GSTR) * 2 + kkb);
            uint32_t bfr[4][2];
            #pragma unroll
            for (int p = 0; p < 2; p++) {
                uint32_t r0, r1, r2, r3;
                ldsm4(r0, r1, r2, r3, b_lm + so + (uint32_t)(p * 16 * GSTR) * 2 + kkb);
                bfr[2 * p][0]     = r0; bfr[2 * p][1]     = r2;
                bfr[2 * p + 1][0] = r1; bfr[2 * p + 1][1] = r3;
            }
            #pragma unroll
            for (int mt = 0; mt < 4; mt++)
                #pragma unroll
                for (int nt = 0; nt < 4; nt++)
                    mma_f16(acc[mt][nt], afr[mt], bfr[nt]);
        }
    };

    load_stage(0, 0);
    if (nk > 1) load_stage(1, BK);
    for (int kt = 0; kt < nk; kt++) {
        if (kt + 1 < nk) cp_wait1(); else cp_wait0();
        __syncthreads();
        if (kt + 2 < nk) load_stage((kt + 2) % 3, (kt + 2) * BK);
        compute_stage(kt % 3);
    }

    // ---- epilogue (vectorized) ----
    #pragma unroll
    for (int mt = 0; mt < 4; mt++) {
        #pragma unroll
        for (int nt = 0; nt < 4; nt++) {
            const int row0 = m0 + wm + mt * 16 + g;
            const int col0 = n0 + wn + nt * 8 + tg * 2;
            #pragma unroll
            for (int hh = 0; hh < 2; hh++) {
                const int row = row0 + hh * 8;
                if (row >= M) continue;
                float v0 = acc[mt][nt][2 * hh + 0];
                float v1 = acc[mt][nt][2 * hh + 1];
                if (bias) { v0 += bias[col0]; v1 += bias[col0 + 1]; }
                if (emode == 3) {
                    Ch[(long long)row * ldc + (col0 >> 1)] =
                        __float2half(v0 * gelu_f(v1));
                    continue;
                }
                if (Res) {
                    float2 r = *(const float2*)(Res + (long long)row * ldres + col0);
                    v0 += r.x; v1 += r.y;
                }
                if (Cf) *(float2*)(Cf + (long long)row * ldc + col0) =
                            make_float2(v0, v1);
                if (Ch) *(__half2*)(Ch + (long long)row * ldc + col0) =
                            __floats2half2_rn(v0, v1);
            }
        }
    }
}

// ---------------------------------------------------------------------------
// Host side
// ---------------------------------------------------------------------------
static void gemm(const __half* A, int lda, const __half* Bt, int ldb,
                 float* Cf, __half* Ch, int ldc,
                 const float* Res, int ldres,
                 const float* bias, int M, int N, int K, int emode = 0) {
    dim3 grid(N / BN, (M + BM - 1) / BM);
    gemm_f16_kernel<<<grid, 256, GEMM_SMEM>>>(
        A, lda, Bt, ldb, Cf, Ch, ldc, Res, ldres, bias, M, K, emode);
}

extern "C" void kernel_launch(void* const* d_in, const int* in_sizes, int n_in,
                              void* d_out, int out_size) {
    const float* in_q     = (const float*)d_in[0];
    const float* in_kv    = (const float*)d_in[1];
    const float* gn_g     = (const float*)d_in[2];
    const float* gn_b     = (const float*)d_in[3];
    const float* ln2_g    = (const float*)d_in[4];
    const float* ln2_b    = (const float*)d_in[5];
    const float* ln3_g    = (const float*)d_in[6];
    const float* ln3_b    = (const float*)d_in[7];
    const float* ln4_g    = (const float*)d_in[8];
    const float* ln4_b    = (const float*)d_in[9];
    const float* fc_in_w  = (const float*)d_in[10];
    const float* fc_in_b  = (const float*)d_in[11];
    const float* fc_out_w = (const float*)d_in[12];
    const float* fc_out_b = (const float*)d_in[13];
    const float* a1_q     = (const float*)d_in[14];
    const float* a1_k     = (const float*)d_in[15];
    const float* a1_v     = (const float*)d_in[16];
    const float* a1_o     = (const float*)d_in[17];
    const float* a1_ob    = (const float*)d_in[18];
    const float* a2_q     = (const float*)d_in[19];
    const float* a2_k     = (const float*)d_in[20];
    const float* a2_v     = (const float*)d_in[21];
    const float* a2_o     = (const float*)d_in[22];
    const float* a2_ob    = (const float*)d_in[23];
    const float* ff_proj_w = (const float*)d_in[24];
    const float* ff_proj_b = (const float*)d_in[25];
    const float* ff_out_w  = (const float*)d_in[26];
    const float* ff_out_b  = (const float*)d_in[27];

    cudaFuncSetAttribute(gemm_f16_kernel,
                         cudaFuncAttributeMaxDynamicSharedMemorySize, GEMM_SMEM);
    cudaFuncSetAttribute(flash_self_kernel,
                         cudaFuncAttributeMaxDynamicSharedMemorySize, FS_TOTAL_H * 2);
    cudaFuncSetAttribute(flash_cross_kernel,
                         cudaFuncAttributeMaxDynamicSharedMemorySize, CF_TOTAL_H * 2);

    float *x, *t, *bFfp, *gnst;
    __half *th, *qkvh, *qh, *kvh, *kv2h, *glh, *xh;
    __half *whFcIn, *whQkv, *whA1o, *whA2q, *whA2o, *whKv2, *whFfp, *whFfo, *whFco;
    cudaGetSymbolAddress((void**)&x,    g_x);
    cudaGetSymbolAddress((void**)&t,    g_t);
    cudaGetSymbolAddress((void**)&bFfp, g_bFfp);
    cudaGetSymbolAddress((void**)&gnst, g_gnstats);
    cudaGetSymbolAddress((void**)&th,   g_th);
    cudaGetSymbolAddress((void**)&qkvh, g_qkvh);
    cudaGetSymbolAddress((void**)&qh,   g_qh);
    cudaGetSymbolAddress((void**)&kvh,  g_kvh);
    cudaGetSymbolAddress((void**)&kv2h, g_kv2h);
    cudaGetSymbolAddress((void**)&glh,  g_glh);
    cudaGetSymbolAddress((void**)&xh,   g_xh);
    cudaGetSymbolAddress((void**)&whFcIn, g_whFcIn);
    cudaGetSymbolAddress((void**)&whQkv,  g_whQkv);
    cudaGetSymbolAddress((void**)&whA1o,  g_whA1o);
    cudaGetSymbolAddress((void**)&whA2q,  g_whA2q);
    cudaGetSymbolAddress((void**)&whA2o,  g_whA2o);
    cudaGetSymbolAddress((void**)&whKv2,  g_whKv2);
    cudaGetSymbolAddress((void**)&whFfp,  g_whFfp);
    cudaGetSymbolAddress((void**)&whFfo,  g_whFfo);
    cudaGetSymbolAddress((void**)&whFco,  g_whFco);

    float* out = (float*)d_out;

    // ---- batched weight transpose+convert (ONE launch) ----
    {
        TrJobs jb;
        const float* srcs[NJOBS] = {fc_in_w, a1_q, a1_k, a1_v, a1_o, a2_q,
                                    a2_o, a2_k, a2_v, ff_proj_w, ff_out_w, fc_out_w};
        __half* dsts[NJOBS] = {whFcIn, whQkv, whQkv + (size_t)512 * 512,
                               whQkv + (size_t)1024 * 512, whA1o, whA2q, whA2o,
                               whKv2, whKv2 + (size_t)512 * 1024,
                               whFfp, whFfo, whFco};
        int Rs[NJOBS] = {512, 512, 512, 512, 512, 512, 512, 1024, 1024, 512, 2048, 512};
        int Cs[NJOBS] = {512, 512, 512, 512, 512, 512, 512, 512, 512, 4096, 512, 512};
        int Il[NJOBS] = {0, 0, 0, 0, 0, 0, 0, 0, 0, 1, 0, 0};
        int acc = 0;
        for (int i = 0; i < NJOBS; i++) {
            jb.src[i] = srcs[i]; jb.dst[i] = dsts[i];
            jb.R[i] = Rs[i]; jb.C[i] = Cs[i]; jb.ileave[i] = Il[i];
            jb.tstart[i] = acc;
            acc += (Rs[i] / 32) * (Cs[i] / 32);
        }
        jb.tstart[NJOBS] = acc;
        trcvt_all_kernel<<<acc, dim3(32, 8)>>>(jb);
    }
    cvt_kernel<<<(BATCH * KVLEN * 1024 + 255) / 256, 256>>>(
        in_kv, kvh, BATCH * KVLEN * 1024);
    bias_ileave_kernel<<<8, 256>>>(ff_proj_b, bFfp);

    // 1. GroupNorm: stats then tiled normalize+transpose -> th (half)
    gn_stats_kernel<<<BATCH * 32, 256>>>(in_q, gnst);
    {
        dim3 grid(SPATIAL / 32, DIMC / 32, BATCH);
        gn_write_kernel<<<grid, dim3(32, 8)>>>(in_q, gnst, gn_g, gn_b, th);
    }

    // 2. x = th @ fc_in + b (fp32)
    gemm(th, 512, whFcIn, 512, x, nullptr, 512, nullptr, 0, fc_in_b,
         NTOK, 512, 512);

    // ---- self attention ----
    layernorm_kernel<<<NTOK / 8, 256>>>(x, ln2_g, ln2_b, th, NTOK);
    gemm(th, 512, whQkv, 512, nullptr, qkvh, 1536, nullptr, 0, nullptr,
         NTOK, 1536, 512);
    {
        dim3 grid(8, 64);
        flash_self_kernel<<<grid, 256, FS_TOTAL_H * 2>>>(qkvh, th);
    }
    gemm(th, 512, whA1o, 512, x, nullptr, 512, x, 512, a1_ob,
         NTOK, 512, 512);

    // ---- cross attention ----
    layernorm_kernel<<<NTOK / 8, 256>>>(x, ln3_g, ln3_b, th, NTOK);
    gemm(th, 512, whA2q, 512, nullptr, qh, 512, nullptr, 0, nullptr,
         NTOK, 512, 512);
    gemm(kvh, 1024, whKv2, 1024, nullptr, kv2h, 1024, nullptr, 0, nullptr,
         BATCH * KVLEN, 1024, 1024);
    {
        dim3 grid(8, 64);
        flash_cross_kernel<<<grid, 256, CF_TOTAL_H * 2>>>(qh, kv2h, th);
    }
    gemm(th, 512, whA2o, 512, x, nullptr, 512, x, 512, a2_ob,
         NTOK, 512, 512);

    // ---- feed-forward (GEGLU, single interleaved GEMM) ----
    layernorm_kernel<<<NTOK / 8, 256>>>(x, ln4_g, ln4_b, th, NTOK);
    gemm(th, 512, whFfp, 512, nullptr, glh, 2048, nullptr, 0, bFfp,
         NTOK, 4096, 512, 3);
    gemm(glh, 2048, whFfo, 2048, x, xh, 512, x, 512, ff_out_b,
         NTOK, 512, 2048);

    // ---- output projection ----
    gemm(xh, 512, whFco, 512, t, nullptr, 512, nullptr, 0, fc_out_b,
         NTOK, 512, 512);

    // ---- tiled transpose + residual ----
    {
        dim3 grid(SPATIAL / 32, DIMC / 32, BATCH);
        output_kernel<<<grid, dim3(32, 8)>>>(t, in_q, out);
    }
}

// round 14
// speedup vs baseline: 2.0145x; 1.0058x over previous
#include <cuda_runtime.h>
#include <cuda_fp16.h>
#include <cstdint>
#include <math.h>

// ---------------------------------------------------------------------------
// Problem constants
// ---------------------------------------------------------------------------
#define BATCH   8
#define DIMC    512
#define SPATIAL 1024
#define NTOK    (BATCH*SPATIAL)  // 8192
#define HEADS   8
#define HDIM    64
#define KVLEN   77
#define KVDIM   1024

// ---------------------------------------------------------------------------
// Scratch buffers
// ---------------------------------------------------------------------------
__device__ float  g_x  [(size_t)NTOK * DIMC];           // fp32 residual stream
__device__ float  g_bFfp[4096];                         // interleaved ffp bias
__device__ float  g_gnstats[BATCH * 32 * 2];            // groupnorm mu/inv
__device__ __half g_th  [(size_t)NTOK * DIMC];
__device__ __half g_qkvh[(size_t)NTOK * 1536];
__device__ __half g_qh  [(size_t)NTOK * DIMC];
__device__ __half g_kvh [(size_t)(BATCH*KVLEN) * 1024];
__device__ __half g_kv2h[(size_t)(BATCH*KVLEN) * 1024];
__device__ __half g_glh [(size_t)NTOK * 2048];
__device__ __half g_xh  [(size_t)NTOK * DIMC];
// half transposed weights [N, K]
__device__ __half g_whFcIn[(size_t)512 * 512];
__device__ __half g_whQkv [(size_t)1536 * 512];
__device__ __half g_whA1o [(size_t)512 * 512];
__device__ __half g_whA2q [(size_t)512 * 512];
__device__ __half g_whA2o [(size_t)512 * 512];
__device__ __half g_whKv2 [(size_t)1024 * 1024];
__device__ __half g_whFfp [(size_t)4096 * 512];         // a/gate interleaved rows
__device__ __half g_whFfo [(size_t)512 * 2048];
__device__ __half g_whFco [(size_t)512 * 512];

// ---------------------------------------------------------------------------
// Helpers
// ---------------------------------------------------------------------------
__device__ __forceinline__ float warpSum(float v) {
    #pragma unroll
    for (int o = 16; o > 0; o >>= 1) v += __shfl_xor_sync(0xffffffffu, v, o);
    return v;
}
__device__ __forceinline__ void mma_f16(float* d, const uint32_t* a, const uint32_t* b) {
    asm volatile(
        "mma.sync.aligned.m16n8k16.row.col.f32.f16.f16.f32 "
        "{%0,%1,%2,%3}, {%4,%5,%6,%7}, {%8,%9}, {%0,%1,%2,%3};"
        : "+f"(d[0]), "+f"(d[1]), "+f"(d[2]), "+f"(d[3])
        : "r"(a[0]), "r"(a[1]), "r"(a[2]), "r"(a[3]), "r"(b[0]), "r"(b[1]));
}
__device__ __forceinline__ void ldsm4(uint32_t& r0, uint32_t& r1,
                                      uint32_t& r2, uint32_t& r3, uint32_t addr) {
    asm volatile("ldmatrix.sync.aligned.m8n8.x4.shared.b16 {%0,%1,%2,%3}, [%4];"
                 : "=r"(r0), "=r"(r1), "=r"(r2), "=r"(r3) : "r"(addr));
}
__device__ __forceinline__ void cp_async16(uint32_t dst, const void* src, int bytes) {
    asm volatile("cp.async.cg.shared.global [%0], [%1], 16, %2;\n"
                 :: "r"(dst), "l"(src), "r"(bytes));
}
__device__ __forceinline__ void cp_commit() { asm volatile("cp.async.commit_group;\n"); }
__device__ __forceinline__ void cp_wait1()  { asm volatile("cp.async.wait_group 1;\n"); }
__device__ __forceinline__ void cp_wait0()  { asm volatile("cp.async.wait_group 0;\n"); }
__device__ __forceinline__ float gelu_f(float v) {
    return 0.5f * v * (1.f + erff(v * 0.70710678118654752f));
}

// ---------------------------------------------------------------------------
// GroupNorm stats: one block per (batch, group). Coalesced read only.
// ---------------------------------------------------------------------------
__global__ void gn_stats_kernel(const float* __restrict__ qin,
                                float* __restrict__ stats) {
    const int blk = blockIdx.x;
    const float* base = qin + (size_t)blk * 16 * SPATIAL;

    float s = 0.f, s2 = 0.f;
    for (int i = threadIdx.x; i < 16 * SPATIAL; i += 256) {
        float v = base[i];
        s += v; s2 += v * v;
    }
    __shared__ float red[2][8];
    s = warpSum(s); s2 = warpSum(s2);
    int wid = threadIdx.x >> 5, lid = threadIdx.x & 31;
    if (lid == 0) { red[0][wid] = s; red[1][wid] = s2; }
    __syncthreads();
    if (threadIdx.x == 0) {
        float a = 0.f, c = 0.f;
        #pragma unroll
        for (int i = 0; i < 8; i++) { a += red[0][i]; c += red[1][i]; }
        const float mu  = a * (1.f / 16384.f);
        const float var = c * (1.f / 16384.f) - mu * mu;
        stats[blk * 2]     = mu;
        stats[blk * 2 + 1] = rsqrtf(var + 1e-6f);
    }
}

// ---------------------------------------------------------------------------
// GroupNorm normalize + transpose to token-major (32x32 tiles, coalesced).
// ---------------------------------------------------------------------------
__global__ void gn_write_kernel(const float* __restrict__ qin,
                                const float* __restrict__ stats,
                                const float* __restrict__ gamma,
                                const float* __restrict__ beta,
                                __half* __restrict__ out) {
    __shared__ float tile[32][33];
    const int b  = blockIdx.z;
    const int c0 = blockIdx.y * 32;
    const int s0 = blockIdx.x * 32;
    const int x = threadIdx.x, y = threadIdx.y;

    #pragma unroll
    for (int i = 0; i < 32; i += 8)
        tile[y + i][x] = qin[((size_t)(b * DIMC + c0 + y + i)) * SPATIAL + s0 + x];
    __syncthreads();

    const int c = c0 + x;
    const int sb = (b * 32 + (c >> 4)) * 2;
    const float mu  = stats[sb];
    const float inv = stats[sb + 1];
    const float gm = gamma[c], bt = beta[c];
    #pragma unroll
    for (int i = 0; i < 32; i += 8) {
        float v = (tile[x][y + i] - mu) * inv * gm + bt;
        out[((size_t)(b * SPATIAL + s0 + y + i)) * DIMC + c] = __float2half(v);
    }
}

// ---------------------------------------------------------------------------
// LayerNorm (fp32 in, half out). One warp per 512-dim row.
// ---------------------------------------------------------------------------
__global__ void layernorm_kernel(const float* __restrict__ x,
                                 const float* __restrict__ gamma,
                                 const float* __restrict__ beta,
                                 __half* __restrict__ out, int rows) {
    int row = blockIdx.x * 8 + (threadIdx.x >> 5);
    if (row >= rows) return;
    int lid = threadIdx.x & 31;
    const float4* xr = (const float4*)(x + (size_t)row * DIMC);

    float4 vals[4];
    float s = 0.f, s2 = 0.f;
    #pragma unroll
    for (int i = 0; i < 4; i++) {
        float4 v = xr[lid + 32 * i];
        vals[i] = v;
        s  += v.x + v.y + v.z + v.w;
        s2 += v.x*v.x + v.y*v.y + v.z*v.z + v.w*v.w;
    }
    s = warpSum(s); s2 = warpSum(s2);
    const float mu  = s * (1.f / 512.f);
    const float inv = rsqrtf(s2 * (1.f / 512.f) - mu * mu + 1e-5f);

    __half2* orow = (__half2*)(out + (size_t)row * DIMC);
    const float4* g4 = (const float4*)gamma;
    const float4* b4 = (const float4*)beta;
    #pragma unroll
    for (int i = 0; i < 4; i++) {
        int idx = lid + 32 * i;
        float4 v = vals[i], g = g4[idx], b = b4[idx];
        float ox = (v.x - mu) * inv * g.x + b.x;
        float oy = (v.y - mu) * inv * g.y + b.y;
        float oz = (v.z - mu) * inv * g.z + b.z;
        float ow = (v.w - mu) * inv * g.w + b.w;
        orow[idx * 2]     = __floats2half2_rn(ox, oy);
        orow[idx * 2 + 1] = __floats2half2_rn(oz, ow);
    }
}

// ---------------------------------------------------------------------------
// Batched transpose + f32->f16 (12 weights, ONE launch).
// ---------------------------------------------------------------------------
#define NJOBS 12
struct TrJobs {
    const float* src[NJOBS];
    __half*      dst[NJOBS];
    int R[NJOBS], C[NJOBS], ileave[NJOBS];
    int tstart[NJOBS + 1];
};

__global__ void trcvt_all_kernel(TrJobs jobs) {
    __shared__ float tile[32][33];
    const int flat = blockIdx.x;
    int j = 0;
    #pragma unroll
    for (int i = 0; i < NJOBS; i++)
        if (flat >= jobs.tstart[i + 1]) j = i + 1;
    const int lt = flat - jobs.tstart[j];
    const int C = jobs.C[j], R = jobs.R[j];
    const int ctiles = C >> 5;
    const int c0 = (lt % ctiles) * 32;
    const int r0 = (lt / ctiles) * 32;
    const float* src = jobs.src[j];
    __half* dst = jobs.dst[j];
    const int il = jobs.ileave[j];
    const int halfC = C >> 1;

    int x = threadIdx.x, y = threadIdx.y;
    #pragma unroll
    for (int i = 0; i < 32; i += 8)
        tile[y + i][x] = src[(size_t)(r0 + y + i) * C + c0 + x];
    __syncthreads();
    #pragma unroll
    for (int i = 0; i < 32; i += 8) {
        int d = c0 + y + i;
        if (il) d = (d < halfC) ? 2 * d : 2 * (d - halfC) + 1;
        dst[(size_t)d * R + r0 + x] = __float2half(tile[x][y + i]);
    }
}

// f32 -> f16 linear convert
__global__ void cvt_kernel(const float* __restrict__ src,
                           __half* __restrict__ dst, int n) {
    int i = blockIdx.x * 256 + threadIdx.x;
    if (i < n) dst[i] = __float2half(src[i]);
}

// interleave ffp bias
__global__ void bias_ileave_kernel(const float* __restrict__ b,
                                   float* __restrict__ dst) {
    int j = blockIdx.x * 256 + threadIdx.x;
    if (j < 2048) {
        dst[2 * j]     = b[j];
        dst[2 * j + 1] = b[2048 + j];
    }
}

// ===========================================================================
// Fused flash self-attention, fp16 operands, fp32 accum.
// ===========================================================================
#define SCL 0.125f
#define FH 72
#define PH 136
#define FS_SQ   0
#define FS_SK   (128*FH)
#define FS_SVT  (FS_SK + 128*FH)
#define FS_SP   (FS_SVT + 64*PH)
#define FS_TOTAL_H (FS_SP + 128*PH)

__global__ void __launch_bounds__(256) flash_self_kernel(
    const __half* __restrict__ qkv, __half* __restrict__ outp) {
    extern __shared__ __half smh[];
    __half* sQ  = smh + FS_SQ;
    __half* sK  = smh + FS_SK;
    __half* sVt = smh + FS_SVT;
    __half* sP  = smh + FS_SP;

    const int b  = blockIdx.y >> 3;
    const int h  = blockIdx.y & 7;
    const int q0 = blockIdx.x * 128;
    const int tid = threadIdx.x;
    const int warp = tid >> 5;
    const int lane = tid & 31;
    const int g  = lane >> 2;
    const int tg = lane & 3;
    const int wm = warp * 16;

    const uint32_t smb = (uint32_t)__cvta_generic_to_shared(smh);
    const uint32_t lr = lane & 15;
    const uint32_t lh = (lane >> 4) * 8;

    for (int i = tid; i < 1024; i += 256) {
        int row = i >> 3;
        int c8  = (i & 7) * 8;
        *(uint4*)(sQ + row * FH + c8) = *(const uint4*)(qkv +
            (size_t)(b * 1024 + q0 + row) * 1536 + h * 64 + c8);
    }
    __syncthreads();

    uint32_t qf[4][4];
    {
        const uint32_t qbase = smb + (uint32_t)(FS_SQ + (wm + lr) * FH + lh) * 2;
        #pragma unroll
        for (int kc = 0; kc < 4; kc++)
            ldsm4(qf[kc][0], qf[kc][1], qf[kc][2], qf[kc][3], qbase + kc * 32);
    }

    float m_[2] = {-1e30f, -1e30f};
    float l_[2] = {0.f, 0.f};
    float acco[8][4];
    #pragma unroll
    for (int i = 0; i < 8; i++)
        #pragma unroll
        for (int r = 0; r < 4; r++) acco[i][r] = 0.f;

    const uint32_t kbase = smb + (uint32_t)(FS_SK + lr * FH + lh) * 2;
    const uint32_t pbase = smb + (uint32_t)(FS_SP + (wm + lr) * PH + lh) * 2;
    const uint32_t vbase = smb + (uint32_t)(FS_SVT + lr * PH + lh) * 2;

    for (int j = 0; j < 8; j++) {
        for (int i = tid; i < 1024; i += 256) {
            int row = i >> 3;
            int c8  = (i & 7) * 8;
            const __half* base = qkv + (size_t)(b * 1024 + j * 128 + row) * 1536 + h * 64;
            *(uint4*)(sK + row * FH + c8) = *(const uint4*)(base + 512 + c8);
            uint4 vv = *(const uint4*)(base + 1024 + c8);
            const __half* hv = (const __half*)&vv;
            #pragma unroll
            for (int q = 0; q < 8; q++) sVt[(c8 + q) * PH + row] = hv[q];
        }
        __syncthreads();

        float accs[16][4];
        #pragma unroll
        for (int nt = 0; nt < 16; nt++)
            #pragma unroll
            for (int r = 0; r < 4; r++) accs[nt][r] = 0.f;

        #pragma unroll
        for (int kc = 0; kc < 4; kc++) {
            const uint32_t ka = kbase + kc * 32;
            #pragma unroll
            for (int p = 0; p < 8; p++) {
                uint32_t b0, b1, b2, b3;
                ldsm4(b0, b1, b2, b3, ka + (uint32_t)(p * 16 * FH) * 2);
                uint32_t bf0[2] = {b0, b2};
                uint32_t bf1[2] = {b1, b3};
                mma_f16(accs[2 * p],     qf[kc], bf0);
                mma_f16(accs[2 * p + 1], qf[kc], bf1);
            }
        }

        float mx0 = -1e30f, mx1 = -1e30f;
        #pragma unroll
        for (int nt = 0; nt < 16; nt++) {
            mx0 = fmaxf(mx0, fmaxf(accs[nt][0], accs[nt][1]));
            mx1 = fmaxf(mx1, fmaxf(accs[nt][2], accs[nt][3]));
        }
        mx0 = fmaxf(mx0, __shfl_xor_sync(0xffffffffu, mx0, 1));
        mx0 = fmaxf(mx0, __shfl_xor_sync(0xffffffffu, mx0, 2));
        mx1 = fmaxf(mx1, __shfl_xor_sync(0xffffffffu, mx1, 1));
        mx1 = fmaxf(mx1, __shfl_xor_sync(0xffffffffu, mx1, 2));
        const float mn0 = fmaxf(m_[0], mx0);
        const float mn1 = fmaxf(m_[1], mx1);
        const float c0 = __expf((m_[0] - mn0) * SCL);
        const float c1 = __expf((m_[1] - mn1) * SCL);
        l_[0] *= c0; l_[1] *= c1;
        #pragma unroll
        for (int nt = 0; nt < 8; nt++) {
            acco[nt][0] *= c0; acco[nt][1] *= c0;
            acco[nt][2] *= c1; acco[nt][3] *= c1;
        }
        float rs0 = 0.f, rs1 = 0.f;
        __half* p0 = sP + (wm + g) * PH + 2 * tg;
        __half* p1 = sP + (wm + g + 8) * PH + 2 * tg;
        #pragma unroll
        for (int nt = 0; nt < 16; nt++) {
            const float e0 = __expf((accs[nt][0] - mn0) * SCL);
            const float e1 = __expf((accs[nt][1] - mn0) * SCL);
            const float e2 = __expf((accs[nt][2] - mn1) * SCL);
            const float e3 = __expf((accs[nt][3] - mn1) * SCL);
            rs0 += e0 + e1; rs1 += e2 + e3;
            *(__half2*)(p0 + nt * 8) = __floats2half2_rn(e0, e1);
            *(__half2*)(p1 + nt * 8) = __floats2half2_rn(e2, e3);
        }
        rs0 += __shfl_xor_sync(0xffffffffu, rs0, 1);
        rs0 += __shfl_xor_sync(0xffffffffu, rs0, 2);
        rs1 += __shfl_xor_sync(0xffffffffu, rs1, 1);
        rs1 += __shfl_xor_sync(0xffffffffu, rs1, 2);
        l_[0] += rs0; l_[1] += rs1;
        m_[0] = mn0; m_[1] = mn1;
        __syncwarp();

        #pragma unroll
        for (int kc = 0; kc < 8; kc++) {
            uint32_t af[4];
            ldsm4(af[0], af[1], af[2], af[3], pbase + kc * 32);
            const uint32_t va = vbase + kc * 32;
            #pragma unroll
            for (int p = 0; p < 4; p++) {
                uint32_t b0, b1, b2, b3;
                ldsm4(b0, b1, b2, b3, va + (uint32_t)(p * 16 * PH) * 2);
                uint32_t bf0[2] = {b0, b2};
                uint32_t bf1[2] = {b1, b3};
                mma_f16(acco[2 * p],     af, bf0);
                mma_f16(acco[2 * p + 1], af, bf1);
            }
        }
        __syncthreads();
    }

    const float i0 = 1.f / l_[0];
    const float i1 = 1.f / l_[1];
    const int row0 = b * 1024 + q0 + wm + g;
    #pragma unroll
    for (int nt = 0; nt < 8; nt++) {
        const int col = h * 64 + nt * 8 + 2 * tg;
        *(__half2*)(outp + (size_t)row0 * 512 + col) =
            __floats2half2_rn(acco[nt][0] * i0, acco[nt][1] * i0);
        *(__half2*)(outp + (size_t)(row0 + 8) * 512 + col) =
            __floats2half2_rn(acco[nt][2] * i1, acco[nt][3] * i1);
    }
}

// ===========================================================================
// Fused flash cross-attention (kv 77 -> padded 80), fp16.
// ===========================================================================
#define CH 88
#define CF_SQ   0
#define CF_SK   (128*FH)
#define CF_SVT  (CF_SK + 80*FH)
#define CF_SP   (CF_SVT + 64*CH)
#define CF_TOTAL_H (CF_SP + 128*CH)

__global__ void __launch_bounds__(256) flash_cross_kernel(
    const __half* __restrict__ qsrc, const __half* __restrict__ kv2,
    __half* __restrict__ outp) {
    extern __shared__ __half smh[];
    __half* sQ  = smh + CF_SQ;
    __half* sK  = smh + CF_SK;
    __half* sVt = smh + CF_SVT;
    __half* sP  = smh + CF_SP;

    const int b  = blockIdx.y >> 3;
    const int h  = blockIdx.y & 7;
    const int q0 = blockIdx.x * 128;
    const int tid = threadIdx.x;
    const int warp = tid >> 5;
    const int lane = tid & 31;
    const int g  = lane >> 2;
    const int tg = lane & 3;
    const int wm = warp * 16;

    const uint32_t smb = (uint32_t)__cvta_generic_to_shared(smh);
    const uint32_t lr = lane & 15;
    const uint32_t lh = (lane >> 4) * 8;

    for (int i = tid; i < 1024; i += 256) {
        int row = i >> 3;
        int c8  = (i & 7) * 8;
        *(uint4*)(sQ + row * FH + c8) = *(const uint4*)(qsrc +
            (size_t)(b * 1024 + q0 + row) * 512 + h * 64 + c8);
    }
    for (int i = tid; i < 640; i += 256) {
        int row = i >> 3;
        int c8  = (i & 7) * 8;
        uint4 kk = make_uint4(0, 0, 0, 0), vv = make_uint4(0, 0, 0, 0);
        if (row < KVLEN) {
            const __half* base = kv2 + (size_t)(b * KVLEN + row) * 1024 + h * 64;
            kk = *(const uint4*)(base + c8);
            vv = *(const uint4*)(base + 512 + c8);
        }
        *(uint4*)(sK + row * FH + c8) = kk;
        const __half* hv = (const __half*)&vv;
        #pragma unroll
        for (int q = 0; q < 8; q++) sVt[(c8 + q) * CH + row] = hv[q];
    }
    __syncthreads();

    uint32_t qf[4][4];
    {
        const uint32_t qbase = smb + (uint32_t)(CF_SQ + (wm + lr) * FH + lh) * 2;
        #pragma unroll
        for (int kc = 0; kc < 4; kc++)
            ldsm4(qf[kc][0], qf[kc][1], qf[kc][2], qf[kc][3], qbase + kc * 32);
    }

    float accs[10][4];
    #pragma unroll
    for (int nt = 0; nt < 10; nt++)
        #pragma unroll
        for (int r = 0; r < 4; r++) accs[nt][r] = 0.f;
    {
        const uint32_t kbase = smb + (uint32_t)(CF_SK + lr * FH + lh) * 2;
        #pragma unroll
        for (int kc = 0; kc < 4; kc++) {
            const uint32_t ka = kbase + kc * 32;
            #pragma unroll
            for (int p = 0; p < 5; p++) {
                uint32_t b0, b1, b2, b3;
                ldsm4(b0, b1, b2, b3, ka + (uint32_t)(p * 16 * FH) * 2);
                uint32_t bf0[2] = {b0, b2};
                uint32_t bf1[2] = {b1, b3};
                mma_f16(accs[2 * p],     qf[kc], bf0);
                mma_f16(accs[2 * p + 1], qf[kc], bf1);
            }
        }
    }

    #pragma unroll
    for (int nt = 0; nt < 10; nt++) {
        const int col0 = nt * 8 + 2 * tg;
        if (col0 >= KVLEN)     { accs[nt][0] = -1e30f; accs[nt][2] = -1e30f; }
        if (col0 + 1 >= KVLEN) { accs[nt][1] = -1e30f; accs[nt][3] = -1e30f; }
    }
    float mx0 = -1e30f, mx1 = -1e30f;
    #pragma unroll
    for (int nt = 0; nt < 10; nt++) {
        mx0 = fmaxf(mx0, fmaxf(accs[nt][0], accs[nt][1]));
        mx1 = fmaxf(mx1, fmaxf(accs[nt][2], accs[nt][3]));
    }
    mx0 = fmaxf(mx0, __shfl_xor_sync(0xffffffffu, mx0, 1));
    mx0 = fmaxf(mx0, __shfl_xor_sync(0xffffffffu, mx0, 2));
    mx1 = fmaxf(mx1, __shfl_xor_sync(0xffffffffu, mx1, 1));
    mx1 = fmaxf(mx1, __shfl_xor_sync(0xffffffffu, mx1, 2));

    float rs0 = 0.f, rs1 = 0.f;
    __half* p0 = sP + (wm + g) * CH + 2 * tg;
    __half* p1 = sP + (wm + g + 8) * CH + 2 * tg;
    #pragma unroll
    for (int nt = 0; nt < 10; nt++) {
        const float e0 = __expf((accs[nt][0] - mx0) * SCL);
        const float e1 = __expf((accs[nt][1] - mx0) * SCL);
        const float e2 = __expf((accs[nt][2] - mx1) * SCL);
        const float e3 = __expf((accs[nt][3] - mx1) * SCL);
        rs0 += e0 + e1; rs1 += e2 + e3;
        *(__half2*)(p0 + nt * 8) = __floats2half2_rn(e0, e1);
        *(__half2*)(p1 + nt * 8) = __floats2half2_rn(e2, e3);
    }
    rs0 += __shfl_xor_sync(0xffffffffu, rs0, 1);
    rs0 += __shfl_xor_sync(0xffffffffu, rs0, 2);
    rs1 += __shfl_xor_sync(0xffffffffu, rs1, 1);
    rs1 += __shfl_xor_sync(0xffffffffu, rs1, 2);
    __syncwarp();

    float acco[8][4];
    #pragma unroll
    for (int nt = 0; nt < 8; nt++)
        #pragma unroll
        for (int r = 0; r < 4; r++) acco[nt][r] = 0.f;
    {
        const uint32_t pb = smb + (uint32_t)(CF_SP + (wm + lr) * CH + lh) * 2;
        const uint32_t vb = smb + (uint32_t)(CF_SVT + lr * CH + lh) * 2;
        #pragma unroll
        for (int kc = 0; kc < 5; kc++) {
            uint32_t af[4];
            ldsm4(af[0], af[1], af[2], af[3], pb + kc * 32);
            const uint32_t va = vb + kc * 32;
            #pragma unroll
            for (int p = 0; p < 4; p++) {
                uint32_t b0, b1, b2, b3;
                ldsm4(b0, b1, b2, b3, va + (uint32_t)(p * 16 * CH) * 2);
                uint32_t bf0[2] = {b0, b2};
                uint32_t bf1[2] = {b1, b3};
                mma_f16(acco[2 * p],     af, bf0);
                mma_f16(acco[2 * p + 1], af, bf1);
            }
        }
    }

    const float i0 = 1.f / rs0;
    const float i1 = 1.f / rs1;
    const int row0 = b * 1024 + q0 + wm + g;
    #pragma unroll
    for (int nt = 0; nt < 8; nt++) {
        const int col = h * 64 + nt * 8 + 2 * tg;
        *(__half2*)(outp + (size_t)row0 * 512 + col) =
            __floats2half2_rn(acco[nt][0] * i0, acco[nt][1] * i0);
        *(__half2*)(outp + (size_t)(row0 + 8) * 512 + col) =
            __floats2half2_rn(acco[nt][2] * i1, acco[nt][3] * i1);
    }
}

// ===========================================================================
// FP16 tensor-core GEMM: C = A @ Bt^T (+bias)(+epilogue)
//   emode 0: plain (+Res fp32 add)
//   emode 3: GEGLU-paired interleaved a/gate -> Ch, ldc = N/2
//   emode 4: transposed-output: row=channel, col=token; writes
//            Cf[(b*512+row)*1024 + s] = v + Res[same], bias[row].
// ===========================================================================
#define BM 128
#define BN 128
#define BK 32
#define GSTR 40
#define STG_BYTES (2 * 128 * GSTR * 2)
#define GEMM_SMEM (3 * STG_BYTES)

__global__ void __launch_bounds__(256, 2) gemm_f16_kernel(
    const __half* __restrict__ A, int lda,
    const __half* __restrict__ Bt, int ldb,
    float* __restrict__ Cf, __half* __restrict__ Ch, int ldc,
    const float* __restrict__ Res, int ldres,
    const float* __restrict__ bias,
    int M, int K, int emode) {

    extern __shared__ __half smh[];

    const int m0 = blockIdx.y * BM;
    const int n0 = blockIdx.x * BN;
    const int tid = threadIdx.x;
    const int warp = tid >> 5;
    const int lane = tid & 31;
    const int g  = lane >> 2;
    const int tg = lane & 3;
    const int wm = (warp >> 2) * 64;
    const int wn = (warp & 3) * 32;

    const uint32_t smem_u32 = (uint32_t)__cvta_generic_to_shared(smh);
    const int nk = K / BK;

    float acc[4][4][4];
    #pragma unroll
    for (int i = 0; i < 4; i++)
        #pragma unroll
        for (int j = 0; j < 4; j++)
            #pragma unroll
            for (int r = 0; r < 4; r++) acc[i][j][r] = 0.f;

    auto load_stage = [&](int stage, int k0) {
        const uint32_t abase = smem_u32 + (uint32_t)(stage * STG_BYTES);
        #pragma unroll
        for (int i = 0; i < 2; i++) {
            int idx = tid + i * 256;
            int row = idx >> 2;
            int kc  = (idx & 3) * 8;
            int bytes = (m0 + row < M) ? 16 : 0;
            cp_async16(abase + (uint32_t)(row * GSTR + kc) * 2,
                       A + (long long)(m0 + row) * lda + k0 + kc, bytes);
        }
        const uint32_t bbase = abase + (uint32_t)(128 * GSTR * 2);
        #pragma unroll
        for (int i = 0; i < 2; i++) {
            int idx = tid + i * 256;
            int row = idx >> 2;
            int kc  = (idx & 3) * 8;
            cp_async16(bbase + (uint32_t)(row * GSTR + kc) * 2,
                       Bt + (long long)(n0 + row) * ldb + k0 + kc, 16);
        }
        cp_commit();
    };

    const uint32_t lm_off = (uint32_t)((lane & 15) * GSTR + ((lane >> 4) * 8)) * 2;
    const uint32_t a_lm = smem_u32 + (uint32_t)(wm * GSTR) * 2 + lm_off;
    const uint32_t b_lm = smem_u32 + (uint32_t)(128 * GSTR + wn * GSTR) * 2 + lm_off;

    auto compute_stage = [&](int stage) {
        const uint32_t so = (uint32_t)(stage * STG_BYTES);
        #pragma unroll
        for (int ks = 0; ks < 2; ks++) {
            const uint32_t kkb = ks * 32;
            uint32_t afr[4][4];
            #pragma unroll
            for (int mt = 0; mt < 4; mt++)
                ldsm4(afr[mt][0], afr[mt][1], afr[mt][2], afr[mt][3],
                      a_lm + so + (uint32_t)(mt * 16 * GSTR) * 2 + kkb);
            uint32_t bfr[4][2];
            #pragma unroll
            for (int p = 0; p < 2; p++) {
                uint32_t r0, r1, r2, r3;
                ldsm4(r0, r1, r2, r3, b_lm + so + (uint32_t)(p * 16 * GSTR) * 2 + kkb);
                bfr[2 * p][0]     = r0; bfr[2 * p][1]     = r2;
                bfr[2 * p + 1][0] = r1; bfr[2 * p + 1][1] = r3;
            }
            #pragma unroll
            for (int mt = 0; mt < 4; mt++)
                #pragma unroll
                for (int nt = 0; nt < 4; nt++)
                    mma_f16(acc[mt][nt], afr[mt], bfr[nt]);
        }
    };

    load_stage(0, 0);
    if (nk > 1) load_stage(1, BK);
    for (int kt = 0; kt < nk; kt++) {
        if (kt + 1 < nk) cp_wait1(); else cp_wait0();
        __syncthreads();
        if (kt + 2 < nk) load_stage((kt + 2) % 3, (kt + 2) * BK);
        compute_stage(kt % 3);
    }

    // ---- epilogue (vectorized) ----
    const int obatch = n0 >> 10;   // for emode 4: batch of this col tile
    #pragma unroll
    for (int mt = 0; mt < 4; mt++) {
        #pragma unroll
        for (int nt = 0; nt < 4; nt++) {
            const int row0 = m0 + wm + mt * 16 + g;
            const int col0 = n0 + wn + nt * 8 + tg * 2;
            #pragma unroll
            for (int hh = 0; hh < 2; hh++) {
                const int row = row0 + hh * 8;
                if (row >= M) continue;
                float v0 = acc[mt][nt][2 * hh + 0];
                float v1 = acc[mt][nt][2 * hh + 1];
                if (emode == 4) {
                    v0 += bias[row]; v1 += bias[row];
                    const size_t o = ((size_t)(obatch * 512 + row)) * 1024 +
                                     (col0 & 1023);
                    float2 r = *(const float2*)(Res + o);
                    *(float2*)(Cf + o) = make_float2(v0 + r.x, v1 + r.y);
                    continue;
                }
                if (bias) { v0 += bias[col0]; v1 += bias[col0 + 1]; }
                if (emode == 3) {
                    Ch[(long long)row * ldc + (col0 >> 1)] =
                        __float2half(v0 * gelu_f(v1));
                    continue;
                }
                if (Res) {
                    float2 r = *(const float2*)(Res + (long long)row * ldres + col0);
                    v0 += r.x; v1 += r.y;
                }
                if (Cf) *(float2*)(Cf + (long long)row * ldc + col0) =
                            make_float2(v0, v1);
                if (Ch) *(__half2*)(Ch + (long long)row * ldc + col0) =
                            __floats2half2_rn(v0, v1);
            }
        }
    }
}

// ---------------------------------------------------------------------------
// Host side
// ---------------------------------------------------------------------------
static void gemm(const __half* A, int lda, const __half* Bt, int ldb,
                 float* Cf, __half* Ch, int ldc,
                 const float* Res, int ldres,
                 const float* bias, int M, int N, int K, int emode = 0) {
    dim3 grid(N / BN, (M + BM - 1) / BM);
    gemm_f16_kernel<<<grid, 256, GEMM_SMEM>>>(
        A, lda, Bt, ldb, Cf, Ch, ldc, Res, ldres, bias, M, K, emode);
}

extern "C" void kernel_launch(void* const* d_in, const int* in_sizes, int n_in,
                              void* d_out, int out_size) {
    const float* in_q     = (const float*)d_in[0];
    const float* in_kv    = (const float*)d_in[1];
    const float* gn_g     = (const float*)d_in[2];
    const float* gn_b     = (const float*)d_in[3];
    const float* ln2_g    = (const float*)d_in[4];
    const float* ln2_b    = (const float*)d_in[5];
    const float* ln3_g    = (const float*)d_in[6];
    const float* ln3_b    = (const float*)d_in[7];
    const float* ln4_g    = (const float*)d_in[8];
    const float* ln4_b    = (const float*)d_in[9];
    const float* fc_in_w  = (const float*)d_in[10];
    const float* fc_in_b  = (const float*)d_in[11];
    const float* fc_out_w = (const float*)d_in[12];
    const float* fc_out_b = (const float*)d_in[13];
    const float* a1_q     = (const float*)d_in[14];
    const float* a1_k     = (const float*)d_in[15];
    const float* a1_v     = (const float*)d_in[16];
    const float* a1_o     = (const float*)d_in[17];
    const float* a1_ob    = (const float*)d_in[18];
    const float* a2_q     = (const float*)d_in[19];
    const float* a2_k     = (const float*)d_in[20];
    const float* a2_v     = (const float*)d_in[21];
    const float* a2_o     = (const float*)d_in[22];
    const float* a2_ob    = (const float*)d_in[23];
    const float* ff_proj_w = (const float*)d_in[24];
    const float* ff_proj_b = (const float*)d_in[25];
    const float* ff_out_w  = (const float*)d_in[26];
    const float* ff_out_b  = (const float*)d_in[27];

    cudaFuncSetAttribute(gemm_f16_kernel,
                         cudaFuncAttributeMaxDynamicSharedMemorySize, GEMM_SMEM);
    cudaFuncSetAttribute(flash_self_kernel,
                         cudaFuncAttributeMaxDynamicSharedMemorySize, FS_TOTAL_H * 2);
    cudaFuncSetAttribute(flash_cross_kernel,
                         cudaFuncAttributeMaxDynamicSharedMemorySize, CF_TOTAL_H * 2);

    float *x, *bFfp, *gnst;
    __half *th, *qkvh, *qh, *kvh, *kv2h, *glh, *xh;
    __half *whFcIn, *whQkv, *whA1o, *whA2q, *whA2o, *whKv2, *whFfp, *whFfo, *whFco;
    cudaGetSymbolAddress((void**)&x,    g_x);
    cudaGetSymbolAddress((void**)&bFfp, g_bFfp);
    cudaGetSymbolAddress((void**)&gnst, g_gnstats);
    cudaGetSymbolAddress((void**)&th,   g_th);
    cudaGetSymbolAddress((void**)&qkvh, g_qkvh);
    cudaGetSymbolAddress((void**)&qh,   g_qh);
    cudaGetSymbolAddress((void**)&kvh,  g_kvh);
    cudaGetSymbolAddress((void**)&kv2h, g_kv2h);
    cudaGetSymbolAddress((void**)&glh,  g_glh);
    cudaGetSymbolAddress((void**)&xh,   g_xh);
    cudaGetSymbolAddress((void**)&whFcIn, g_whFcIn);
    cudaGetSymbolAddress((void**)&whQkv,  g_whQkv);
    cudaGetSymbolAddress((void**)&whA1o,  g_whA1o);
    cudaGetSymbolAddress((void**)&whA2q,  g_whA2q);
    cudaGetSymbolAddress((void**)&whA2o,  g_whA2o);
    cudaGetSymbolAddress((void**)&whKv2,  g_whKv2);
    cudaGetSymbolAddress((void**)&whFfp,  g_whFfp);
    cudaGetSymbolAddress((void**)&whFfo,  g_whFfo);
    cudaGetSymbolAddress((void**)&whFco,  g_whFco);

    float* out = (float*)d_out;

    // ---- batched weight transpose+convert (ONE launch) ----
    {
        TrJobs jb;
        const float* srcs[NJOBS] = {fc_in_w, a1_q, a1_k, a1_v, a1_o, a2_q,
                                    a2_o, a2_k, a2_v, ff_proj_w, ff_out_w, fc_out_w};
        __half* dsts[NJOBS] = {whFcIn, whQkv, whQkv + (size_t)512 * 512,
                               whQkv + (size_t)1024 * 512, whA1o, whA2q, whA2o,
                               whKv2, whKv2 + (size_t)512 * 1024,
                               whFfp, whFfo, whFco};
        int Rs[NJOBS] = {512, 512, 512, 512, 512, 512, 512, 1024, 1024, 512, 2048, 512};
        int Cs[NJOBS] = {512, 512, 512, 512, 512, 512, 512, 512, 512, 4096, 512, 512};
        int Il[NJOBS] = {0, 0, 0, 0, 0, 0, 0, 0, 0, 1, 0, 0};
        int acc = 0;
        for (int i = 0; i < NJOBS; i++) {
            jb.src[i] = srcs[i]; jb.dst[i] = dsts[i];
            jb.R[i] = Rs[i]; jb.C[i] = Cs[i]; jb.ileave[i] = Il[i];
            jb.tstart[i] = acc;
            acc += (Rs[i] / 32) * (Cs[i] / 32);
        }
        jb.tstart[NJOBS] = acc;
        trcvt_all_kernel<<<acc, dim3(32, 8)>>>(jb);
    }
    cvt_kernel<<<(BATCH * KVLEN * 1024 + 255) / 256, 256>>>(
        in_kv, kvh, BATCH * KVLEN * 1024);
    bias_ileave_kernel<<<8, 256>>>(ff_proj_b, bFfp);

    // 1. GroupNorm: stats then tiled normalize+transpose -> th (half)
    gn_stats_kernel<<<BATCH * 32, 256>>>(in_q, gnst);
    {
        dim3 grid(SPATIAL / 32, DIMC / 32, BATCH);
        gn_write_kernel<<<grid, dim3(32, 8)>>>(in_q, gnst, gn_g, gn_b, th);
    }

    // 2. x = th @ fc_in + b (fp32)
    gemm(th, 512, whFcIn, 512, x, nullptr, 512, nullptr, 0, fc_in_b,
         NTOK, 512, 512);

    // ---- self attention ----
    layernorm_kernel<<<NTOK / 8, 256>>>(x, ln2_g, ln2_b, th, NTOK);
    gemm(th, 512, whQkv, 512, nullptr, qkvh, 1536, nullptr, 0, nullptr,
         NTOK, 1536, 512);
    {
        dim3 grid(8, 64);
        flash_self_kernel<<<grid, 256, FS_TOTAL_H * 2>>>(qkvh, th);
    }
    gemm(th, 512, whA1o, 512, x, nullptr, 512, x, 512, a1_ob,
         NTOK, 512, 512);

    // ---- cross attention ----
    layernorm_kernel<<<NTOK / 8, 256>>>(x, ln3_g, ln3_b, th, NTOK);
    gemm(th, 512, whA2q, 512, nullptr, qh, 512, nullptr, 0, nullptr,
         NTOK, 512, 512);
    gemm(kvh, 1024, whKv2, 1024, nullptr, kv2h, 1024, nullptr, 0, nullptr,
         BATCH * KVLEN, 1024, 1024);
    {
        dim3 grid(8, 64);
        flash_cross_kernel<<<grid, 256, CF_TOTAL_H * 2>>>(qh, kv2h, th);
    }
    gemm(th, 512, whA2o, 512, x, nullptr, 512, x, 512, a2_ob,
         NTOK, 512, 512);

    // ---- feed-forward (GEGLU, single interleaved GEMM) ----
    layernorm_kernel<<<NTOK / 8, 256>>>(x, ln4_g, ln4_b, th, NTOK);
    gemm(th, 512, whFfp, 512, nullptr, glh, 2048, nullptr, 0, bFfp,
         NTOK, 4096, 512, 3);
    // x += glh @ Wout + b; only half mirror xh needed downstream
    gemm(glh, 2048, whFfo, 2048, nullptr, xh, 512, x, 512, ff_out_b,
         NTOK, 512, 2048);

    // ---- output projection, transposed: out[b,c,s] = fco + qin ----
    // A = whFco [c, k], Bt = xh [token, k]  ->  C'[c, token]
    gemm(whFco, 512, xh, 512, out, nullptr, 0, in_q, 0, fc_out_b,
         512, NTOK, 512, 4);
}

// round 15
// speedup vs baseline: 2.1690x; 1.0767x over previous
#include <cuda_runtime.h>
#include <cuda_fp16.h>
#include <cstdint>
#include <math.h>

// ---------------------------------------------------------------------------
// Problem constants
// ---------------------------------------------------------------------------
#define BATCH   8
#define DIMC    512
#define SPATIAL 1024
#define NTOK    (BATCH*SPATIAL)  // 8192
#define HEADS   8
#define HDIM    64
#define KVLEN   77
#define KVDIM   1024

// ---------------------------------------------------------------------------
// Scratch buffers
// ---------------------------------------------------------------------------
__device__ float  g_x  [(size_t)NTOK * DIMC];           // fp32 residual stream
__device__ float  g_bFfp[4096];                         // interleaved ffp bias
__device__ float  g_gnstats[BATCH * 32 * 2];            // groupnorm mu/inv
__device__ __half g_th  [(size_t)NTOK * DIMC];
__device__ __half g_qkvh[(size_t)NTOK * 1536];
__device__ __half g_qh  [(size_t)NTOK * DIMC];
__device__ __half g_kvh [(size_t)(BATCH*KVLEN) * 1024];
__device__ __half g_kv2h[(size_t)(BATCH*KVLEN) * 1024];
__device__ __half g_glh [(size_t)NTOK * 2048];
__device__ __half g_xh  [(size_t)NTOK * DIMC];
// half transposed weights [N, K]
__device__ __half g_whFcIn[(size_t)512 * 512];
__device__ __half g_whQkv [(size_t)1536 * 512];
__device__ __half g_whA1o [(size_t)512 * 512];
__device__ __half g_whA2q [(size_t)512 * 512];
__device__ __half g_whA2o [(size_t)512 * 512];
__device__ __half g_whKv2 [(size_t)1024 * 1024];
__device__ __half g_whFfp [(size_t)4096 * 512];         // a/gate interleaved rows
__device__ __half g_whFfo [(size_t)512 * 2048];
__device__ __half g_whFco [(size_t)512 * 512];

// ---------------------------------------------------------------------------
// Helpers
// ---------------------------------------------------------------------------
__device__ __forceinline__ float warpSum(float v) {
    #pragma unroll
    for (int o = 16; o > 0; o >>= 1) v += __shfl_xor_sync(0xffffffffu, v, o);
    return v;
}
__device__ __forceinline__ void mma_f16(float* d, const uint32_t* a, const uint32_t* b) {
    asm volatile(
        "mma.sync.aligned.m16n8k16.row.col.f32.f16.f16.f32 "
        "{%0,%1,%2,%3}, {%4,%5,%6,%7}, {%8,%9}, {%0,%1,%2,%3};"
        : "+f"(d[0]), "+f"(d[1]), "+f"(d[2]), "+f"(d[3])
        : "r"(a[0]), "r"(a[1]), "r"(a[2]), "r"(a[3]), "r"(b[0]), "r"(b[1]));
}
__device__ __forceinline__ void ldsm4(uint32_t& r0, uint32_t& r1,
                                      uint32_t& r2, uint32_t& r3, uint32_t addr) {
    asm volatile("ldmatrix.sync.aligned.m8n8.x4.shared.b16 {%0,%1,%2,%3}, [%4];"
                 : "=r"(r0), "=r"(r1), "=r"(r2), "=r"(r3) : "r"(addr));
}
__device__ __forceinline__ void ldsm4t(uint32_t& r0, uint32_t& r1,
                                       uint32_t& r2, uint32_t& r3, uint32_t addr) {
    asm volatile("ldmatrix.sync.aligned.m8n8.x4.trans.shared.b16 {%0,%1,%2,%3}, [%4];"
                 : "=r"(r0), "=r"(r1), "=r"(r2), "=r"(r3) : "r"(addr));
}
__device__ __forceinline__ void cp_async16(uint32_t dst, const void* src, int bytes) {
    asm volatile("cp.async.cg.shared.global [%0], [%1], 16, %2;\n"
                 :: "r"(dst), "l"(src), "r"(bytes));
}
__device__ __forceinline__ void cp_commit() { asm volatile("cp.async.commit_group;\n"); }
__device__ __forceinline__ void cp_wait1()  { asm volatile("cp.async.wait_group 1;\n"); }
__device__ __forceinline__ void cp_wait0()  { asm volatile("cp.async.wait_group 0;\n"); }
__device__ __forceinline__ float gelu_f(float v) {
    return 0.5f * v * (1.f + erff(v * 0.70710678118654752f));
}

// ---------------------------------------------------------------------------
// GroupNorm stats: one block per (batch, group). Coalesced read only.
// ---------------------------------------------------------------------------
__global__ void gn_stats_kernel(const float* __restrict__ qin,
                                float* __restrict__ stats) {
    const int blk = blockIdx.x;
    const float* base = qin + (size_t)blk * 16 * SPATIAL;

    float s = 0.f, s2 = 0.f;
    for (int i = threadIdx.x; i < 16 * SPATIAL; i += 256) {
        float v = base[i];
        s += v; s2 += v * v;
    }
    __shared__ float red[2][8];
    s = warpSum(s); s2 = warpSum(s2);
    int wid = threadIdx.x >> 5, lid = threadIdx.x & 31;
    if (lid == 0) { red[0][wid] = s; red[1][wid] = s2; }
    __syncthreads();
    if (threadIdx.x == 0) {
        float a = 0.f, c = 0.f;
        #pragma unroll
        for (int i = 0; i < 8; i++) { a += red[0][i]; c += red[1][i]; }
        const float mu  = a * (1.f / 16384.f);
        const float var = c * (1.f / 16384.f) - mu * mu;
        stats[blk * 2]     = mu;
        stats[blk * 2 + 1] = rsqrtf(var + 1e-6f);
    }
}

// ---------------------------------------------------------------------------
// GroupNorm normalize + transpose to token-major (32x32 tiles, coalesced).
// ---------------------------------------------------------------------------
__global__ void gn_write_kernel(const float* __restrict__ qin,
                                const float* __restrict__ stats,
                                const float* __restrict__ gamma,
                                const float* __restrict__ beta,
                                __half* __restrict__ out) {
    __shared__ float tile[32][33];
    const int b  = blockIdx.z;
    const int c0 = blockIdx.y * 32;
    const int s0 = blockIdx.x * 32;
    const int x = threadIdx.x, y = threadIdx.y;

    #pragma unroll
    for (int i = 0; i < 32; i += 8)
        tile[y + i][x] = qin[((size_t)(b * DIMC + c0 + y + i)) * SPATIAL + s0 + x];
    __syncthreads();

    const int c = c0 + x;
    const int sb = (b * 32 + (c >> 4)) * 2;
    const float mu  = stats[sb];
    const float inv = stats[sb + 1];
    const float gm = gamma[c], bt = beta[c];
    #pragma unroll
    for (int i = 0; i < 32; i += 8) {
        float v = (tile[x][y + i] - mu) * inv * gm + bt;
        out[((size_t)(b * SPATIAL + s0 + y + i)) * DIMC + c] = __float2half(v);
    }
}

// ---------------------------------------------------------------------------
// LayerNorm (fp32 in, half out). One warp per 512-dim row.
// ---------------------------------------------------------------------------
__global__ void layernorm_kernel(const float* __restrict__ x,
                                 const float* __restrict__ gamma,
                                 const float* __restrict__ beta,
                                 __half* __restrict__ out, int rows) {
    int row = blockIdx.x * 8 + (threadIdx.x >> 5);
    if (row >= rows) return;
    int lid = threadIdx.x & 31;
    const float4* xr = (const float4*)(x + (size_t)row * DIMC);

    float4 vals[4];
    float s = 0.f, s2 = 0.f;
    #pragma unroll
    for (int i = 0; i < 4; i++) {
        float4 v = xr[lid + 32 * i];
        vals[i] = v;
        s  += v.x + v.y + v.z + v.w;
        s2 += v.x*v.x + v.y*v.y + v.z*v.z + v.w*v.w;
    }
    s = warpSum(s); s2 = warpSum(s2);
    const float mu  = s * (1.f / 512.f);
    const float inv = rsqrtf(s2 * (1.f / 512.f) - mu * mu + 1e-5f);

    __half2* orow = (__half2*)(out + (size_t)row * DIMC);
    const float4* g4 = (const float4*)gamma;
    const float4* b4 = (const float4*)beta;
    #pragma unroll
    for (int i = 0; i < 4; i++) {
        int idx = lid + 32 * i;
        float4 v = vals[i], g = g4[idx], b = b4[idx];
        float ox = (v.x - mu) * inv * g.x + b.x;
        float oy = (v.y - mu) * inv * g.y + b.y;
        float oz = (v.z - mu) * inv * g.z + b.z;
        float ow = (v.w - mu) * inv * g.w + b.w;
        orow[idx * 2]     = __floats2half2_rn(ox, oy);
        orow[idx * 2 + 1] = __floats2half2_rn(oz, ow);
    }
}

// ---------------------------------------------------------------------------
// Batched transpose + f32->f16 (12 weights, ONE launch).
// ---------------------------------------------------------------------------
#define NJOBS 12
struct TrJobs {
    const float* src[NJOBS];
    __half*      dst[NJOBS];
    int R[NJOBS], C[NJOBS], ileave[NJOBS];
    int tstart[NJOBS + 1];
};

__global__ void trcvt_all_kernel(TrJobs jobs) {
    __shared__ float tile[32][33];
    const int flat = blockIdx.x;
    int j = 0;
    #pragma unroll
    for (int i = 0; i < NJOBS; i++)
        if (flat >= jobs.tstart[i + 1]) j = i + 1;
    const int lt = flat - jobs.tstart[j];
    const int C = jobs.C[j], R = jobs.R[j];
    const int ctiles = C >> 5;
    const int c0 = (lt % ctiles) * 32;
    const int r0 = (lt / ctiles) * 32;
    const float* src = jobs.src[j];
    __half* dst = jobs.dst[j];
    const int il = jobs.ileave[j];
    const int halfC = C >> 1;

    int x = threadIdx.x, y = threadIdx.y;
    #pragma unroll
    for (int i = 0; i < 32; i += 8)
        tile[y + i][x] = src[(size_t)(r0 + y + i) * C + c0 + x];
    __syncthreads();
    #pragma unroll
    for (int i = 0; i < 32; i += 8) {
        int d = c0 + y + i;
        if (il) d = (d < halfC) ? 2 * d : 2 * (d - halfC) + 1;
        dst[(size_t)d * R + r0 + x] = __float2half(tile[x][y + i]);
    }
}

// f32 -> f16 linear convert
__global__ void cvt_kernel(const float* __restrict__ src,
                           __half* __restrict__ dst, int n) {
    int i = blockIdx.x * 256 + threadIdx.x;
    if (i < n) dst[i] = __float2half(src[i]);
}

// interleave ffp bias
__global__ void bias_ileave_kernel(const float* __restrict__ b,
                                   float* __restrict__ dst) {
    int j = blockIdx.x * 256 + threadIdx.x;
    if (j < 2048) {
        dst[2 * j]     = b[j];
        dst[2 * j + 1] = b[2048 + j];
    }
}

// ===========================================================================
// Fused flash self-attention, fp16 operands, fp32 accum.
// V stored raw [kvpos][d]; PV B-fragments via ldmatrix.trans.
// cp.async K/V loads. smem ~90KB -> 2 CTAs/SM.
// ===========================================================================
#define SCL 0.125f
#define FH 72
#define PH 136
#define FS_SQ   0
#define FS_SK   (128*FH)
#define FS_SV   (FS_SK + 128*FH)
#define FS_SP   (FS_SV + 128*FH)
#define FS_TOTAL_H (FS_SP + 128*PH)   // 45056 halves = 90112 B

__global__ void __launch_bounds__(256) flash_self_kernel(
    const __half* __restrict__ qkv, __half* __restrict__ outp) {
    extern __shared__ __half smh[];
    __half* sQ = smh + FS_SQ;
    __half* sP = smh + FS_SP;

    const int b  = blockIdx.y >> 3;
    const int h  = blockIdx.y & 7;
    const int q0 = blockIdx.x * 128;
    const int tid = threadIdx.x;
    const int warp = tid >> 5;
    const int lane = tid & 31;
    const int g  = lane >> 2;
    const int tg = lane & 3;
    const int wm = warp * 16;

    const uint32_t smb = (uint32_t)__cvta_generic_to_shared(smh);
    const uint32_t lr = lane & 15;
    const uint32_t lh = (lane >> 4) * 8;

    // ---- load Q tile via cp.async ----
    for (int i = tid; i < 1024; i += 256) {
        int row = i >> 3;
        int c8  = (i & 7) * 8;
        cp_async16(smb + (uint32_t)(FS_SQ + row * FH + c8) * 2,
                   qkv + (size_t)(b * 1024 + q0 + row) * 1536 + h * 64 + c8, 16);
    }
    cp_commit(); cp_wait0();
    __syncthreads();

    uint32_t qf[4][4];
    {
        const uint32_t qbase = smb + (uint32_t)(FS_SQ + (wm + lr) * FH + lh) * 2;
        #pragma unroll
        for (int kc = 0; kc < 4; kc++)
            ldsm4(qf[kc][0], qf[kc][1], qf[kc][2], qf[kc][3], qbase + kc * 32);
    }

    float m_[2] = {-1e30f, -1e30f};
    float l_[2] = {0.f, 0.f};
    float acco[8][4];
    #pragma unroll
    for (int i = 0; i < 8; i++)
        #pragma unroll
        for (int r = 0; r < 4; r++) acco[i][r] = 0.f;

    const uint32_t kbase = smb + (uint32_t)(FS_SK + lr * FH + lh) * 2;
    const uint32_t pbase = smb + (uint32_t)(FS_SP + (wm + lr) * PH + lh) * 2;
    const uint32_t vbase = smb + (uint32_t)(FS_SV + lr * FH + lh) * 2;

    for (int j = 0; j < 8; j++) {
        // ---- cp.async K + V (raw layout) ----
        {
            const __half* base = qkv + (size_t)(b * 1024 + j * 128) * 1536 + h * 64;
            for (int i = tid; i < 1024; i += 256) {
                int row = i >> 3;
                int c8  = (i & 7) * 8;
                const __half* rb = base + (size_t)row * 1536 + c8;
                cp_async16(smb + (uint32_t)(FS_SK + row * FH + c8) * 2, rb + 512, 16);
                cp_async16(smb + (uint32_t)(FS_SV + row * FH + c8) * 2, rb + 1024, 16);
            }
            cp_commit(); cp_wait0();
        }
        __syncthreads();

        // ---- S = Q @ K^T (16 x 128 per warp) ----
        float accs[16][4];
        #pragma unroll
        for (int nt = 0; nt < 16; nt++)
            #pragma unroll
            for (int r = 0; r < 4; r++) accs[nt][r] = 0.f;

        #pragma unroll
        for (int kc = 0; kc < 4; kc++) {
            const uint32_t ka = kbase + kc * 32;
            #pragma unroll
            for (int p = 0; p < 8; p++) {
                uint32_t b0, b1, b2, b3;
                ldsm4(b0, b1, b2, b3, ka + (uint32_t)(p * 16 * FH) * 2);
                uint32_t bf0[2] = {b0, b2};
                uint32_t bf1[2] = {b1, b3};
                mma_f16(accs[2 * p],     qf[kc], bf0);
                mma_f16(accs[2 * p + 1], qf[kc], bf1);
            }
        }

        // ---- online softmax ----
        float mx0 = -1e30f, mx1 = -1e30f;
        #pragma unroll
        for (int nt = 0; nt < 16; nt++) {
            mx0 = fmaxf(mx0, fmaxf(accs[nt][0], accs[nt][1]));
            mx1 = fmaxf(mx1, fmaxf(accs[nt][2], accs[nt][3]));
        }
        mx0 = fmaxf(mx0, __shfl_xor_sync(0xffffffffu, mx0, 1));
        mx0 = fmaxf(mx0, __shfl_xor_sync(0xffffffffu, mx0, 2));
        mx1 = fmaxf(mx1, __shfl_xor_sync(0xffffffffu, mx1, 1));
        mx1 = fmaxf(mx1, __shfl_xor_sync(0xffffffffu, mx1, 2));
        const float mn0 = fmaxf(m_[0], mx0);
        const float mn1 = fmaxf(m_[1], mx1);
        const float c0 = __expf((m_[0] - mn0) * SCL);
        const float c1 = __expf((m_[1] - mn1) * SCL);
        l_[0] *= c0; l_[1] *= c1;
        #pragma unroll
        for (int nt = 0; nt < 8; nt++) {
            acco[nt][0] *= c0; acco[nt][1] *= c0;
            acco[nt][2] *= c1; acco[nt][3] *= c1;
        }
        float rs0 = 0.f, rs1 = 0.f;
        __half* p0 = sP + (wm + g) * PH + 2 * tg;
        __half* p1 = sP + (wm + g + 8) * PH + 2 * tg;
        #pragma unroll
        for (int nt = 0; nt < 16; nt++) {
            const float e0 = __expf((accs[nt][0] - mn0) * SCL);
            const float e1 = __expf((accs[nt][1] - mn0) * SCL);
            const float e2 = __expf((accs[nt][2] - mn1) * SCL);
            const float e3 = __expf((accs[nt][3] - mn1) * SCL);
            rs0 += e0 + e1; rs1 += e2 + e3;
            *(__half2*)(p0 + nt * 8) = __floats2half2_rn(e0, e1);
            *(__half2*)(p1 + nt * 8) = __floats2half2_rn(e2, e3);
        }
        rs0 += __shfl_xor_sync(0xffffffffu, rs0, 1);
        rs0 += __shfl_xor_sync(0xffffffffu, rs0, 2);
        rs1 += __shfl_xor_sync(0xffffffffu, rs1, 1);
        rs1 += __shfl_xor_sync(0xffffffffu, rs1, 2);
        l_[0] += rs0; l_[1] += rs1;
        m_[0] = mn0; m_[1] = mn1;
        __syncwarp();

        // ---- O += P @ V  (V raw, trans ldmatrix) ----
        #pragma unroll
        for (int kc = 0; kc < 8; kc++) {
            uint32_t af[4];
            ldsm4(af[0], af[1], af[2], af[3], pbase + kc * 32);
            const uint32_t va = vbase + (uint32_t)(kc * 16 * FH) * 2;
            #pragma unroll
            for (int p = 0; p < 4; p++) {
                uint32_t t0, t1, t2, t3;
                ldsm4t(t0, t1, t2, t3, va + (uint32_t)(p * 16) * 2);
                uint32_t bf0[2] = {t0, t1};
                uint32_t bf1[2] = {t2, t3};
                mma_f16(acco[2 * p],     af, bf0);
                mma_f16(acco[2 * p + 1], af, bf1);
            }
        }
        __syncthreads();
    }

    const float i0 = 1.f / l_[0];
    const float i1 = 1.f / l_[1];
    const int row0 = b * 1024 + q0 + wm + g;
    #pragma unroll
    for (int nt = 0; nt < 8; nt++) {
        const int col = h * 64 + nt * 8 + 2 * tg;
        *(__half2*)(outp + (size_t)row0 * 512 + col) =
            __floats2half2_rn(acco[nt][0] * i0, acco[nt][1] * i0);
        *(__half2*)(outp + (size_t)(row0 + 8) * 512 + col) =
            __floats2half2_rn(acco[nt][2] * i1, acco[nt][3] * i1);
    }
}

// ===========================================================================
// Fused flash cross-attention (kv 77 -> padded 80), fp16, trans-V.
// ===========================================================================
#define CH 88
#define CF_SQ   0
#define CF_SK   (128*FH)
#define CF_SV   (CF_SK + 80*FH)
#define CF_SP   (CF_SV + 80*FH)
#define CF_TOTAL_H (CF_SP + 128*CH)

__global__ void __launch_bounds__(256) flash_cross_kernel(
    const __half* __restrict__ qsrc, const __half* __restrict__ kv2,
    __half* __restrict__ outp) {
    extern __shared__ __half smh[];
    __half* sP = smh + CF_SP;

    const int b  = blockIdx.y >> 3;
    const int h  = blockIdx.y & 7;
    const int q0 = blockIdx.x * 128;
    const int tid = threadIdx.x;
    const int warp = tid >> 5;
    const int lane = tid & 31;
    const int g  = lane >> 2;
    const int tg = lane & 3;
    const int wm = warp * 16;

    const uint32_t smb = (uint32_t)__cvta_generic_to_shared(smh);
    const uint32_t lr = lane & 15;
    const uint32_t lh = (lane >> 4) * 8;

    // Q via cp.async
    for (int i = tid; i < 1024; i += 256) {
        int row = i >> 3;
        int c8  = (i & 7) * 8;
        cp_async16(smb + (uint32_t)(CF_SQ + row * FH + c8) * 2,
                   qsrc + (size_t)(b * 1024 + q0 + row) * 512 + h * 64 + c8, 16);
    }
    // K + V raw (rows >= KVLEN zero-filled via bytes=0)
    for (int i = tid; i < 640; i += 256) {
        int row = i >> 3;
        int c8  = (i & 7) * 8;
        int bytes = (row < KVLEN) ? 16 : 0;
        const __half* base = kv2 + (size_t)(b * KVLEN + row) * 1024 + h * 64;
        cp_async16(smb + (uint32_t)(CF_SK + row * FH + c8) * 2, base + c8, bytes);
        cp_async16(smb + (uint32_t)(CF_SV + row * FH + c8) * 2, base + 512 + c8, bytes);
    }
    cp_commit(); cp_wait0();
    __syncthreads();

    uint32_t qf[4][4];
    {
        const uint32_t qbase = smb + (uint32_t)(CF_SQ + (wm + lr) * FH + lh) * 2;
        #pragma unroll
        for (int kc = 0; kc < 4; kc++)
            ldsm4(qf[kc][0], qf[kc][1], qf[kc][2], qf[kc][3], qbase + kc * 32);
    }

    float accs[10][4];
    #pragma unroll
    for (int nt = 0; nt < 10; nt++)
        #pragma unroll
        for (int r = 0; r < 4; r++) accs[nt][r] = 0.f;
    {
        const uint32_t kbase = smb + (uint32_t)(CF_SK + lr * FH + lh) * 2;
        #pragma unroll
        for (int kc = 0; kc < 4; kc++) {
            const uint32_t ka = kbase + kc * 32;
            #pragma unroll
            for (int p = 0; p < 5; p++) {
                uint32_t b0, b1, b2, b3;
                ldsm4(b0, b1, b2, b3, ka + (uint32_t)(p * 16 * FH) * 2);
                uint32_t bf0[2] = {b0, b2};
                uint32_t bf1[2] = {b1, b3};
                mma_f16(accs[2 * p],     qf[kc], bf0);
                mma_f16(accs[2 * p + 1], qf[kc], bf1);
            }
        }
    }

    #pragma unroll
    for (int nt = 0; nt < 10; nt++) {
        const int col0 = nt * 8 + 2 * tg;
        if (col0 >= KVLEN)     { accs[nt][0] = -1e30f; accs[nt][2] = -1e30f; }
        if (col0 + 1 >= KVLEN) { accs[nt][1] = -1e30f; accs[nt][3] = -1e30f; }
    }
    float mx0 = -1e30f, mx1 = -1e30f;
    #pragma unroll
    for (int nt = 0; nt < 10; nt++) {
        mx0 = fmaxf(mx0, fmaxf(accs[nt][0], accs[nt][1]));
        mx1 = fmaxf(mx1, fmaxf(accs[nt][2], accs[nt][3]));
    }
    mx0 = fmaxf(mx0, __shfl_xor_sync(0xffffffffu, mx0, 1));
    mx0 = fmaxf(mx0, __shfl_xor_sync(0xffffffffu, mx0, 2));
    mx1 = fmaxf(mx1, __shfl_xor_sync(0xffffffffu, mx1, 1));
    mx1 = fmaxf(mx1, __shfl_xor_sync(0xffffffffu, mx1, 2));

    float rs0 = 0.f, rs1 = 0.f;
    __half* p0 = sP + (wm + g) * CH + 2 * tg;
    __half* p1 = sP + (wm + g + 8) * CH + 2 * tg;
    #pragma unroll
    for (int nt = 0; nt < 10; nt++) {
        const float e0 = __expf((accs[nt][0] - mx0) * SCL);
        const float e1 = __expf((accs[nt][1] - mx0) * SCL);
        const float e2 = __expf((accs[nt][2] - mx1) * SCL);
        const float e3 = __expf((accs[nt][3] - mx1) * SCL);
        rs0 += e0 + e1; rs1 += e2 + e3;
        *(__half2*)(p0 + nt * 8) = __floats2half2_rn(e0, e1);
        *(__half2*)(p1 + nt * 8) = __floats2half2_rn(e2, e3);
    }
    rs0 += __shfl_xor_sync(0xffffffffu, rs0, 1);
    rs0 += __shfl_xor_sync(0xffffffffu, rs0, 2);
    rs1 += __shfl_xor_sync(0xffffffffu, rs1, 1);
    rs1 += __shfl_xor_sync(0xffffffffu, rs1, 2);
    __syncwarp();

    float acco[8][4];
    #pragma unroll
    for (int nt = 0; nt < 8; nt++)
        #pragma unroll
        for (int r = 0; r < 4; r++) acco[nt][r] = 0.f;
    {
        const uint32_t pb = smb + (uint32_t)(CF_SP + (wm + lr) * CH + lh) * 2;
        const uint32_t vb = smb + (uint32_t)(CF_SV + lr * FH + lh) * 2;
        #pragma unroll
        for (int kc = 0; kc < 5; kc++) {
            uint32_t af[4];
            ldsm4(af[0], af[1], af[2], af[3], pb + kc * 32);
            const uint32_t va = vb + (uint32_t)(kc * 16 * FH) * 2;
            #pragma unroll
            for (int p = 0; p < 4; p++) {
                uint32_t t0, t1, t2, t3;
                ldsm4t(t0, t1, t2, t3, va + (uint32_t)(p * 16) * 2);
                uint32_t bf0[2] = {t0, t1};
                uint32_t bf1[2] = {t2, t3};
                mma_f16(acco[2 * p],     af, bf0);
                mma_f16(acco[2 * p + 1], af, bf1);
            }
        }
    }

    const float i0 = 1.f / rs0;
    const float i1 = 1.f / rs1;
    const int row0 = b * 1024 + q0 + wm + g;
    #pragma unroll
    for (int nt = 0; nt < 8; nt++) {
        const int col = h * 64 + nt * 8 + 2 * tg;
        *(__half2*)(outp + (size_t)row0 * 512 + col) =
            __floats2half2_rn(acco[nt][0] * i0, acco[nt][1] * i0);
        *(__half2*)(outp + (size_t)(row0 + 8) * 512 + col) =
            __floats2half2_rn(acco[nt][2] * i1, acco[nt][3] * i1);
    }
}

// ===========================================================================
// FP16 tensor-core GEMM: C = A @ Bt^T (+bias)(+epilogue)
//   emode 0: plain (+Res fp32 add)
//   emode 3: GEGLU-paired interleaved a/gate -> Ch, ldc = N/2
//   emode 4: transposed-output write to [b,c,s] + qin residual.
// ===========================================================================
#define BM 128
#define BN 128
#define BK 32
#define GSTR 40
#define STG_BYTES (2 * 128 * GSTR * 2)
#define GEMM_SMEM (3 * STG_BYTES)

__global__ void __launch_bounds__(256, 2) gemm_f16_kernel(
    const __half* __restrict__ A, int lda,
    const __half* __restrict__ Bt, int ldb,
    float* __restrict__ Cf, __half* __restrict__ Ch, int ldc,
    const float* __restrict__ Res, int ldres,
    const float* __restrict__ bias,
    int M, int K, int emode) {

    extern __shared__ __half smh[];

    const int m0 = blockIdx.y * BM;
    const int n0 = blockIdx.x * BN;
    const int tid = threadIdx.x;
    const int warp = tid >> 5;
    const int lane = tid & 31;
    const int g  = lane >> 2;
    const int tg = lane & 3;
    const int wm = (warp >> 2) * 64;
    const int wn = (warp & 3) * 32;

    const uint32_t smem_u32 = (uint32_t)__cvta_generic_to_shared(smh);
    const int nk = K / BK;

    float acc[4][4][4];
    #pragma unroll
    for (int i = 0; i < 4; i++)
        #pragma unroll
        for (int j = 0; j < 4; j++)
            #pragma unroll
            for (int r = 0; r < 4; r++) acc[i][j][r] = 0.f;

    auto load_stage = [&](int stage, int k0) {
        const uint32_t abase = smem_u32 + (uint32_t)(stage * STG_BYTES);
        #pragma unroll
        for (int i = 0; i < 2; i++) {
            int idx = tid + i * 256;
            int row = idx >> 2;
            int kc  = (idx & 3) * 8;
            int bytes = (m0 + row < M) ? 16 : 0;
            cp_async16(abase + (uint32_t)(row * GSTR + kc) * 2,
                       A + (long long)(m0 + row) * lda + k0 + kc, bytes);
        }
        const uint32_t bbase = abase + (uint32_t)(128 * GSTR * 2);
        #pragma unroll
        for (int i = 0; i < 2; i++) {
            int idx = tid + i * 256;
            int row = idx >> 2;
            int kc  = (idx & 3) * 8;
            cp_async16(bbase + (uint32_t)(row * GSTR + kc) * 2,
                       Bt + (long long)(n0 + row) * ldb + k0 + kc, 16);
        }
        cp_commit();
    };

    const uint32_t lm_off = (uint32_t)((lane & 15) * GSTR + ((lane >> 4) * 8)) * 2;
    const uint32_t a_lm = smem_u32 + (uint32_t)(wm * GSTR) * 2 + lm_off;
    const uint32_t b_lm = smem_u32 + (uint32_t)(128 * GSTR + wn * GSTR) * 2 + lm_off;

    auto compute_stage = [&](int stage) {
        const uint32_t so = (uint32_t)(stage * STG_BYTES);
        #pragma unroll
        for (int ks = 0; ks < 2; ks++) {
            const uint32_t kkb = ks * 32;
            uint32_t afr[4][4];
            #pragma unroll
            for (int mt = 0; mt < 4; mt++)
                ldsm4(afr[mt][0], afr[mt][1], afr[mt][2], afr[mt][3],
                      a_lm + so + (uint32_t)(mt * 16 * GSTR) * 2 + kkb);
            uint32_t bfr[4][2];
            #pragma unroll
            for (int p = 0; p < 2; p++) {
                uint32_t r0, r1, r2, r3;
                ldsm4(r0, r1, r2, r3, b_lm + so + (uint32_t)(p * 16 * GSTR) * 2 + kkb);
                bfr[2 * p][0]     = r0; bfr[2 * p][1]     = r2;
                bfr[2 * p + 1][0] = r1; bfr[2 * p + 1][1] = r3;
            }
            #pragma unroll
            for (int mt = 0; mt < 4; mt++)
                #pragma unroll
                for (int nt = 0; nt < 4; nt++)
                    mma_f16(acc[mt][nt], afr[mt], bfr[nt]);
        }
    };

    load_stage(0, 0);
    if (nk > 1) load_stage(1, BK);
    for (int kt = 0; kt < nk; kt++) {
        if (kt + 1 < nk) cp_wait1(); else cp_wait0();
        __syncthreads();
        if (kt + 2 < nk) load_stage((kt + 2) % 3, (kt + 2) * BK);
        compute_stage(kt % 3);
    }

    // ---- epilogue (vectorized) ----
    const int obatch = n0 >> 10;
    #pragma unroll
    for (int mt = 0; mt < 4; mt++) {
        #pragma unroll
        for (int nt = 0; nt < 4; nt++) {
            const int row0 = m0 + wm + mt * 16 + g;
            const int col0 = n0 + wn + nt * 8 + tg * 2;
            #pragma unroll
            for (int hh = 0; hh < 2; hh++) {
                const int row = row0 + hh * 8;
                if (row >= M) continue;
                float v0 = acc[mt][nt][2 * hh + 0];
                float v1 = acc[mt][nt][2 * hh + 1];
                if (emode == 4) {
                    v0 += bias[row]; v1 += bias[row];
                    const size_t o = ((size_t)(obatch * 512 + row)) * 1024 +
                                     (col0 & 1023);
                    float2 r = *(const float2*)(Res + o);
                    *(float2*)(Cf + o) = make_float2(v0 + r.x, v1 + r.y);
                    continue;
                }
                if (bias) { v0 += bias[col0]; v1 += bias[col0 + 1]; }
                if (emode == 3) {
                    Ch[(long long)row * ldc + (col0 >> 1)] =
                        __float2half(v0 * gelu_f(v1));
                    continue;
                }
                if (Res) {
                    float2 r = *(const float2*)(Res + (long long)row * ldres + col0);
                    v0 += r.x; v1 += r.y;
                }
                if (Cf) *(float2*)(Cf + (long long)row * ldc + col0) =
                            make_float2(v0, v1);
                if (Ch) *(__half2*)(Ch + (long long)row * ldc + col0) =
                            __floats2half2_rn(v0, v1);
            }
        }
    }
}

// ---------------------------------------------------------------------------
// Host side
// ---------------------------------------------------------------------------
static void gemm(const __half* A, int lda, const __half* Bt, int ldb,
                 float* Cf, __half* Ch, int ldc,
                 const float* Res, int ldres,
                 const float* bias, int M, int N, int K, int emode = 0) {
    dim3 grid(N / BN, (M + BM - 1) / BM);
    gemm_f16_kernel<<<grid, 256, GEMM_SMEM>>>(
        A, lda, Bt, ldb, Cf, Ch, ldc, Res, ldres, bias, M, K, emode);
}

extern "C" void kernel_launch(void* const* d_in, const int* in_sizes, int n_in,
                              void* d_out, int out_size) {
    const float* in_q     = (const float*)d_in[0];
    const float* in_kv    = (const float*)d_in[1];
    const float* gn_g     = (const float*)d_in[2];
    const float* gn_b     = (const float*)d_in[3];
    const float* ln2_g    = (const float*)d_in[4];
    const float* ln2_b    = (const float*)d_in[5];
    const float* ln3_g    = (const float*)d_in[6];
    const float* ln3_b    = (const float*)d_in[7];
    const float* ln4_g    = (const float*)d_in[8];
    const float* ln4_b    = (const float*)d_in[9];
    const float* fc_in_w  = (const float*)d_in[10];
    const float* fc_in_b  = (const float*)d_in[11];
    const float* fc_out_w = (const float*)d_in[12];
    const float* fc_out_b = (const float*)d_in[13];
    const float* a1_q     = (const float*)d_in[14];
    const float* a1_k     = (const float*)d_in[15];
    const float* a1_v     = (const float*)d_in[16];
    const float* a1_o     = (const float*)d_in[17];
    const float* a1_ob    = (const float*)d_in[18];
    const float* a2_q     = (const float*)d_in[19];
    const float* a2_k     = (const float*)d_in[20];
    const float* a2_v     = (const float*)d_in[21];
    const float* a2_o     = (const float*)d_in[22];
    const float* a2_ob    = (const float*)d_in[23];
    const float* ff_proj_w = (const float*)d_in[24];
    const float* ff_proj_b = (const float*)d_in[25];
    const float* ff_out_w  = (const float*)d_in[26];
    const float* ff_out_b  = (const float*)d_in[27];

    cudaFuncSetAttribute(gemm_f16_kernel,
                         cudaFuncAttributeMaxDynamicSharedMemorySize, GEMM_SMEM);
    cudaFuncSetAttribute(flash_self_kernel,
                         cudaFuncAttributeMaxDynamicSharedMemorySize, FS_TOTAL_H * 2);
    cudaFuncSetAttribute(flash_cross_kernel,
                         cudaFuncAttributeMaxDynamicSharedMemorySize, CF_TOTAL_H * 2);

    float *x, *bFfp, *gnst;
    __half *th, *qkvh, *qh, *kvh, *kv2h, *glh, *xh;
    __half *whFcIn, *whQkv, *whA1o, *whA2q, *whA2o, *whKv2, *whFfp, *whFfo, *whFco;
    cudaGetSymbolAddress((void**)&x,    g_x);
    cudaGetSymbolAddress((void**)&bFfp, g_bFfp);
    cudaGetSymbolAddress((void**)&gnst, g_gnstats);
    cudaGetSymbolAddress((void**)&th,   g_th);
    cudaGetSymbolAddress((void**)&qkvh, g_qkvh);
    cudaGetSymbolAddress((void**)&qh,   g_qh);
    cudaGetSymbolAddress((void**)&kvh,  g_kvh);
    cudaGetSymbolAddress((void**)&kv2h, g_kv2h);
    cudaGetSymbolAddress((void**)&glh,  g_glh);
    cudaGetSymbolAddress((void**)&xh,   g_xh);
    cudaGetSymbolAddress((void**)&whFcIn, g_whFcIn);
    cudaGetSymbolAddress((void**)&whQkv,  g_whQkv);
    cudaGetSymbolAddress((void**)&whA1o,  g_whA1o);
    cudaGetSymbolAddress((void**)&whA2q,  g_whA2q);
    cudaGetSymbolAddress((void**)&whA2o,  g_whA2o);
    cudaGetSymbolAddress((void**)&whKv2,  g_whKv2);
    cudaGetSymbolAddress((void**)&whFfp,  g_whFfp);
    cudaGetSymbolAddress((void**)&whFfo,  g_whFfo);
    cudaGetSymbolAddress((void**)&whFco,  g_whFco);

    float* out = (float*)d_out;

    // ---- batched weight transpose+convert (ONE launch) ----
    {
        TrJobs jb;
        const float* srcs[NJOBS] = {fc_in_w, a1_q, a1_k, a1_v, a1_o, a2_q,
                                    a2_o, a2_k, a2_v, ff_proj_w, ff_out_w, fc_out_w};
        __half* dsts[NJOBS] = {whFcIn, whQkv, whQkv + (size_t)512 * 512,
                               whQkv + (size_t)1024 * 512, whA1o, whA2q, whA2o,
                               whKv2, whKv2 + (size_t)512 * 1024,
                               whFfp, whFfo, whFco};
        int Rs[NJOBS] = {512, 512, 512, 512, 512, 512, 512, 1024, 1024, 512, 2048, 512};
        int Cs[NJOBS] = {512, 512, 512, 512, 512, 512, 512, 512, 512, 4096, 512, 512};
        int Il[NJOBS] = {0, 0, 0, 0, 0, 0, 0, 0, 0, 1, 0, 0};
        int acc = 0;
        for (int i = 0; i < NJOBS; i++) {
            jb.src[i] = srcs[i]; jb.dst[i] = dsts[i];
            jb.R[i] = Rs[i]; jb.C[i] = Cs[i]; jb.ileave[i] = Il[i];
            jb.tstart[i] = acc;
            acc += (Rs[i] / 32) * (Cs[i] / 32);
        }
        jb.tstart[NJOBS] = acc;
        trcvt_all_kernel<<<acc, dim3(32, 8)>>>(jb);
    }
    cvt_kernel<<<(BATCH * KVLEN * 1024 + 255) / 256, 256>>>(
        in_kv, kvh, BATCH * KVLEN * 1024);
    bias_ileave_kernel<<<8, 256>>>(ff_proj_b, bFfp);

    // 1. GroupNorm: stats then tiled normalize+transpose -> th (half)
    gn_stats_kernel<<<BATCH * 32, 256>>>(in_q, gnst);
    {
        dim3 grid(SPATIAL / 32, DIMC / 32, BATCH);
        gn_write_kernel<<<grid, dim3(32, 8)>>>(in_q, gnst, gn_g, gn_b, th);
    }

    // 2. x = th @ fc_in + b (fp32)
    gemm(th, 512, whFcIn, 512, x, nullptr, 512, nullptr, 0, fc_in_b,
         NTOK, 512, 512);

    // ---- self attention ----
    layernorm_kernel<<<NTOK / 8, 256>>>(x, ln2_g, ln2_b, th, NTOK);
    gemm(th, 512, whQkv, 512, nullptr, qkvh, 1536, nullptr, 0, nullptr,
         NTOK, 1536, 512);
    {
        dim3 grid(8, 64);
        flash_self_kernel<<<grid, 256, FS_TOTAL_H * 2>>>(qkvh, th);
    }
    gemm(th, 512, whA1o, 512, x, nullptr, 512, x, 512, a1_ob,
         NTOK, 512, 512);

    // ---- cross attention ----
    layernorm_kernel<<<NTOK / 8, 256>>>(x, ln3_g, ln3_b, th, NTOK);
    gemm(th, 512, whA2q, 512, nullptr, qh, 512, nullptr, 0, nullptr,
         NTOK, 512, 512);
    gemm(kvh, 1024, whKv2, 1024, nullptr, kv2h, 1024, nullptr, 0, nullptr,
         BATCH * KVLEN, 1024, 1024);
    {
        dim3 grid(8, 64);
        flash_cross_kernel<<<grid, 256, CF_TOTAL_H * 2>>>(qh, kv2h, th);
    }
    gemm(th, 512, whA2o, 512, x, nullptr, 512, x, 512, a2_ob,
         NTOK, 512, 512);

    // ---- feed-forward (GEGLU, single interleaved GEMM) ----
    layernorm_kernel<<<NTOK / 8, 256>>>(x, ln4_g, ln4_b, th, NTOK);
    gemm(th, 512, whFfp, 512, nullptr, glh, 2048, nullptr, 0, bFfp,
         NTOK, 4096, 512, 3);
    gemm(glh, 2048, whFfo, 2048, nullptr, xh, 512, x, 512, ff_out_b,
         NTOK, 512, 2048);

    // ---- output projection, transposed: out[b,c,s] = fco + qin ----
    gemm(whFco, 512, xh, 512, out, nullptr, 0, in_q, 0, fc_out_b,
         512, NTOK, 512, 4);
}

// round 16
// speedup vs baseline: 2.2153x; 1.0214x over previous
#include <cuda_runtime.h>
#include <cuda_fp16.h>
#include <cstdint>
#include <math.h>

// ---------------------------------------------------------------------------
// Problem constants
// ---------------------------------------------------------------------------
#define BATCH   8
#define DIMC    512
#define SPATIAL 1024
#define NTOK    (BATCH*SPATIAL)  // 8192
#define HEADS   8
#define HDIM    64
#define KVLEN   77
#define KVDIM   1024

// ---------------------------------------------------------------------------
// Scratch buffers
// ---------------------------------------------------------------------------
__device__ float  g_x  [(size_t)NTOK * DIMC];           // fp32 residual stream
__device__ float  g_bFfp[4096];                         // interleaved ffp bias
__device__ float  g_gnstats[BATCH * 32 * 2];            // groupnorm mu/inv
__device__ __half g_th  [(size_t)NTOK * DIMC];
__device__ __half g_qkvh[(size_t)NTOK * 1536];
__device__ __half g_qh  [(size_t)NTOK * DIMC];
__device__ __half g_kvh [(size_t)(BATCH*KVLEN) * 1024];
__device__ __half g_kv2h[(size_t)(BATCH*KVLEN) * 1024];
__device__ __half g_glh [(size_t)NTOK * 2048];
__device__ __half g_xh  [(size_t)NTOK * DIMC];
// half transposed weights [N, K]
__device__ __half g_whFcIn[(size_t)512 * 512];
__device__ __half g_whQkv [(size_t)1536 * 512];
__device__ __half g_whA1o [(size_t)512 * 512];
__device__ __half g_whA2q [(size_t)512 * 512];
__device__ __half g_whA2o [(size_t)512 * 512];
__device__ __half g_whKv2 [(size_t)1024 * 1024];
__device__ __half g_whFfp [(size_t)4096 * 512];         // a/gate interleaved rows
__device__ __half g_whFfo [(size_t)512 * 2048];
__device__ __half g_whFco [(size_t)512 * 512];

// ---------------------------------------------------------------------------
// Helpers
// ---------------------------------------------------------------------------
__device__ __forceinline__ float warpSum(float v) {
    #pragma unroll
    for (int o = 16; o > 0; o >>= 1) v += __shfl_xor_sync(0xffffffffu, v, o);
    return v;
}
__device__ __forceinline__ void mma_f16(float* d, const uint32_t* a, const uint32_t* b) {
    asm volatile(
        "mma.sync.aligned.m16n8k16.row.col.f32.f16.f16.f32 "
        "{%0,%1,%2,%3}, {%4,%5,%6,%7}, {%8,%9}, {%0,%1,%2,%3};"
        : "+f"(d[0]), "+f"(d[1]), "+f"(d[2]), "+f"(d[3])
        : "r"(a[0]), "r"(a[1]), "r"(a[2]), "r"(a[3]), "r"(b[0]), "r"(b[1]));
}
__device__ __forceinline__ void ldsm4(uint32_t& r0, uint32_t& r1,
                                      uint32_t& r2, uint32_t& r3, uint32_t addr) {
    asm volatile("ldmatrix.sync.aligned.m8n8.x4.shared.b16 {%0,%1,%2,%3}, [%4];"
                 : "=r"(r0), "=r"(r1), "=r"(r2), "=r"(r3) : "r"(addr));
}
__device__ __forceinline__ void ldsm4t(uint32_t& r0, uint32_t& r1,
                                       uint32_t& r2, uint32_t& r3, uint32_t addr) {
    asm volatile("ldmatrix.sync.aligned.m8n8.x4.trans.shared.b16 {%0,%1,%2,%3}, [%4];"
                 : "=r"(r0), "=r"(r1), "=r"(r2), "=r"(r3) : "r"(addr));
}
__device__ __forceinline__ void cp_async16(uint32_t dst, const void* src, int bytes) {
    asm volatile("cp.async.cg.shared.global [%0], [%1], 16, %2;\n"
                 :: "r"(dst), "l"(src), "r"(bytes));
}
__device__ __forceinline__ void cp_commit() { asm volatile("cp.async.commit_group;\n"); }
__device__ __forceinline__ void cp_wait1()  { asm volatile("cp.async.wait_group 1;\n"); }
__device__ __forceinline__ void cp_wait0()  { asm volatile("cp.async.wait_group 0;\n"); }
__device__ __forceinline__ float gelu_f(float v) {
    return 0.5f * v * (1.f + erff(v * 0.70710678118654752f));
}

// ---------------------------------------------------------------------------
// GroupNorm stats: one block per (batch, group). Coalesced read only.
// ---------------------------------------------------------------------------
__global__ void gn_stats_kernel(const float* __restrict__ qin,
                                float* __restrict__ stats) {
    const int blk = blockIdx.x;
    const float* base = qin + (size_t)blk * 16 * SPATIAL;

    float s = 0.f, s2 = 0.f;
    for (int i = threadIdx.x; i < 16 * SPATIAL; i += 256) {
        float v = base[i];
        s += v; s2 += v * v;
    }
    __shared__ float red[2][8];
    s = warpSum(s); s2 = warpSum(s2);
    int wid = threadIdx.x >> 5, lid = threadIdx.x & 31;
    if (lid == 0) { red[0][wid] = s; red[1][wid] = s2; }
    __syncthreads();
    if (threadIdx.x == 0) {
        float a = 0.f, c = 0.f;
        #pragma unroll
        for (int i = 0; i < 8; i++) { a += red[0][i]; c += red[1][i]; }
        const float mu  = a * (1.f / 16384.f);
        const float var = c * (1.f / 16384.f) - mu * mu;
        stats[blk * 2]     = mu;
        stats[blk * 2 + 1] = rsqrtf(var + 1e-6f);
    }
}

// ---------------------------------------------------------------------------
// GroupNorm normalize + transpose to token-major (32x32 tiles, coalesced).
// ---------------------------------------------------------------------------
__global__ void gn_write_kernel(const float* __restrict__ qin,
                                const float* __restrict__ stats,
                                const float* __restrict__ gamma,
                                const float* __restrict__ beta,
                                __half* __restrict__ out) {
    __shared__ float tile[32][33];
    const int b  = blockIdx.z;
    const int c0 = blockIdx.y * 32;
    const int s0 = blockIdx.x * 32;
    const int x = threadIdx.x, y = threadIdx.y;

    #pragma unroll
    for (int i = 0; i < 32; i += 8)
        tile[y + i][x] = qin[((size_t)(b * DIMC + c0 + y + i)) * SPATIAL + s0 + x];
    __syncthreads();

    const int c = c0 + x;
    const int sb = (b * 32 + (c >> 4)) * 2;
    const float mu  = stats[sb];
    const float inv = stats[sb + 1];
    const float gm = gamma[c], bt = beta[c];
    #pragma unroll
    for (int i = 0; i < 32; i += 8) {
        float v = (tile[x][y + i] - mu) * inv * gm + bt;
        out[((size_t)(b * SPATIAL + s0 + y + i)) * DIMC + c] = __float2half(v);
    }
}

// ---------------------------------------------------------------------------
// LayerNorm (fp32 in, half out). One warp per 512-dim row.
// ---------------------------------------------------------------------------
__global__ void layernorm_kernel(const float* __restrict__ x,
                                 const float* __restrict__ gamma,
                                 const float* __restrict__ beta,
                                 __half* __restrict__ out, int rows) {
    int row = blockIdx.x * 8 + (threadIdx.x >> 5);
    if (row >= rows) return;
    int lid = threadIdx.x & 31;
    const float4* xr = (const float4*)(x + (size_t)row * DIMC);

    float4 vals[4];
    float s = 0.f, s2 = 0.f;
    #pragma unroll
    for (int i = 0; i < 4; i++) {
        float4 v = xr[lid + 32 * i];
        vals[i] = v;
        s  += v.x + v.y + v.z + v.w;
        s2 += v.x*v.x + v.y*v.y + v.z*v.z + v.w*v.w;
    }
    s = warpSum(s); s2 = warpSum(s2);
    const float mu  = s * (1.f / 512.f);
    const float inv = rsqrtf(s2 * (1.f / 512.f) - mu * mu + 1e-5f);

    __half2* orow = (__half2*)(out + (size_t)row * DIMC);
    const float4* g4 = (const float4*)gamma;
    const float4* b4 = (const float4*)beta;
    #pragma unroll
    for (int i = 0; i < 4; i++) {
        int idx = lid + 32 * i;
        float4 v = vals[i], g = g4[idx], b = b4[idx];
        float ox = (v.x - mu) * inv * g.x + b.x;
        float oy = (v.y - mu) * inv * g.y + b.y;
        float oz = (v.z - mu) * inv * g.z + b.z;
        float ow = (v.w - mu) * inv * g.w + b.w;
        orow[idx * 2]     = __floats2half2_rn(ox, oy);
        orow[idx * 2 + 1] = __floats2half2_rn(oz, ow);
    }
}

// ---------------------------------------------------------------------------
// Batched transpose + f32->f16 (12 weights, ONE launch).
// ---------------------------------------------------------------------------
#define NJOBS 12
struct TrJobs {
    const float* src[NJOBS];
    __half*      dst[NJOBS];
    int R[NJOBS], C[NJOBS], ileave[NJOBS];
    int tstart[NJOBS + 1];
};

__global__ void trcvt_all_kernel(TrJobs jobs) {
    __shared__ float tile[32][33];
    const int flat = blockIdx.x;
    int j = 0;
    #pragma unroll
    for (int i = 0; i < NJOBS; i++)
        if (flat >= jobs.tstart[i + 1]) j = i + 1;
    const int lt = flat - jobs.tstart[j];
    const int C = jobs.C[j], R = jobs.R[j];
    const int ctiles = C >> 5;
    const int c0 = (lt % ctiles) * 32;
    const int r0 = (lt / ctiles) * 32;
    const float* src = jobs.src[j];
    __half* dst = jobs.dst[j];
    const int il = jobs.ileave[j];
    const int halfC = C >> 1;

    int x = threadIdx.x, y = threadIdx.y;
    #pragma unroll
    for (int i = 0; i < 32; i += 8)
        tile[y + i][x] = src[(size_t)(r0 + y + i) * C + c0 + x];
    __syncthreads();
    #pragma unroll
    for (int i = 0; i < 32; i += 8) {
        int d = c0 + y + i;
        if (il) d = (d < halfC) ? 2 * d : 2 * (d - halfC) + 1;
        dst[(size_t)d * R + r0 + x] = __float2half(tile[x][y + i]);
    }
}

// f32 -> f16 linear convert
__global__ void cvt_kernel(const float* __restrict__ src,
                           __half* __restrict__ dst, int n) {
    int i = blockIdx.x * 256 + threadIdx.x;
    if (i < n) dst[i] = __float2half(src[i]);
}

// interleave ffp bias
__global__ void bias_ileave_kernel(const float* __restrict__ b,
                                   float* __restrict__ dst) {
    int j = blockIdx.x * 256 + threadIdx.x;
    if (j < 2048) {
        dst[2 * j]     = b[j];
        dst[2 * j + 1] = b[2048 + j];
    }
}

// ===========================================================================
// Fused flash self-attention, fp16, fp32 accum.
// Double-buffered K, single V buffer, cp.async group pipelining:
//   top of iter j:  wait0 (K[j] done; all warps past prev PV) + sync
//                   issue V[j] (group), issue K[j+1] (group)
//   S from Kbuf[j&1]  (K[j] load hid behind prev iter's softmax+PV)
//   softmax/P, then wait1 (V[j] done, K[j+1] still flying) + sync
//   PV from sV (trans ldmatrix)
// smem = Q + 2K + V + P = 108.5KB -> 2 CTAs/SM.
// ===========================================================================
#define SCL 0.125f
#define FH 72
#define PH 136
#define FS_SQ   0
#define FS_SK0  (128*FH)
#define FS_SK1  (2*128*FH)
#define FS_SV   (3*128*FH)
#define FS_SP   (4*128*FH)
#define FS_TOTAL_H (FS_SP + 128*PH)   // 54272 halves = 108544 B

__global__ void __launch_bounds__(256) flash_self_kernel(
    const __half* __restrict__ qkv, __half* __restrict__ outp) {
    extern __shared__ __half smh[];
    __half* sP = smh + FS_SP;

    const int b  = blockIdx.y >> 3;
    const int h  = blockIdx.y & 7;
    const int q0 = blockIdx.x * 128;
    const int tid = threadIdx.x;
    const int warp = tid >> 5;
    const int lane = tid & 31;
    const int g  = lane >> 2;
    const int tg = lane & 3;
    const int wm = warp * 16;

    const uint32_t smb = (uint32_t)__cvta_generic_to_shared(smh);
    const uint32_t lr = lane & 15;
    const uint32_t lh = (lane >> 4) * 8;

    // per-thread load coords (8 rows apart, 8-half chunks)
    const int lrow = tid >> 3;
    const int lc8  = (tid & 7) * 8;

    // ---- prologue: Q (group), K[0] (group) ----
    #pragma unroll
    for (int r = 0; r < 4; r++) {
        int row = lrow + r * 32;
        cp_async16(smb + (uint32_t)(FS_SQ + row * FH + lc8) * 2,
                   qkv + (size_t)(b * 1024 + q0 + row) * 1536 + h * 64 + lc8, 16);
    }
    cp_commit();
    {
        const __half* kb = qkv + (size_t)(b * 1024) * 1536 + h * 64 + 512;
        #pragma unroll
        for (int r = 0; r < 4; r++) {
            int row = lrow + r * 32;
            cp_async16(smb + (uint32_t)(FS_SK0 + row * FH + lc8) * 2,
                       kb + (size_t)row * 1536 + lc8, 16);
        }
    }
    cp_commit();
    cp_wait1();          // Q done
    __syncthreads();

    uint32_t qf[4][4];
    {
        const uint32_t qbase = smb + (uint32_t)(FS_SQ + (wm + lr) * FH + lh) * 2;
        #pragma unroll
        for (int kc = 0; kc < 4; kc++)
            ldsm4(qf[kc][0], qf[kc][1], qf[kc][2], qf[kc][3], qbase + kc * 32);
    }

    float m_[2] = {-1e30f, -1e30f};
    float l_[2] = {0.f, 0.f};
    float acco[8][4];
    #pragma unroll
    for (int i = 0; i < 8; i++)
        #pragma unroll
        for (int r = 0; r < 4; r++) acco[i][r] = 0.f;

    const uint32_t pbase = smb + (uint32_t)(FS_SP + (wm + lr) * PH + lh) * 2;
    const uint32_t vbase = smb + (uint32_t)(FS_SV + lr * FH + lh) * 2;

    for (int j = 0; j < 8; j++) {
        // ---- top: K[j] ready, sV free ----
        cp_wait0();
        __syncthreads();

        // issue V[j] (own group)
        {
            const __half* vb = qkv + (size_t)(b * 1024 + j * 128) * 1536 + h * 64 + 1024;
            #pragma unroll
            for (int r = 0; r < 4; r++) {
                int row = lrow + r * 32;
                cp_async16(smb + (uint32_t)(FS_SV + row * FH + lc8) * 2,
                           vb + (size_t)row * 1536 + lc8, 16);
            }
        }
        cp_commit();
        // issue K[j+1] (own group)
        if (j + 1 < 8) {
            const int kbuf = ((j + 1) & 1) ? FS_SK1 : FS_SK0;
            const __half* kb = qkv + (size_t)(b * 1024 + (j + 1) * 128) * 1536 + h * 64 + 512;
            #pragma unroll
            for (int r = 0; r < 4; r++) {
                int row = lrow + r * 32;
                cp_async16(smb + (uint32_t)(kbuf + row * FH + lc8) * 2,
                           kb + (size_t)row * 1536 + lc8, 16);
            }
            cp_commit();
        }

        // ---- S = Q @ K[j]^T ----
        const uint32_t kbase = smb +
            (uint32_t)(((j & 1) ? FS_SK1 : FS_SK0) + lr * FH + lh) * 2;
        float accs[16][4];
        #pragma unroll
        for (int nt = 0; nt < 16; nt++)
            #pragma unroll
            for (int r = 0; r < 4; r++) accs[nt][r] = 0.f;

        #pragma unroll
        for (int kc = 0; kc < 4; kc++) {
            const uint32_t ka = kbase + kc * 32;
            #pragma unroll
            for (int p = 0; p < 8; p++) {
                uint32_t b0, b1, b2, b3;
                ldsm4(b0, b1, b2, b3, ka + (uint32_t)(p * 16 * FH) * 2);
                uint32_t bf0[2] = {b0, b2};
                uint32_t bf1[2] = {b1, b3};
                mma_f16(accs[2 * p],     qf[kc], bf0);
                mma_f16(accs[2 * p + 1], qf[kc], bf1);
            }
        }

        // ---- online softmax ----
        float mx0 = -1e30f, mx1 = -1e30f;
        #pragma unroll
        for (int nt = 0; nt < 16; nt++) {
            mx0 = fmaxf(mx0, fmaxf(accs[nt][0], accs[nt][1]));
            mx1 = fmaxf(mx1, fmaxf(accs[nt][2], accs[nt][3]));
        }
        mx0 = fmaxf(mx0, __shfl_xor_sync(0xffffffffu, mx0, 1));
        mx0 = fmaxf(mx0, __shfl_xor_sync(0xffffffffu, mx0, 2));
        mx1 = fmaxf(mx1, __shfl_xor_sync(0xffffffffu, mx1, 1));
        mx1 = fmaxf(mx1, __shfl_xor_sync(0xffffffffu, mx1, 2));
        const float mn0 = fmaxf(m_[0], mx0);
        const float mn1 = fmaxf(m_[1], mx1);
        const float c0 = __expf((m_[0] - mn0) * SCL);
        const float c1 = __expf((m_[1] - mn1) * SCL);
        l_[0] *= c0; l_[1] *= c1;
        #pragma unroll
        for (int nt = 0; nt < 8; nt++) {
            acco[nt][0] *= c0; acco[nt][1] *= c0;
            acco[nt][2] *= c1; acco[nt][3] *= c1;
        }
        float rs0 = 0.f, rs1 = 0.f;
        __half* p0 = sP + (wm + g) * PH + 2 * tg;
        __half* p1 = sP + (wm + g + 8) * PH + 2 * tg;
        #pragma unroll
        for (int nt = 0; nt < 16; nt++) {
            const float e0 = __expf((accs[nt][0] - mn0) * SCL);
            const float e1 = __expf((accs[nt][1] - mn0) * SCL);
            const float e2 = __expf((accs[nt][2] - mn1) * SCL);
            const float e3 = __expf((accs[nt][3] - mn1) * SCL);
            rs0 += e0 + e1; rs1 += e2 + e3;
            *(__half2*)(p0 + nt * 8) = __floats2half2_rn(e0, e1);
            *(__half2*)(p1 + nt * 8) = __floats2half2_rn(e2, e3);
        }
        rs0 += __shfl_xor_sync(0xffffffffu, rs0, 1);
        rs0 += __shfl_xor_sync(0xffffffffu, rs0, 2);
        rs1 += __shfl_xor_sync(0xffffffffu, rs1, 1);
        rs1 += __shfl_xor_sync(0xffffffffu, rs1, 2);
        l_[0] += rs0; l_[1] += rs1;
        m_[0] = mn0; m_[1] = mn1;

        // ---- wait V[j] (older group; K[j+1] keeps flying) ----
        if (j + 1 < 8) cp_wait1(); else cp_wait0();
        __syncthreads();

        // ---- O += P @ V  (V raw, trans ldmatrix) ----
        #pragma unroll
        for (int kc = 0; kc < 8; kc++) {
            uint32_t af[4];
            ldsm4(af[0], af[1], af[2], af[3], pbase + kc * 32);
            const uint32_t va = vbase + (uint32_t)(kc * 16 * FH) * 2;
            #pragma unroll
            for (int p = 0; p < 4; p++) {
                uint32_t t0, t1, t2, t3;
                ldsm4t(t0, t1, t2, t3, va + (uint32_t)(p * 16) * 2);
                uint32_t bf0[2] = {t0, t1};
                uint32_t bf1[2] = {t2, t3};
                mma_f16(acco[2 * p],     af, bf0);
                mma_f16(acco[2 * p + 1], af, bf1);
            }
        }
        // no end barrier: next-top wait0+sync protects sV / K buffers
    }

    const float i0 = 1.f / l_[0];
    const float i1 = 1.f / l_[1];
    const int row0 = b * 1024 + q0 + wm + g;
    #pragma unroll
    for (int nt = 0; nt < 8; nt++) {
        const int col = h * 64 + nt * 8 + 2 * tg;
        *(__half2*)(outp + (size_t)row0 * 512 + col) =
            __floats2half2_rn(acco[nt][0] * i0, acco[nt][1] * i0);
        *(__half2*)(outp + (size_t)(row0 + 8) * 512 + col) =
            __floats2half2_rn(acco[nt][2] * i1, acco[nt][3] * i1);
    }
}

// ===========================================================================
// Fused flash cross-attention (kv 77 -> padded 80), fp16, trans-V.
// ===========================================================================
#define CH 88
#define CF_SQ   0
#define CF_SK   (128*FH)
#define CF_SV   (CF_SK + 80*FH)
#define CF_SP   (CF_SV + 80*FH)
#define CF_TOTAL_H (CF_SP + 128*CH)

__global__ void __launch_bounds__(256) flash_cross_kernel(
    const __half* __restrict__ qsrc, const __half* __restrict__ kv2,
    __half* __restrict__ outp) {
    extern __shared__ __half smh[];
    __half* sP = smh + CF_SP;

    const int b  = blockIdx.y >> 3;
    const int h  = blockIdx.y & 7;
    const int q0 = blockIdx.x * 128;
    const int tid = threadIdx.x;
    const int warp = tid >> 5;
    const int lane = tid & 31;
    const int g  = lane >> 2;
    const int tg = lane & 3;
    const int wm = warp * 16;

    const uint32_t smb = (uint32_t)__cvta_generic_to_shared(smh);
    const uint32_t lr = lane & 15;
    const uint32_t lh = (lane >> 4) * 8;

    for (int i = tid; i < 1024; i += 256) {
        int row = i >> 3;
        int c8  = (i & 7) * 8;
        cp_async16(smb + (uint32_t)(CF_SQ + row * FH + c8) * 2,
                   qsrc + (size_t)(b * 1024 + q0 + row) * 512 + h * 64 + c8, 16);
    }
    for (int i = tid; i < 640; i += 256) {
        int row = i >> 3;
        int c8  = (i & 7) * 8;
        int bytes = (row < KVLEN) ? 16 : 0;
        const __half* base = kv2 + (size_t)(b * KVLEN + row) * 1024 + h * 64;
        cp_async16(smb + (uint32_t)(CF_SK + row * FH + c8) * 2, base + c8, bytes);
        cp_async16(smb + (uint32_t)(CF_SV + row * FH + c8) * 2, base + 512 + c8, bytes);
    }
    cp_commit(); cp_wait0();
    __syncthreads();

    uint32_t qf[4][4];
    {
        const uint32_t qbase = smb + (uint32_t)(CF_SQ + (wm + lr) * FH + lh) * 2;
        #pragma unroll
        for (int kc = 0; kc < 4; kc++)
            ldsm4(qf[kc][0], qf[kc][1], qf[kc][2], qf[kc][3], qbase + kc * 32);
    }

    float accs[10][4];
    #pragma unroll
    for (int nt = 0; nt < 10; nt++)
        #pragma unroll
        for (int r = 0; r < 4; r++) accs[nt][r] = 0.f;
    {
        const uint32_t kbase = smb + (uint32_t)(CF_SK + lr * FH + lh) * 2;
        #pragma unroll
        for (int kc = 0; kc < 4; kc++) {
            const uint32_t ka = kbase + kc * 32;
            #pragma unroll
            for (int p = 0; p < 5; p++) {
                uint32_t b0, b1, b2, b3;
                ldsm4(b0, b1, b2, b3, ka + (uint32_t)(p * 16 * FH) * 2);
                uint32_t bf0[2] = {b0, b2};
                uint32_t bf1[2] = {b1, b3};
                mma_f16(accs[2 * p],     qf[kc], bf0);
                mma_f16(accs[2 * p + 1], qf[kc], bf1);
            }
        }
    }

    #pragma unroll
    for (int nt = 0; nt < 10; nt++) {
        const int col0 = nt * 8 + 2 * tg;
        if (col0 >= KVLEN)     { accs[nt][0] = -1e30f; accs[nt][2] = -1e30f; }
        if (col0 + 1 >= KVLEN) { accs[nt][1] = -1e30f; accs[nt][3] = -1e30f; }
    }
    float mx0 = -1e30f, mx1 = -1e30f;
    #pragma unroll
    for (int nt = 0; nt < 10; nt++) {
        mx0 = fmaxf(mx0, fmaxf(accs[nt][0], accs[nt][1]));
        mx1 = fmaxf(mx1, fmaxf(accs[nt][2], accs[nt][3]));
    }
    mx0 = fmaxf(mx0, __shfl_xor_sync(0xffffffffu, mx0, 1));
    mx0 = fmaxf(mx0, __shfl_xor_sync(0xffffffffu, mx0, 2));
    mx1 = fmaxf(mx1, __shfl_xor_sync(0xffffffffu, mx1, 1));
    mx1 = fmaxf(mx1, __shfl_xor_sync(0xffffffffu, mx1, 2));

    float rs0 = 0.f, rs1 = 0.f;
    __half* p0 = sP + (wm + g) * CH + 2 * tg;
    __half* p1 = sP + (wm + g + 8) * CH + 2 * tg;
    #pragma unroll
    for (int nt = 0; nt < 10; nt++) {
        const float e0 = __expf((accs[nt][0] - mx0) * SCL);
        const float e1 = __expf((accs[nt][1] - mx0) * SCL);
        const float e2 = __expf((accs[nt][2] - mx1) * SCL);
        const float e3 = __expf((accs[nt][3] - mx1) * SCL);
        rs0 += e0 + e1; rs1 += e2 + e3;
        *(__half2*)(p0 + nt * 8) = __floats2half2_rn(e0, e1);
        *(__half2*)(p1 + nt * 8) = __floats2half2_rn(e2, e3);
    }
    rs0 += __shfl_xor_sync(0xffffffffu, rs0, 1);
    rs0 += __shfl_xor_sync(0xffffffffu, rs0, 2);
    rs1 += __shfl_xor_sync(0xffffffffu, rs1, 1);
    rs1 += __shfl_xor_sync(0xffffffffu, rs1, 2);
    __syncwarp();

    float acco[8][4];
    #pragma unroll
    for (int nt = 0; nt < 8; nt++)
        #pragma unroll
        for (int r = 0; r < 4; r++) acco[nt][r] = 0.f;
    {
        const uint32_t pb = smb + (uint32_t)(CF_SP + (wm + lr) * CH + lh) * 2;
        const uint32_t vb = smb + (uint32_t)(CF_SV + lr * FH + lh) * 2;
        #pragma unroll
        for (int kc = 0; kc < 5; kc++) {
            uint32_t af[4];
            ldsm4(af[0], af[1], af[2], af[3], pb + kc * 32);
            const uint32_t va = vb + (uint32_t)(kc * 16 * FH) * 2;
            #pragma unroll
            for (int p = 0; p < 4; p++) {
                uint32_t t0, t1, t2, t3;
                ldsm4t(t0, t1, t2, t3, va + (uint32_t)(p * 16) * 2);
                uint32_t bf0[2] = {t0, t1};
                uint32_t bf1[2] = {t2, t3};
                mma_f16(acco[2 * p],     af, bf0);
                mma_f16(acco[2 * p + 1], af, bf1);
            }
        }
    }

    const float i0 = 1.f / rs0;
    const float i1 = 1.f / rs1;
    const int row0 = b * 1024 + q0 + wm + g;
    #pragma unroll
    for (int nt = 0; nt < 8; nt++) {
        const int col = h * 64 + nt * 8 + 2 * tg;
        *(__half2*)(outp + (size_t)row0 * 512 + col) =
            __floats2half2_rn(acco[nt][0] * i0, acco[nt][1] * i0);
        *(__half2*)(outp + (size_t)(row0 + 8) * 512 + col) =
            __floats2half2_rn(acco[nt][2] * i1, acco[nt][3] * i1);
    }
}

// ===========================================================================
// FP16 tensor-core GEMM: C = A @ Bt^T (+bias)(+epilogue)
//   emode 0: plain (+Res fp32 add)
//   emode 3: GEGLU-paired interleaved a/gate -> Ch, ldc = N/2
//   emode 4: transposed-output write to [b,c,s] + qin residual.
// ===========================================================================
#define BM 128
#define BN 128
#define BK 32
#define GSTR 40
#define STG_BYTES (2 * 128 * GSTR * 2)
#define GEMM_SMEM (3 * STG_BYTES)

__global__ void __launch_bounds__(256, 2) gemm_f16_kernel(
    const __half* __restrict__ A, int lda,
    const __half* __restrict__ Bt, int ldb,
    float* __restrict__ Cf, __half* __restrict__ Ch, int ldc,
    const float* __restrict__ Res, int ldres,
    const float* __restrict__ bias,
    int M, int K, int emode) {

    extern __shared__ __half smh[];

    const int m0 = blockIdx.y * BM;
    const int n0 = blockIdx.x * BN;
    const int tid = threadIdx.x;
    const int warp = tid >> 5;
    const int lane = tid & 31;
    const int g  = lane >> 2;
    const int tg = lane & 3;
    const int wm = (warp >> 2) * 64;
    const int wn = (warp & 3) * 32;

    const uint32_t smem_u32 = (uint32_t)__cvta_generic_to_shared(smh);
    const int nk = K / BK;

    float acc[4][4][4];
    #pragma unroll
    for (int i = 0; i < 4; i++)
        #pragma unroll
        for (int j = 0; j < 4; j++)
            #pragma unroll
            for (int r = 0; r < 4; r++) acc[i][j][r] = 0.f;

    auto load_stage = [&](int stage, int k0) {
        const uint32_t abase = smem_u32 + (uint32_t)(stage * STG_BYTES);
        #pragma unroll
        for (int i = 0; i < 2; i++) {
            int idx = tid + i * 256;
            int row = idx >> 2;
            int kc  = (idx & 3) * 8;
            int bytes = (m0 + row < M) ? 16 : 0;
            cp_async16(abase + (uint32_t)(row * GSTR + kc) * 2,
                       A + (long long)(m0 + row) * lda + k0 + kc, bytes);
        }
        const uint32_t bbase = abase + (uint32_t)(128 * GSTR * 2);
        #pragma unroll
        for (int i = 0; i < 2; i++) {
            int idx = tid + i * 256;
            int row = idx >> 2;
            int kc  = (idx & 3) * 8;
            cp_async16(bbase + (uint32_t)(row * GSTR + kc) * 2,
                       Bt + (long long)(n0 + row) * ldb + k0 + kc, 16);
        }
        cp_commit();
    };

    const uint32_t lm_off = (uint32_t)((lane & 15) * GSTR + ((lane >> 4) * 8)) * 2;
    const uint32_t a_lm = smem_u32 + (uint32_t)(wm * GSTR) * 2 + lm_off;
    const uint32_t b_lm = smem_u32 + (uint32_t)(128 * GSTR + wn * GSTR) * 2 + lm_off;

    auto compute_stage = [&](int stage) {
        const uint32_t so = (uint32_t)(stage * STG_BYTES);
        #pragma unroll
        for (int ks = 0; ks < 2; ks++) {
            const uint32_t kkb = ks * 32;
            uint32_t afr[4][4];
            #pragma unroll
            for (int mt = 0; mt < 4; mt++)
                ldsm4(afr[mt][0], afr[mt][1], afr[mt][2], afr[mt][3],
                      a_lm + so + (uint32_t)(mt * 16 * GSTR) * 2 + kkb);
            uint32_t bfr[4][2];
            #pragma unroll
            for (int p = 0; p < 2; p++) {
                uint32_t r0, r1, r2, r3;
                ldsm4(r0, r1, r2, r3, b_lm + so + (uint32_t)(p * 16 * GSTR) * 2 + kkb);
                bfr[2 * p][0]     = r0; bfr[2 * p][1]     = r2;
                bfr[2 * p + 1][0] = r1; bfr[2 * p + 1][1] = r3;
            }
            #pragma unroll
            for (int mt = 0; mt < 4; mt++)
                #pragma unroll
                for (int nt = 0; nt < 4; nt++)
                    mma_f16(acc[mt][nt], afr[mt], bfr[nt]);
        }
    };

    load_stage(0, 0);
    if (nk > 1) load_stage(1, BK);
    for (int kt = 0; kt < nk; kt++) {
        if (kt + 1 < nk) cp_wait1(); else cp_wait0();
        __syncthreads();
        if (kt + 2 < nk) load_stage((kt + 2) % 3, (kt + 2) * BK);
        compute_stage(kt % 3);
    }

    // ---- epilogue (vectorized) ----
    const int obatch = n0 >> 10;
    #pragma unroll
    for (int mt = 0; mt < 4; mt++) {
        #pragma unroll
        for (int nt = 0; nt < 4; nt++) {
            const int row0 = m0 + wm + mt * 16 + g;
            const int col0 = n0 + wn + nt * 8 + tg * 2;
            #pragma unroll
            for (int hh = 0; hh < 2; hh++) {
                const int row = row0 + hh * 8;
                if (row >= M) continue;
                float v0 = acc[mt][nt][2 * hh + 0];
                float v1 = acc[mt][nt][2 * hh + 1];
                if (emode == 4) {
                    v0 += bias[row]; v1 += bias[row];
                    const size_t o = ((size_t)(obatch * 512 + row)) * 1024 +
                                     (col0 & 1023);
                    float2 r = *(const float2*)(Res + o);
                    *(float2*)(Cf + o) = make_float2(v0 + r.x, v1 + r.y);
                    continue;
                }
                if (bias) { v0 += bias[col0]; v1 += bias[col0 + 1]; }
                if (emode == 3) {
                    Ch[(long long)row * ldc + (col0 >> 1)] =
                        __float2half(v0 * gelu_f(v1));
                    continue;
                }
                if (Res) {
                    float2 r = *(const float2*)(Res + (long long)row * ldres + col0);
                    v0 += r.x; v1 += r.y;
                }
                if (Cf) *(float2*)(Cf + (long long)row * ldc + col0) =
                            make_float2(v0, v1);
                if (Ch) *(__half2*)(Ch + (long long)row * ldc + col0) =
                            __floats2half2_rn(v0, v1);
            }
        }
    }
}

// ---------------------------------------------------------------------------
// Host side
// ---------------------------------------------------------------------------
static void gemm(const __half* A, int lda, const __half* Bt, int ldb,
                 float* Cf, __half* Ch, int ldc,
                 const float* Res, int ldres,
                 const float* bias, int M, int N, int K, int emode = 0) {
    dim3 grid(N / BN, (M + BM - 1) / BM);
    gemm_f16_kernel<<<grid, 256, GEMM_SMEM>>>(
        A, lda, Bt, ldb, Cf, Ch, ldc, Res, ldres, bias, M, K, emode);
}

extern "C" void kernel_launch(void* const* d_in, const int* in_sizes, int n_in,
                              void* d_out, int out_size) {
    const float* in_q     = (const float*)d_in[0];
    const float* in_kv    = (const float*)d_in[1];
    const float* gn_g     = (const float*)d_in[2];
    const float* gn_b     = (const float*)d_in[3];
    const float* ln2_g    = (const float*)d_in[4];
    const float* ln2_b    = (const float*)d_in[5];
    const float* ln3_g    = (const float*)d_in[6];
    const float* ln3_b    = (const float*)d_in[7];
    const float* ln4_g    = (const float*)d_in[8];
    const float* ln4_b    = (const float*)d_in[9];
    const float* fc_in_w  = (const float*)d_in[10];
    const float* fc_in_b  = (const float*)d_in[11];
    const float* fc_out_w = (const float*)d_in[12];
    const float* fc_out_b = (const float*)d_in[13];
    const float* a1_q     = (const float*)d_in[14];
    const float* a1_k     = (const float*)d_in[15];
    const float* a1_v     = (const float*)d_in[16];
    const float* a1_o     = (const float*)d_in[17];
    const float* a1_ob    = (const float*)d_in[18];
    const float* a2_q     = (const float*)d_in[19];
    const float* a2_k     = (const float*)d_in[20];
    const float* a2_v     = (const float*)d_in[21];
    const float* a2_o     = (const float*)d_in[22];
    const float* a2_ob    = (const float*)d_in[23];
    const float* ff_proj_w = (const float*)d_in[24];
    const float* ff_proj_b = (const float*)d_in[25];
    const float* ff_out_w  = (const float*)d_in[26];
    const float* ff_out_b  = (const float*)d_in[27];

    cudaFuncSetAttribute(gemm_f16_kernel,
                         cudaFuncAttributeMaxDynamicSharedMemorySize, GEMM_SMEM);
    cudaFuncSetAttribute(flash_self_kernel,
                         cudaFuncAttributeMaxDynamicSharedMemorySize, FS_TOTAL_H * 2);
    cudaFuncSetAttribute(flash_cross_kernel,
                         cudaFuncAttributeMaxDynamicSharedMemorySize, CF_TOTAL_H * 2);

    float *x, *bFfp, *gnst;
    __half *th, *qkvh, *qh, *kvh, *kv2h, *glh, *xh;
    __half *whFcIn, *whQkv, *whA1o, *whA2q, *whA2o, *whKv2, *whFfp, *whFfo, *whFco;
    cudaGetSymbolAddress((void**)&x,    g_x);
    cudaGetSymbolAddress((void**)&bFfp, g_bFfp);
    cudaGetSymbolAddress((void**)&gnst, g_gnstats);
    cudaGetSymbolAddress((void**)&th,   g_th);
    cudaGetSymbolAddress((void**)&qkvh, g_qkvh);
    cudaGetSymbolAddress((void**)&qh,   g_qh);
    cudaGetSymbolAddress((void**)&kvh,  g_kvh);
    cudaGetSymbolAddress((void**)&kv2h, g_kv2h);
    cudaGetSymbolAddress((void**)&glh,  g_glh);
    cudaGetSymbolAddress((void**)&xh,   g_xh);
    cudaGetSymbolAddress((void**)&whFcIn, g_whFcIn);
    cudaGetSymbolAddress((void**)&whQkv,  g_whQkv);
    cudaGetSymbolAddress((void**)&whA1o,  g_whA1o);
    cudaGetSymbolAddress((void**)&whA2q,  g_whA2q);
    cudaGetSymbolAddress((void**)&whA2o,  g_whA2o);
    cudaGetSymbolAddress((void**)&whKv2,  g_whKv2);
    cudaGetSymbolAddress((void**)&whFfp,  g_whFfp);
    cudaGetSymbolAddress((void**)&whFfo,  g_whFfo);
    cudaGetSymbolAddress((void**)&whFco,  g_whFco);

    float* out = (float*)d_out;

    // ---- batched weight transpose+convert (ONE launch) ----
    {
        TrJobs jb;
        const float* srcs[NJOBS] = {fc_in_w, a1_q, a1_k, a1_v, a1_o, a2_q,
                                    a2_o, a2_k, a2_v, ff_proj_w, ff_out_w, fc_out_w};
        __half* dsts[NJOBS] = {whFcIn, whQkv, whQkv + (size_t)512 * 512,
                               whQkv + (size_t)1024 * 512, whA1o, whA2q, whA2o,
                               whKv2, whKv2 + (size_t)512 * 1024,
                               whFfp, whFfo, whFco};
        int Rs[NJOBS] = {512, 512, 512, 512, 512, 512, 512, 1024, 1024, 512, 2048, 512};
        int Cs[NJOBS] = {512, 512, 512, 512, 512, 512, 512, 512, 512, 4096, 512, 512};
        int Il[NJOBS] = {0, 0, 0, 0, 0, 0, 0, 0, 0, 1, 0, 0};
        int acc = 0;
        for (int i = 0; i < NJOBS; i++) {
            jb.src[i] = srcs[i]; jb.dst[i] = dsts[i];
            jb.R[i] = Rs[i]; jb.C[i] = Cs[i]; jb.ileave[i] = Il[i];
            jb.tstart[i] = acc;
            acc += (Rs[i] / 32) * (Cs[i] / 32);
        }
        jb.tstart[NJOBS] = acc;
        trcvt_all_kernel<<<acc, dim3(32, 8)>>>(jb);
    }
    cvt_kernel<<<(BATCH * KVLEN * 1024 + 255) / 256, 256>>>(
        in_kv, kvh, BATCH * KVLEN * 1024);
    bias_ileave_kernel<<<8, 256>>>(ff_proj_b, bFfp);

    // 1. GroupNorm: stats then tiled normalize+transpose -> th (half)
    gn_stats_kernel<<<BATCH * 32, 256>>>(in_q, gnst);
    {
        dim3 grid(SPATIAL / 32, DIMC / 32, BATCH);
        gn_write_kernel<<<grid, dim3(32, 8)>>>(in_q, gnst, gn_g, gn_b, th);
    }

    // 2. x = th @ fc_in + b (fp32)
    gemm(th, 512, whFcIn, 512, x, nullptr, 512, nullptr, 0, fc_in_b,
         NTOK, 512, 512);

    // ---- self attention ----
    layernorm_kernel<<<NTOK / 8, 256>>>(x, ln2_g, ln2_b, th, NTOK);
    gemm(th, 512, whQkv, 512, nullptr, qkvh, 1536, nullptr, 0, nullptr,
         NTOK, 1536, 512);
    {
        dim3 grid(8, 64);
        flash_self_kernel<<<grid, 256, FS_TOTAL_H * 2>>>(qkvh, th);
    }
    gemm(th, 512, whA1o, 512, x, nullptr, 512, x, 512, a1_ob,
         NTOK, 512, 512);

    // ---- cross attention ----
    layernorm_kernel<<<NTOK / 8, 256>>>(x, ln3_g, ln3_b, th, NTOK);
    gemm(th, 512, whA2q, 512, nullptr, qh, 512, nullptr, 0, nullptr,
         NTOK, 512, 512);
    gemm(kvh, 1024, whKv2, 1024, nullptr, kv2h, 1024, nullptr, 0, nullptr,
         BATCH * KVLEN, 1024, 1024);
    {
        dim3 grid(8, 64);
        flash_cross_kernel<<<grid, 256, CF_TOTAL_H * 2>>>(qh, kv2h, th);
    }
    gemm(th, 512, whA2o, 512, x, nullptr, 512, x, 512, a2_ob,
         NTOK, 512, 512);

    // ---- feed-forward (GEGLU, single interleaved GEMM) ----
    layernorm_kernel<<<NTOK / 8, 256>>>(x, ln4_g, ln4_b, th, NTOK);
    gemm(th, 512, whFfp, 512, nullptr, glh, 2048, nullptr, 0, bFfp,
         NTOK, 4096, 512, 3);
    gemm(glh, 2048, whFfo, 2048, nullptr, xh, 512, x, 512, ff_out_b,
         NTOK, 512, 2048);

    // ---- output projection, transposed: out[b,c,s] = fco + qin ----
    gemm(whFco, 512, xh, 512, out, nullptr, 0, in_q, 0, fc_out_b,
         512, NTOK, 512, 4);
}